// round 1
// baseline (speedup 1.0000x reference)
#include <cuda_runtime.h>
#include <float.h>
#include <math.h>

#define MAX_NODES 100000
#define MAX_GRAPHS 512

// ---------------- scratch (device globals; no allocation allowed) ----------------
__device__ float g_h1[(size_t)MAX_NODES * 128];   // layer1 features (then reused for relu output)
__device__ float g_acc1[(size_t)MAX_NODES * 128]; // layer1 weighted sums
__device__ float g_h2[(size_t)MAX_NODES * 64];    // layer2 features
__device__ float g_acc2[(size_t)MAX_NODES * 64];  // layer2 weighted sums
__device__ float g_as1[MAX_NODES * 2], g_ad1[MAX_NODES * 2];
__device__ float g_m1[MAX_NODES * 2], g_den1[MAX_NODES * 2];
__device__ float g_as2[MAX_NODES], g_ad2[MAX_NODES];
__device__ float g_m2[MAX_NODES], g_den2[MAX_NODES];
__device__ float g_psum[MAX_GRAPHS * 64], g_pmax[MAX_GRAPHS * 64], g_cnt[MAX_GRAPHS];

// ---------------- helpers ----------------
__device__ __forceinline__ void atomicMaxF(float* addr, float value) {
    // standard signed-int / unsigned-int monotonic trick
    if (value >= 0.f)
        atomicMax((int*)addr, __float_as_int(value));
    else
        atomicMin((unsigned int*)addr, __float_as_uint(value));
}

__global__ void fillf(float* __restrict__ p, float v, int n) {
    int i = blockIdx.x * blockDim.x + threadIdx.x;
    if (i < n) p[i] = v;
}

// ---------------- GEMM: C[n, NOUT] = A[n,128] @ W[128, NOUT] ----------------
// Block: 256 threads, 64 rows x NOUT cols. Thread: 8 rows x (NOUT/32) cols.
template <int NOUT>
__global__ void gemm_k128(const float* __restrict__ A, const float* __restrict__ W,
                          float* __restrict__ C, int n) {
    constexpr int VEC = NOUT / 32;  // 4 for 128, 2 for 64
    __shared__ float sA[64][132];
    const int t = threadIdx.x;
    const int tc = t & 31;
    const int tr = t >> 5;  // 0..7
    const int row0 = blockIdx.x * 64;

    // load A tile (64 rows x 128 cols) via float4
    for (int i = t; i < 64 * 32; i += 256) {
        int r = i >> 5, c4 = i & 31;
        float4 v = make_float4(0.f, 0.f, 0.f, 0.f);
        if (row0 + r < n)
            v = reinterpret_cast<const float4*>(A)[(size_t)(row0 + r) * 32 + c4];
        sA[r][c4 * 4 + 0] = v.x;
        sA[r][c4 * 4 + 1] = v.y;
        sA[r][c4 * 4 + 2] = v.z;
        sA[r][c4 * 4 + 3] = v.w;
    }
    __syncthreads();

    float acc[8][VEC];
#pragma unroll
    for (int i = 0; i < 8; i++)
#pragma unroll
        for (int j = 0; j < VEC; j++) acc[i][j] = 0.f;

#pragma unroll 4
    for (int k = 0; k < 128; k++) {
        float wv[VEC];
        if (VEC == 4) {
            float4 w4 = reinterpret_cast<const float4*>(W + (size_t)k * NOUT)[tc];
            wv[0] = w4.x; wv[1] = w4.y; wv[2] = w4.z; wv[3] = w4.w;
        } else {
            float2 w2 = reinterpret_cast<const float2*>(W + (size_t)k * NOUT)[tc];
            wv[0] = w2.x; wv[1] = w2.y;
        }
#pragma unroll
        for (int i = 0; i < 8; i++) {
            float a = sA[tr + 8 * i][k];
#pragma unroll
            for (int j = 0; j < VEC; j++) acc[i][j] = fmaf(a, wv[j], acc[i][j]);
        }
    }

#pragma unroll
    for (int i = 0; i < 8; i++) {
        int r = row0 + tr + 8 * i;
        if (r < n) {
#pragma unroll
            for (int j = 0; j < VEC; j++)
                C[(size_t)r * NOUT + tc * VEC + j] = acc[i][j];
        }
    }
}

// ---------------- attention logit coefficients ----------------
// layer 1: 2 heads of 64 dims over h[n,128]
__global__ void alpha1_kernel(const float* __restrict__ h, const float* __restrict__ a_s,
                              const float* __restrict__ a_d, float* __restrict__ as_out,
                              float* __restrict__ ad_out, int n) {
    int w = (blockIdx.x * blockDim.x + threadIdx.x) >> 5;
    int lane = threadIdx.x & 31;
    if (w >= n) return;
    const float* hp = h + (size_t)w * 128;
    float s0 = hp[lane] * a_s[lane] + hp[lane + 32] * a_s[lane + 32];
    float s1 = hp[lane + 64] * a_s[lane + 64] + hp[lane + 96] * a_s[lane + 96];
    float d0 = hp[lane] * a_d[lane] + hp[lane + 32] * a_d[lane + 32];
    float d1 = hp[lane + 64] * a_d[lane + 64] + hp[lane + 96] * a_d[lane + 96];
#pragma unroll
    for (int o = 16; o > 0; o >>= 1) {
        s0 += __shfl_down_sync(0xffffffffu, s0, o);
        s1 += __shfl_down_sync(0xffffffffu, s1, o);
        d0 += __shfl_down_sync(0xffffffffu, d0, o);
        d1 += __shfl_down_sync(0xffffffffu, d1, o);
    }
    if (lane == 0) {
        as_out[w * 2] = s0;
        as_out[w * 2 + 1] = s1;
        ad_out[w * 2] = d0;
        ad_out[w * 2 + 1] = d1;
    }
}

// layer 2: 1 head of 64 dims over h[n,64]
__global__ void alpha2_kernel(const float* __restrict__ h, const float* __restrict__ a_s,
                              const float* __restrict__ a_d, float* __restrict__ as_out,
                              float* __restrict__ ad_out, int n) {
    int w = (blockIdx.x * blockDim.x + threadIdx.x) >> 5;
    int lane = threadIdx.x & 31;
    if (w >= n) return;
    const float* hp = h + (size_t)w * 64;
    float s = hp[lane] * a_s[lane] + hp[lane + 32] * a_s[lane + 32];
    float d = hp[lane] * a_d[lane] + hp[lane + 32] * a_d[lane + 32];
#pragma unroll
    for (int o = 16; o > 0; o >>= 1) {
        s += __shfl_down_sync(0xffffffffu, s, o);
        d += __shfl_down_sync(0xffffffffu, d, o);
    }
    if (lane == 0) {
        as_out[w] = s;
        ad_out[w] = d;
    }
}

// ---------------- edge pass A: segment max of leaky-relu logits ----------------
template <int HEADS>
__global__ void edgemax_kernel(const int* __restrict__ ei, const float* __restrict__ as,
                               const float* __restrict__ ad, float* __restrict__ m,
                               int E, int n) {
    int i = blockIdx.x * blockDim.x + threadIdx.x;
    if (i >= E + n) return;
    int s, d;
    if (i < E) { s = ei[i]; d = ei[E + i]; } else { s = i - E; d = i - E; }
#pragma unroll
    for (int h = 0; h < HEADS; h++) {
        float e = as[s * HEADS + h] + ad[d * HEADS + h];
        e = e >= 0.f ? e : 0.2f * e;
        atomicMaxF(&m[d * HEADS + h], e);
    }
}

// ---------------- edge pass B layer1: exp + weighted gather-scatter ----------------
__global__ void edgeacc1_kernel(const int* __restrict__ ei, const float* __restrict__ as,
                                const float* __restrict__ ad, const float* __restrict__ m,
                                const float* __restrict__ h, float* __restrict__ den,
                                float* __restrict__ acc, int E, int n) {
    int w = (blockIdx.x * blockDim.x + threadIdx.x) >> 5;
    int lane = threadIdx.x & 31;
    if (w >= E + n) return;
    int s, d;
    if (w < E) { s = ei[w]; d = ei[E + w]; } else { s = w - E; d = w - E; }
    float e0 = as[s * 2] + ad[d * 2];
    e0 = e0 >= 0.f ? e0 : 0.2f * e0;
    float e1 = as[s * 2 + 1] + ad[d * 2 + 1];
    e1 = e1 >= 0.f ? e1 : 0.2f * e1;
    float ex0 = expf(e0 - m[d * 2]);
    float ex1 = expf(e1 - m[d * 2 + 1]);
    if (lane == 0) {
        atomicAdd(&den[d * 2], ex0);
        atomicAdd(&den[d * 2 + 1], ex1);
    }
    const float* hs = h + (size_t)s * 128;
    float* ao = acc + (size_t)d * 128;
    atomicAdd(&ao[lane], ex0 * hs[lane]);
    atomicAdd(&ao[lane + 32], ex0 * hs[lane + 32]);
    atomicAdd(&ao[lane + 64], ex1 * hs[lane + 64]);
    atomicAdd(&ao[lane + 96], ex1 * hs[lane + 96]);
}

// ---------------- edge pass B layer2 ----------------
__global__ void edgeacc2_kernel(const int* __restrict__ ei, const float* __restrict__ as,
                                const float* __restrict__ ad, const float* __restrict__ m,
                                const float* __restrict__ h, float* __restrict__ den,
                                float* __restrict__ acc, int E, int n) {
    int w = (blockIdx.x * blockDim.x + threadIdx.x) >> 5;
    int lane = threadIdx.x & 31;
    if (w >= E + n) return;
    int s, d;
    if (w < E) { s = ei[w]; d = ei[E + w]; } else { s = w - E; d = w - E; }
    float e = as[s] + ad[d];
    e = e >= 0.f ? e : 0.2f * e;
    float ex = expf(e - m[d]);
    if (lane == 0) atomicAdd(&den[d], ex);
    const float* hs = h + (size_t)s * 64;
    float* ao = acc + (size_t)d * 64;
    atomicAdd(&ao[lane], ex * hs[lane]);
    atomicAdd(&ao[lane + 32], ex * hs[lane + 32]);
}

// ---------------- finalize layer1: normalize + bias + relu ----------------
__global__ void finalize1_kernel(const float* __restrict__ acc, const float* __restrict__ den,
                                 const float* __restrict__ b, float* __restrict__ out, int n) {
    int i = blockIdx.x * blockDim.x + threadIdx.x;
    if (i >= n * 128) return;
    int node = i >> 7;
    int c = i & 127;
    int head = c >> 6;
    float v = acc[i] / fmaxf(den[node * 2 + head], 1e-16f) + b[c];
    out[i] = fmaxf(v, 0.f);
}

// ---------------- finalize layer2: normalize + bias (no relu) ----------------
__global__ void finalize2_kernel(const float* __restrict__ acc, const float* __restrict__ den,
                                 const float* __restrict__ b, float* __restrict__ out, int n) {
    int i = blockIdx.x * blockDim.x + threadIdx.x;
    if (i >= n * 64) return;
    int node = i >> 6;
    int c = i & 63;
    out[i] = acc[i] / fmaxf(den[node], 1e-16f) + b[c];
}

// ---------------- per-graph pooling ----------------
__global__ void pool_kernel(const float* __restrict__ h, const int* __restrict__ batch,
                            float* __restrict__ psum, float* __restrict__ pmax,
                            float* __restrict__ cnt, int n) {
    int w = (blockIdx.x * blockDim.x + threadIdx.x) >> 5;
    int lane = threadIdx.x & 31;
    if (w >= n) return;
    int g = batch[w];
    float v0 = h[(size_t)w * 64 + lane];
    float v1 = h[(size_t)w * 64 + lane + 32];
    atomicAdd(&psum[g * 64 + lane], v0);
    atomicAdd(&psum[g * 64 + lane + 32], v1);
    atomicMaxF(&pmax[g * 64 + lane], v0);
    atomicMaxF(&pmax[g * 64 + lane + 32], v1);
    if (lane == 0) atomicAdd(&cnt[g], 1.f);
}

// ---------------- final MLP head: out[g] = relu(pooled@Wf1+bf1)@Wf2+bf2 ----------------
__global__ void final_mlp_kernel(const float* __restrict__ psum, const float* __restrict__ pmax,
                                 const float* __restrict__ cnt, const float* __restrict__ Wf1,
                                 const float* __restrict__ bf1, const float* __restrict__ Wf2,
                                 const float* __restrict__ bf2, float* __restrict__ out) {
    __shared__ float pooled[128];
    __shared__ float red[64];
    int g = blockIdx.x;
    int t = threadIdx.x;  // 64
    float c = cnt[g];
    pooled[t] = psum[g * 64 + t] / fmaxf(c, 1.f);
    pooled[64 + t] = (c > 0.f) ? pmax[g * 64 + t] : 0.f;
    __syncthreads();
    float hj = bf1[t];
#pragma unroll 8
    for (int k = 0; k < 128; k++) hj = fmaf(pooled[k], Wf1[k * 64 + t], hj);
    hj = fmaxf(hj, 0.f);
    red[t] = hj * Wf2[t];
    __syncthreads();
    for (int s = 32; s > 0; s >>= 1) {
        if (t < s) red[t] += red[t + s];
        __syncthreads();
    }
    if (t == 0) out[g] = red[0] + bf2[0];
}

// ---------------- host launch ----------------
static inline int cdiv(int a, int b) { return (a + b - 1) / b; }

extern "C" void kernel_launch(void* const* d_in, const int* in_sizes, int n_in,
                              void* d_out, int out_size) {
    const float* x   = (const float*)d_in[0];
    const int*   ei  = (const int*)d_in[1];
    const int*   bat = (const int*)d_in[2];
    const float* W1  = (const float*)d_in[3];
    const float* as1 = (const float*)d_in[4];
    const float* ad1 = (const float*)d_in[5];
    const float* b1  = (const float*)d_in[6];
    const float* W2  = (const float*)d_in[7];
    const float* as2 = (const float*)d_in[8];
    const float* ad2 = (const float*)d_in[9];
    const float* b2  = (const float*)d_in[10];
    const float* Wf1 = (const float*)d_in[11];
    const float* bf1 = (const float*)d_in[12];
    const float* Wf2 = (const float*)d_in[13];
    const float* bf2 = (const float*)d_in[14];
    float* out = (float*)d_out;

    const int n = in_sizes[0] / 128;  // 100000
    const int E = in_sizes[1] / 2;    // 600000
    const int etot = E + n;
    const int G = out_size;           // 512

    float *p_h1, *p_acc1, *p_h2, *p_acc2;
    float *p_as1, *p_ad1, *p_m1, *p_den1;
    float *p_as2, *p_ad2, *p_m2, *p_den2;
    float *p_psum, *p_pmax, *p_cnt;
    cudaGetSymbolAddress((void**)&p_h1, g_h1);
    cudaGetSymbolAddress((void**)&p_acc1, g_acc1);
    cudaGetSymbolAddress((void**)&p_h2, g_h2);
    cudaGetSymbolAddress((void**)&p_acc2, g_acc2);
    cudaGetSymbolAddress((void**)&p_as1, g_as1);
    cudaGetSymbolAddress((void**)&p_ad1, g_ad1);
    cudaGetSymbolAddress((void**)&p_m1, g_m1);
    cudaGetSymbolAddress((void**)&p_den1, g_den1);
    cudaGetSymbolAddress((void**)&p_as2, g_as2);
    cudaGetSymbolAddress((void**)&p_ad2, g_ad2);
    cudaGetSymbolAddress((void**)&p_m2, g_m2);
    cudaGetSymbolAddress((void**)&p_den2, g_den2);
    cudaGetSymbolAddress((void**)&p_psum, g_psum);
    cudaGetSymbolAddress((void**)&p_pmax, g_pmax);
    cudaGetSymbolAddress((void**)&p_cnt, g_cnt);

    const int TB = 256;

    // ---- init layer-1 scratch ----
    fillf<<<cdiv(n * 128, TB), TB>>>(p_acc1, 0.f, n * 128);
    fillf<<<cdiv(n * 2, TB), TB>>>(p_den1, 0.f, n * 2);
    fillf<<<cdiv(n * 2, TB), TB>>>(p_m1, -FLT_MAX, n * 2);

    // ---- layer 1 ----
    gemm_k128<128><<<cdiv(n, 64), TB>>>(x, W1, p_h1, n);
    alpha1_kernel<<<cdiv(n * 32, TB), TB>>>(p_h1, as1, ad1, p_as1, p_ad1, n);
    edgemax_kernel<2><<<cdiv(etot, TB), TB>>>(ei, p_as1, p_ad1, p_m1, E, n);
    edgeacc1_kernel<<<cdiv(etot * 32, TB), TB>>>(ei, p_as1, p_ad1, p_m1, p_h1, p_den1, p_acc1, E, n);
    finalize1_kernel<<<cdiv(n * 128, TB), TB>>>(p_acc1, p_den1, b1, p_h1, n);  // relu, reuse g_h1

    // ---- init layer-2 scratch ----
    fillf<<<cdiv(n * 64, TB), TB>>>(p_acc2, 0.f, n * 64);
    fillf<<<cdiv(n, TB), TB>>>(p_den2, 0.f, n);
    fillf<<<cdiv(n, TB), TB>>>(p_m2, -FLT_MAX, n);

    // ---- layer 2 ----
    gemm_k128<64><<<cdiv(n, 64), TB>>>(p_h1, W2, p_h2, n);
    alpha2_kernel<<<cdiv(n * 32, TB), TB>>>(p_h2, as2, ad2, p_as2, p_ad2, n);
    edgemax_kernel<1><<<cdiv(etot, TB), TB>>>(ei, p_as2, p_ad2, p_m2, E, n);
    edgeacc2_kernel<<<cdiv(etot * 32, TB), TB>>>(ei, p_as2, p_ad2, p_m2, p_h2, p_den2, p_acc2, E, n);
    finalize2_kernel<<<cdiv(n * 64, TB), TB>>>(p_acc2, p_den2, b2, p_h2, n);  // reuse g_h2

    // ---- pooling + head ----
    fillf<<<cdiv(G * 64, TB), TB>>>(p_psum, 0.f, G * 64);
    fillf<<<cdiv(G * 64, TB), TB>>>(p_pmax, -FLT_MAX, G * 64);
    fillf<<<cdiv(G, TB), TB>>>(p_cnt, 0.f, G);
    pool_kernel<<<cdiv(n * 32, TB), TB>>>(p_h2, bat, p_psum, p_pmax, p_cnt, n);
    final_mlp_kernel<<<G, 64>>>(p_psum, p_pmax, p_cnt, Wf1, bf1, Wf2, bf2, out);
}

// round 2
// speedup vs baseline: 1.5227x; 1.5227x over previous
#include <cuda_runtime.h>
#include <float.h>
#include <math.h>

#define MAX_NODES 100000
#define MAX_EDGES 600000
#define MAX_GRAPHS 512

// ---------------- scratch (device globals) ----------------
__device__ float g_h1[(size_t)MAX_NODES * 128];   // gemm1 output
__device__ float g_o1[(size_t)MAX_NODES * 128];   // layer1 output (post relu)
__device__ float g_h2[(size_t)MAX_NODES * 64];    // gemm2 output
__device__ float g_o2[(size_t)MAX_NODES * 64];    // layer2 output
__device__ float g_as1[MAX_NODES * 2], g_ad1[MAX_NODES * 2];
__device__ float g_as2[MAX_NODES], g_ad2[MAX_NODES];
// CSR scratch
__device__ int g_deg[MAX_NODES];
__device__ int g_incl[MAX_NODES];
__device__ int g_bsum[256];
__device__ int g_rowptr[MAX_NODES + 1];
__device__ int g_cursor[MAX_NODES];
__device__ int g_adj[MAX_EDGES + MAX_NODES];
// pooling
__device__ float g_psum[MAX_GRAPHS * 64], g_pmax[MAX_GRAPHS * 64], g_cnt[MAX_GRAPHS];

// ---------------- helpers ----------------
__device__ __forceinline__ void atomicMaxF(float* addr, float value) {
    if (value >= 0.f)
        atomicMax((int*)addr, __float_as_int(value));
    else
        atomicMin((unsigned int*)addr, __float_as_uint(value));
}

__global__ void fillf(float* __restrict__ p, float v, int n) {
    int i = blockIdx.x * blockDim.x + threadIdx.x;
    if (i < n) p[i] = v;
}

// ---------------- CSR build ----------------
__global__ void deg_init(int* __restrict__ deg, int n) {
    int i = blockIdx.x * blockDim.x + threadIdx.x;
    if (i < n) deg[i] = 1;  // self loop
}
__global__ void deg_count(const int* __restrict__ ei, int* __restrict__ deg, int E) {
    int i = blockIdx.x * blockDim.x + threadIdx.x;
    if (i < E) atomicAdd(&deg[ei[E + i]], 1);
}
// per-block inclusive scan (1024 elems/block)
__global__ void scan_block(const int* __restrict__ deg, int* __restrict__ incl,
                           int* __restrict__ bsum, int n) {
    __shared__ int sh[1024];
    int tid = threadIdx.x;
    int gid = blockIdx.x * 1024 + tid;
    int v = (gid < n) ? deg[gid] : 0;
    sh[tid] = v;
    __syncthreads();
#pragma unroll
    for (int off = 1; off < 1024; off <<= 1) {
        int t = 0;
        if (tid >= off) t = sh[tid - off];
        __syncthreads();
        sh[tid] += t;
        __syncthreads();
    }
    if (gid < n) incl[gid] = sh[tid];
    if (tid == 1023) bsum[blockIdx.x] = sh[1023];
}
// scan of block sums (nb <= 128), in-place exclusive
__global__ void scan_bsum(int* __restrict__ bsum, int nb) {
    __shared__ int sh[128];
    int tid = threadIdx.x;
    int v = (tid < nb) ? bsum[tid] : 0;
    sh[tid] = v;
    __syncthreads();
#pragma unroll
    for (int off = 1; off < 128; off <<= 1) {
        int t = 0;
        if (tid >= off) t = sh[tid - off];
        __syncthreads();
        sh[tid] += t;
        __syncthreads();
    }
    if (tid < nb) bsum[tid] = sh[tid] - v;  // exclusive
}
__global__ void scan_finish(const int* __restrict__ incl, const int* __restrict__ bsum,
                            int* __restrict__ rowptr, int* __restrict__ cursor, int n) {
    int i = blockIdx.x * blockDim.x + threadIdx.x;
    if (i < n) {
        int excl_end = incl[i] + bsum[i >> 10];
        rowptr[i + 1] = excl_end;
        cursor[i] = excl_end - ((i >> 10 == 0 && i == 0) ? incl[0] : 0);  // placeholder (fixed below)
    }
    if (i == 0) rowptr[0] = 0;
}
// cursor = rowptr[i] (start offsets); separate tiny kernel for clarity/correctness
__global__ void cursor_init(const int* __restrict__ rowptr, int* __restrict__ cursor, int n) {
    int i = blockIdx.x * blockDim.x + threadIdx.x;
    if (i < n) cursor[i] = rowptr[i];
}
__global__ void scatter_edges(const int* __restrict__ ei, int* __restrict__ cursor,
                              int* __restrict__ adj, int E, int n) {
    int i = blockIdx.x * blockDim.x + threadIdx.x;
    if (i >= E + n) return;
    int s, d;
    if (i < E) { s = ei[i]; d = ei[E + i]; } else { s = i - E; d = s; }
    int pos = atomicAdd(&cursor[d], 1);
    adj[pos] = s;
}

// ---------------- SGEMM: C[n,128] = A[n,128] @ W[128,128] ----------------
// 128x128 block tile, BK=16, 256 threads, 8x8 micro-tile
__global__ __launch_bounds__(256) void sgemm_128(const float* __restrict__ A,
                                                 const float* __restrict__ W,
                                                 float* __restrict__ C, int n) {
    __shared__ float sA[16][132];
    __shared__ float sW[16][128];
    const int t = threadIdx.x;
    const int tr = t >> 4;       // 0..15
    const int tc = t & 15;       // 0..15
    const int row0 = blockIdx.x * 128;

    float acc[8][8];
#pragma unroll
    for (int i = 0; i < 8; i++)
#pragma unroll
        for (int j = 0; j < 8; j++) acc[i][j] = 0.f;

    for (int k0 = 0; k0 < 128; k0 += 16) {
        // load A chunk: 128 rows x 16 cols = 512 float4, 2 per thread, transpose
#pragma unroll
        for (int it = 0; it < 2; it++) {
            int idx = t + it * 256;
            int r = idx >> 2, c4 = idx & 3;
            float4 v = make_float4(0.f, 0.f, 0.f, 0.f);
            if (row0 + r < n)
                v = *reinterpret_cast<const float4*>(A + (size_t)(row0 + r) * 128 + k0 + c4 * 4);
            sA[c4 * 4 + 0][r] = v.x;
            sA[c4 * 4 + 1][r] = v.y;
            sA[c4 * 4 + 2][r] = v.z;
            sA[c4 * 4 + 3][r] = v.w;
        }
        // load W chunk: 16 rows x 128 cols = 512 float4, 2 per thread
#pragma unroll
        for (int it = 0; it < 2; it++) {
            int idx = t + it * 256;
            int kr = idx >> 5, kc4 = idx & 31;
            float4 v = *reinterpret_cast<const float4*>(W + (size_t)(k0 + kr) * 128 + kc4 * 4);
            *reinterpret_cast<float4*>(&sW[kr][kc4 * 4]) = v;
        }
        __syncthreads();
#pragma unroll
        for (int kk = 0; kk < 16; kk++) {
            float4 a0 = *reinterpret_cast<const float4*>(&sA[kk][tr * 8]);
            float4 a1 = *reinterpret_cast<const float4*>(&sA[kk][tr * 8 + 4]);
            float4 w0 = *reinterpret_cast<const float4*>(&sW[kk][tc * 8]);
            float4 w1 = *reinterpret_cast<const float4*>(&sW[kk][tc * 8 + 4]);
            float am[8] = {a0.x, a0.y, a0.z, a0.w, a1.x, a1.y, a1.z, a1.w};
            float wn[8] = {w0.x, w0.y, w0.z, w0.w, w1.x, w1.y, w1.z, w1.w};
#pragma unroll
            for (int i = 0; i < 8; i++)
#pragma unroll
                for (int j = 0; j < 8; j++) acc[i][j] = fmaf(am[i], wn[j], acc[i][j]);
        }
        __syncthreads();
    }
#pragma unroll
    for (int i = 0; i < 8; i++) {
        int r = row0 + tr * 8 + i;
        if (r < n) {
            float4 v0 = make_float4(acc[i][0], acc[i][1], acc[i][2], acc[i][3]);
            float4 v1 = make_float4(acc[i][4], acc[i][5], acc[i][6], acc[i][7]);
            *reinterpret_cast<float4*>(C + (size_t)r * 128 + tc * 8) = v0;
            *reinterpret_cast<float4*>(C + (size_t)r * 128 + tc * 8 + 4) = v1;
        }
    }
}

// ---------------- SGEMM: C[n,64] = A[n,128] @ W[128,64] ----------------
// 128x64 block tile, BK=16, 256 threads, 4x8 micro-tile
__global__ __launch_bounds__(256) void sgemm_64(const float* __restrict__ A,
                                                const float* __restrict__ W,
                                                float* __restrict__ C, int n) {
    __shared__ float sA[16][132];
    __shared__ float sW[16][64];
    const int t = threadIdx.x;
    const int tr = t >> 3;   // 0..31
    const int tc = t & 7;    // 0..7
    const int row0 = blockIdx.x * 128;

    float acc[4][8];
#pragma unroll
    for (int i = 0; i < 4; i++)
#pragma unroll
        for (int j = 0; j < 8; j++) acc[i][j] = 0.f;

    for (int k0 = 0; k0 < 128; k0 += 16) {
#pragma unroll
        for (int it = 0; it < 2; it++) {
            int idx = t + it * 256;
            int r = idx >> 2, c4 = idx & 3;
            float4 v = make_float4(0.f, 0.f, 0.f, 0.f);
            if (row0 + r < n)
                v = *reinterpret_cast<const float4*>(A + (size_t)(row0 + r) * 128 + k0 + c4 * 4);
            sA[c4 * 4 + 0][r] = v.x;
            sA[c4 * 4 + 1][r] = v.y;
            sA[c4 * 4 + 2][r] = v.z;
            sA[c4 * 4 + 3][r] = v.w;
        }
        // W chunk: 16 x 64 = 256 float4, 1 per thread
        {
            int kr = t >> 4, kc4 = t & 15;
            float4 v = *reinterpret_cast<const float4*>(W + (size_t)(k0 + kr) * 64 + kc4 * 4);
            *reinterpret_cast<float4*>(&sW[kr][kc4 * 4]) = v;
        }
        __syncthreads();
#pragma unroll
        for (int kk = 0; kk < 16; kk++) {
            float4 a0 = *reinterpret_cast<const float4*>(&sA[kk][tr * 4]);
            float4 w0 = *reinterpret_cast<const float4*>(&sW[kk][tc * 8]);
            float4 w1 = *reinterpret_cast<const float4*>(&sW[kk][tc * 8 + 4]);
            float am[4] = {a0.x, a0.y, a0.z, a0.w};
            float wn[8] = {w0.x, w0.y, w0.z, w0.w, w1.x, w1.y, w1.z, w1.w};
#pragma unroll
            for (int i = 0; i < 4; i++)
#pragma unroll
                for (int j = 0; j < 8; j++) acc[i][j] = fmaf(am[i], wn[j], acc[i][j]);
        }
        __syncthreads();
    }
#pragma unroll
    for (int i = 0; i < 4; i++) {
        int r = row0 + tr * 4 + i;
        if (r < n) {
            float4 v0 = make_float4(acc[i][0], acc[i][1], acc[i][2], acc[i][3]);
            float4 v1 = make_float4(acc[i][4], acc[i][5], acc[i][6], acc[i][7]);
            *reinterpret_cast<float4*>(C + (size_t)r * 64 + tc * 8) = v0;
            *reinterpret_cast<float4*>(C + (size_t)r * 64 + tc * 8 + 4) = v1;
        }
    }
}

// ---------------- attention logit coefficients ----------------
__global__ void alpha1_kernel(const float* __restrict__ h, const float* __restrict__ a_s,
                              const float* __restrict__ a_d, float* __restrict__ as_out,
                              float* __restrict__ ad_out, int n) {
    int w = (blockIdx.x * blockDim.x + threadIdx.x) >> 5;
    int lane = threadIdx.x & 31;
    if (w >= n) return;
    const float* hp = h + (size_t)w * 128;
    float s0 = hp[lane] * a_s[lane] + hp[lane + 32] * a_s[lane + 32];
    float s1 = hp[lane + 64] * a_s[lane + 64] + hp[lane + 96] * a_s[lane + 96];
    float d0 = hp[lane] * a_d[lane] + hp[lane + 32] * a_d[lane + 32];
    float d1 = hp[lane + 64] * a_d[lane + 64] + hp[lane + 96] * a_d[lane + 96];
#pragma unroll
    for (int o = 16; o > 0; o >>= 1) {
        s0 += __shfl_down_sync(0xffffffffu, s0, o);
        s1 += __shfl_down_sync(0xffffffffu, s1, o);
        d0 += __shfl_down_sync(0xffffffffu, d0, o);
        d1 += __shfl_down_sync(0xffffffffu, d1, o);
    }
    if (lane == 0) {
        as_out[w * 2] = s0;
        as_out[w * 2 + 1] = s1;
        ad_out[w * 2] = d0;
        ad_out[w * 2 + 1] = d1;
    }
}

__global__ void alpha2_kernel(const float* __restrict__ h, const float* __restrict__ a_s,
                              const float* __restrict__ a_d, float* __restrict__ as_out,
                              float* __restrict__ ad_out, int n) {
    int w = (blockIdx.x * blockDim.x + threadIdx.x) >> 5;
    int lane = threadIdx.x & 31;
    if (w >= n) return;
    const float* hp = h + (size_t)w * 64;
    float s = hp[lane] * a_s[lane] + hp[lane + 32] * a_s[lane + 32];
    float d = hp[lane] * a_d[lane] + hp[lane + 32] * a_d[lane + 32];
#pragma unroll
    for (int o = 16; o > 0; o >>= 1) {
        s += __shfl_down_sync(0xffffffffu, s, o);
        d += __shfl_down_sync(0xffffffffu, d, o);
    }
    if (lane == 0) {
        as_out[w] = s;
        ad_out[w] = d;
    }
}

// ---------------- layer1 node aggregation: warp per dst node ----------------
// softmax over in-edges + weighted gather + normalize + bias + relu, all fused
__global__ void gat_node1(const int* __restrict__ rowptr, const int* __restrict__ adj,
                          const float* __restrict__ as, const float* __restrict__ ad,
                          const float* __restrict__ h, const float* __restrict__ b,
                          float* __restrict__ out, int n) {
    int node = (blockIdx.x * blockDim.x + threadIdx.x) >> 5;
    int lane = threadIdx.x & 31;
    if (node >= n) return;
    int start = rowptr[node], end = rowptr[node + 1];
    float ad0 = ad[node * 2], ad1 = ad[node * 2 + 1];

    // pass 1: segment max (lanes over edges)
    float m0 = -FLT_MAX, m1 = -FLT_MAX;
    for (int j = start + lane; j < end; j += 32) {
        int s = adj[j];
        float e0 = as[s * 2] + ad0;
        e0 = e0 >= 0.f ? e0 : 0.2f * e0;
        float e1 = as[s * 2 + 1] + ad1;
        e1 = e1 >= 0.f ? e1 : 0.2f * e1;
        m0 = fmaxf(m0, e0);
        m1 = fmaxf(m1, e1);
    }
#pragma unroll
    for (int o = 16; o > 0; o >>= 1) {
        m0 = fmaxf(m0, __shfl_xor_sync(0xffffffffu, m0, o));
        m1 = fmaxf(m1, __shfl_xor_sync(0xffffffffu, m1, o));
    }

    // pass 2: exp weights + gather-accumulate (lanes over channels)
    float a0 = 0.f, a1 = 0.f, a2 = 0.f, a3 = 0.f, den0 = 0.f, den1 = 0.f;
    for (int base = start; base < end; base += 32) {
        int cnt = min(32, end - base);
        int s_l = 0;
        float ex0_l = 0.f, ex1_l = 0.f;
        if (lane < cnt) {
            s_l = adj[base + lane];
            float e0 = as[s_l * 2] + ad0;
            e0 = e0 >= 0.f ? e0 : 0.2f * e0;
            float e1 = as[s_l * 2 + 1] + ad1;
            e1 = e1 >= 0.f ? e1 : 0.2f * e1;
            ex0_l = expf(e0 - m0);
            ex1_l = expf(e1 - m1);
        }
        den0 += ex0_l;
        den1 += ex1_l;
        for (int tt = 0; tt < cnt; tt++) {
            int s = __shfl_sync(0xffffffffu, s_l, tt);
            float ex0 = __shfl_sync(0xffffffffu, ex0_l, tt);
            float ex1 = __shfl_sync(0xffffffffu, ex1_l, tt);
            const float* hs = h + (size_t)s * 128;
            a0 = fmaf(ex0, hs[lane], a0);
            a1 = fmaf(ex0, hs[lane + 32], a1);
            a2 = fmaf(ex1, hs[lane + 64], a2);
            a3 = fmaf(ex1, hs[lane + 96], a3);
        }
    }
#pragma unroll
    for (int o = 16; o > 0; o >>= 1) {
        den0 += __shfl_xor_sync(0xffffffffu, den0, o);
        den1 += __shfl_xor_sync(0xffffffffu, den1, o);
    }
    den0 = fmaxf(den0, 1e-16f);
    den1 = fmaxf(den1, 1e-16f);
    float* op = out + (size_t)node * 128;
    op[lane]      = fmaxf(a0 / den0 + b[lane], 0.f);
    op[lane + 32] = fmaxf(a1 / den0 + b[lane + 32], 0.f);
    op[lane + 64] = fmaxf(a2 / den1 + b[lane + 64], 0.f);
    op[lane + 96] = fmaxf(a3 / den1 + b[lane + 96], 0.f);
}

// ---------------- layer2 node aggregation (1 head, 64 ch, no relu) ----------------
__global__ void gat_node2(const int* __restrict__ rowptr, const int* __restrict__ adj,
                          const float* __restrict__ as, const float* __restrict__ ad,
                          const float* __restrict__ h, const float* __restrict__ b,
                          float* __restrict__ out, int n) {
    int node = (blockIdx.x * blockDim.x + threadIdx.x) >> 5;
    int lane = threadIdx.x & 31;
    if (node >= n) return;
    int start = rowptr[node], end = rowptr[node + 1];
    float add = ad[node];

    float m = -FLT_MAX;
    for (int j = start + lane; j < end; j += 32) {
        int s = adj[j];
        float e = as[s] + add;
        e = e >= 0.f ? e : 0.2f * e;
        m = fmaxf(m, e);
    }
#pragma unroll
    for (int o = 16; o > 0; o >>= 1)
        m = fmaxf(m, __shfl_xor_sync(0xffffffffu, m, o));

    float a0 = 0.f, a1 = 0.f, den = 0.f;
    for (int base = start; base < end; base += 32) {
        int cnt = min(32, end - base);
        int s_l = 0;
        float ex_l = 0.f;
        if (lane < cnt) {
            s_l = adj[base + lane];
            float e = as[s_l] + add;
            e = e >= 0.f ? e : 0.2f * e;
            ex_l = expf(e - m);
        }
        den += ex_l;
        for (int tt = 0; tt < cnt; tt++) {
            int s = __shfl_sync(0xffffffffu, s_l, tt);
            float ex = __shfl_sync(0xffffffffu, ex_l, tt);
            const float* hs = h + (size_t)s * 64;
            a0 = fmaf(ex, hs[lane], a0);
            a1 = fmaf(ex, hs[lane + 32], a1);
        }
    }
#pragma unroll
    for (int o = 16; o > 0; o >>= 1)
        den += __shfl_xor_sync(0xffffffffu, den, o);
    den = fmaxf(den, 1e-16f);
    float* op = out + (size_t)node * 64;
    op[lane]      = a0 / den + b[lane];
    op[lane + 32] = a1 / den + b[lane + 32];
}

// ---------------- per-graph pooling ----------------
__global__ void pool_kernel(const float* __restrict__ h, const int* __restrict__ batch,
                            float* __restrict__ psum, float* __restrict__ pmax,
                            float* __restrict__ cnt, int n) {
    int w = (blockIdx.x * blockDim.x + threadIdx.x) >> 5;
    int lane = threadIdx.x & 31;
    if (w >= n) return;
    int g = batch[w];
    float v0 = h[(size_t)w * 64 + lane];
    float v1 = h[(size_t)w * 64 + lane + 32];
    atomicAdd(&psum[g * 64 + lane], v0);
    atomicAdd(&psum[g * 64 + lane + 32], v1);
    atomicMaxF(&pmax[g * 64 + lane], v0);
    atomicMaxF(&pmax[g * 64 + lane + 32], v1);
    if (lane == 0) atomicAdd(&cnt[g], 1.f);
}

// ---------------- final MLP head ----------------
__global__ void final_mlp_kernel(const float* __restrict__ psum, const float* __restrict__ pmax,
                                 const float* __restrict__ cnt, const float* __restrict__ Wf1,
                                 const float* __restrict__ bf1, const float* __restrict__ Wf2,
                                 const float* __restrict__ bf2, float* __restrict__ out) {
    __shared__ float pooled[128];
    __shared__ float red[64];
    int g = blockIdx.x;
    int t = threadIdx.x;  // 64
    float c = cnt[g];
    pooled[t] = psum[g * 64 + t] / fmaxf(c, 1.f);
    pooled[64 + t] = (c > 0.f) ? pmax[g * 64 + t] : 0.f;
    __syncthreads();
    float hj = bf1[t];
#pragma unroll 8
    for (int k = 0; k < 128; k++) hj = fmaf(pooled[k], Wf1[k * 64 + t], hj);
    hj = fmaxf(hj, 0.f);
    red[t] = hj * Wf2[t];
    __syncthreads();
    for (int s = 32; s > 0; s >>= 1) {
        if (t < s) red[t] += red[t + s];
        __syncthreads();
    }
    if (t == 0) out[g] = red[0] + bf2[0];
}

// ---------------- host launch ----------------
static inline int cdiv(int a, int b) { return (a + b - 1) / b; }

extern "C" void kernel_launch(void* const* d_in, const int* in_sizes, int n_in,
                              void* d_out, int out_size) {
    const float* x   = (const float*)d_in[0];
    const int*   ei  = (const int*)d_in[1];
    const int*   bat = (const int*)d_in[2];
    const float* W1  = (const float*)d_in[3];
    const float* as1 = (const float*)d_in[4];
    const float* ad1 = (const float*)d_in[5];
    const float* b1  = (const float*)d_in[6];
    const float* W2  = (const float*)d_in[7];
    const float* as2 = (const float*)d_in[8];
    const float* ad2 = (const float*)d_in[9];
    const float* b2  = (const float*)d_in[10];
    const float* Wf1 = (const float*)d_in[11];
    const float* bf1 = (const float*)d_in[12];
    const float* Wf2 = (const float*)d_in[13];
    const float* bf2 = (const float*)d_in[14];
    float* out = (float*)d_out;

    const int n = in_sizes[0] / 128;  // 100000
    const int E = in_sizes[1] / 2;    // 600000
    const int G = out_size;           // 512

    float *p_h1, *p_o1, *p_h2, *p_o2;
    float *p_as1, *p_ad1, *p_as2, *p_ad2;
    float *p_psum, *p_pmax, *p_cnt;
    int *p_deg, *p_incl, *p_bsum, *p_rowptr, *p_cursor, *p_adj;
    cudaGetSymbolAddress((void**)&p_h1, g_h1);
    cudaGetSymbolAddress((void**)&p_o1, g_o1);
    cudaGetSymbolAddress((void**)&p_h2, g_h2);
    cudaGetSymbolAddress((void**)&p_o2, g_o2);
    cudaGetSymbolAddress((void**)&p_as1, g_as1);
    cudaGetSymbolAddress((void**)&p_ad1, g_ad1);
    cudaGetSymbolAddress((void**)&p_as2, g_as2);
    cudaGetSymbolAddress((void**)&p_ad2, g_ad2);
    cudaGetSymbolAddress((void**)&p_psum, g_psum);
    cudaGetSymbolAddress((void**)&p_pmax, g_pmax);
    cudaGetSymbolAddress((void**)&p_cnt, g_cnt);
    cudaGetSymbolAddress((void**)&p_deg, g_deg);
    cudaGetSymbolAddress((void**)&p_incl, g_incl);
    cudaGetSymbolAddress((void**)&p_bsum, g_bsum);
    cudaGetSymbolAddress((void**)&p_rowptr, g_rowptr);
    cudaGetSymbolAddress((void**)&p_cursor, g_cursor);
    cudaGetSymbolAddress((void**)&p_adj, g_adj);

    const int TB = 256;
    const int nb = cdiv(n, 1024);

    // ---- CSR build (shared by both layers) ----
    deg_init<<<cdiv(n, TB), TB>>>(p_deg, n);
    deg_count<<<cdiv(E, TB), TB>>>(ei, p_deg, E);
    scan_block<<<nb, 1024>>>(p_deg, p_incl, p_bsum, n);
    scan_bsum<<<1, 128>>>(p_bsum, nb);
    scan_finish<<<cdiv(n, TB), TB>>>(p_incl, p_bsum, p_rowptr, p_cursor, n);
    cursor_init<<<cdiv(n, TB), TB>>>(p_rowptr, p_cursor, n);
    scatter_edges<<<cdiv(E + n, TB), TB>>>(ei, p_cursor, p_adj, E, n);

    // ---- layer 1 ----
    sgemm_128<<<cdiv(n, 128), 256>>>(x, W1, p_h1, n);
    alpha1_kernel<<<cdiv(n * 32, TB), TB>>>(p_h1, as1, ad1, p_as1, p_ad1, n);
    gat_node1<<<cdiv(n * 32, TB), TB>>>(p_rowptr, p_adj, p_as1, p_ad1, p_h1, b1, p_o1, n);

    // ---- layer 2 ----
    sgemm_64<<<cdiv(n, 128), 256>>>(p_o1, W2, p_h2, n);
    alpha2_kernel<<<cdiv(n * 32, TB), TB>>>(p_h2, as2, ad2, p_as2, p_ad2, n);
    gat_node2<<<cdiv(n * 32, TB), TB>>>(p_rowptr, p_adj, p_as2, p_ad2, p_h2, b2, p_o2, n);

    // ---- pooling + head ----
    fillf<<<cdiv(G * 64, TB), TB>>>(p_psum, 0.f, G * 64);
    fillf<<<cdiv(G * 64, TB), TB>>>(p_pmax, -FLT_MAX, G * 64);
    fillf<<<cdiv(G, TB), TB>>>(p_cnt, 0.f, G);
    pool_kernel<<<cdiv(n * 32, TB), TB>>>(p_o2, bat, p_psum, p_pmax, p_cnt, n);
    final_mlp_kernel<<<G, 64>>>(p_psum, p_pmax, p_cnt, Wf1, bf1, Wf2, bf2, out);
}

// round 6
// speedup vs baseline: 1.9597x; 1.2870x over previous
#include <cuda_runtime.h>
#include <cuda_bf16.h>
#include <cstdint>
#include <stdint.h>
#include <float.h>
#include <math.h>

#define MAX_NODES 100000
#define MAX_EDGES 600000
#define MAX_GRAPHS 512

// ---------------- scratch (device globals) ----------------
__device__ float g_h1[(size_t)MAX_NODES * 128];
__device__ float g_o1[(size_t)MAX_NODES * 128];
__device__ float g_h2[(size_t)MAX_NODES * 64];
__device__ float g_o2[(size_t)MAX_NODES * 64];
__device__ float g_as1[MAX_NODES * 2];
__device__ float g_ad1[MAX_NODES * 2];
__device__ float g_as2[MAX_NODES];
__device__ float g_ad2[MAX_NODES];
// W transposed to [nout][128] bf16 hi/lo (unpadded)
__device__ __nv_bfloat16 g_w1hi[128 * 128];
__device__ __nv_bfloat16 g_w1lo[128 * 128];
__device__ __nv_bfloat16 g_w2hi[64 * 128];
__device__ __nv_bfloat16 g_w2lo[64 * 128];
__device__ int g_deg[MAX_NODES];
__device__ int g_incl[MAX_NODES];
__device__ int g_bsum[256];
__device__ int g_rowptr[MAX_NODES + 1];
__device__ int g_cursor[MAX_NODES];
__device__ int g_adj[MAX_EDGES + MAX_NODES];
__device__ float g_psum[MAX_GRAPHS * 64];
__device__ float g_pmax[MAX_GRAPHS * 64];
__device__ float g_cnt[MAX_GRAPHS];

// ---------------- misc ----------------
__device__ __forceinline__ void atomicMaxF(float* addr, float value) {
    if (value >= 0.f) {
        atomicMax((int*)addr, __float_as_int(value));
    } else {
        atomicMin((unsigned int*)addr, __float_as_uint(value));
    }
}

__global__ void fillf(float* __restrict__ p, float v, int n) {
    int i = blockIdx.x * blockDim.x + threadIdx.x;
    if (i < n) p[i] = v;
}

__device__ __forceinline__ void mma_bf16(float* d, const uint32_t* a, uint32_t b0, uint32_t b1) {
    asm volatile(
        "mma.sync.aligned.m16n8k16.row.col.f32.bf16.bf16.f32 "
        "{%0, %1, %2, %3}, {%4, %5, %6, %7}, {%8, %9}, {%0, %1, %2, %3};"
        : "+f"(d[0]), "+f"(d[1]), "+f"(d[2]), "+f"(d[3])
        : "r"(a[0]), "r"(a[1]), "r"(a[2]), "r"(a[3]), "r"(b0), "r"(b1));
}

// ---------------- weight prep: W[128, nout] fp32 -> Wt[nout][128] bf16 hi/lo ----------------
__global__ void prep_w(const float* __restrict__ W, __nv_bfloat16* __restrict__ whi,
                       __nv_bfloat16* __restrict__ wlo, int nout) {
    int idx = blockIdx.x * blockDim.x + threadIdx.x;
    if (idx >= nout * 128) return;
    int nrow = idx >> 7;
    int k = idx & 127;
    float v = W[k * nout + nrow];
    __nv_bfloat16 h = __float2bfloat16(v);
    __nv_bfloat16 l = __float2bfloat16(v - __bfloat162float(h));
    whi[nrow * 128 + k] = h;
    wlo[nrow * 128 + k] = l;
}

// ---------------- HMMA GEMM + fused alpha epilogue ----------------
// C[n,NOUT] = A[n,128] @ W[128,NOUT]; 128 rows per CTA (256 threads, 8 warps, 16 rows/warp).
// bf16 split: D = Ahi*Whi + Ahi*Wlo + Alo*Whi (fp32 accum).
template <int NOUT, int HEADS>
__global__ __launch_bounds__(256) void gemm_mma(
    const float* __restrict__ A, const __nv_bfloat16* __restrict__ Whi,
    const __nv_bfloat16* __restrict__ Wlo, const float* __restrict__ avs,
    const float* __restrict__ avd, float* __restrict__ Hout, float* __restrict__ as_out,
    float* __restrict__ ad_out, int n) {
    extern __shared__ __align__(16) char sm[];
    constexpr int NT = NOUT / 8;       // n-tiles per row band
    constexpr int STRIDE_B = 272;      // 136 bf16 per row (128 + 8 pad) -> conflict-free
    constexpr int ST_W = NOUT + 4;     // stage stride in floats
    const uint32_t OFF_AVS = 0;
    const uint32_t OFF_AVD = 512;
    const uint32_t OFF_AHI = 1024;
    const uint32_t OFF_ALO = OFF_AHI + 128 * STRIDE_B;      // +34816
    const uint32_t OFF_WHI = OFF_ALO + 128 * STRIDE_B;      // +34816
    const uint32_t OFF_WLO = OFF_WHI + NOUT * STRIDE_B;

    const int tid = threadIdx.x;
    const int row0 = blockIdx.x * 128;

    if (tid < NOUT) {
        reinterpret_cast<float*>(sm + OFF_AVS)[tid] = avs[tid];
        reinterpret_cast<float*>(sm + OFF_AVD)[tid] = avd[tid];
    }

    // ---- A rows -> bf16 hi/lo (thread = half row) ----
    {
        int r = tid >> 1;
        int half = tid & 1;
        bool valid = (row0 + r) < n;
        const float4* arow =
            reinterpret_cast<const float4*>(A + (size_t)(row0 + r) * 128 + half * 64);
#pragma unroll
        for (int g = 0; g < 8; g++) {
            float vs[8];
            if (valid) {
                float4 v0 = arow[g * 2];
                float4 v1 = arow[g * 2 + 1];
                vs[0] = v0.x; vs[1] = v0.y; vs[2] = v0.z; vs[3] = v0.w;
                vs[4] = v1.x; vs[5] = v1.y; vs[6] = v1.z; vs[7] = v1.w;
            } else {
#pragma unroll
                for (int q = 0; q < 8; q++) vs[q] = 0.f;
            }
            uint32_t hw[4];
            uint32_t lw[4];
#pragma unroll
            for (int q = 0; q < 4; q++) {
                __nv_bfloat16 h0 = __float2bfloat16(vs[2 * q]);
                __nv_bfloat16 h1 = __float2bfloat16(vs[2 * q + 1]);
                __nv_bfloat16 l0 = __float2bfloat16(vs[2 * q] - __bfloat162float(h0));
                __nv_bfloat16 l1 = __float2bfloat16(vs[2 * q + 1] - __bfloat162float(h1));
                hw[q] = (uint32_t)__bfloat16_as_ushort(h0) |
                        ((uint32_t)__bfloat16_as_ushort(h1) << 16);
                lw[q] = (uint32_t)__bfloat16_as_ushort(l0) |
                        ((uint32_t)__bfloat16_as_ushort(l1) << 16);
            }
            uint32_t off = r * STRIDE_B + half * 128 + g * 16;
            *reinterpret_cast<uint4*>(sm + OFF_AHI + off) = make_uint4(hw[0], hw[1], hw[2], hw[3]);
            *reinterpret_cast<uint4*>(sm + OFF_ALO + off) = make_uint4(lw[0], lw[1], lw[2], lw[3]);
        }
    }
    // ---- W copy to padded smem ----
    {
        const uint4* wh = reinterpret_cast<const uint4*>(Whi);
        const uint4* wl = reinterpret_cast<const uint4*>(Wlo);
        for (int i = tid; i < NOUT * 16; i += 256) {
            int nrow = i >> 4;
            int seg = i & 15;
            uint32_t off = nrow * STRIDE_B + seg * 16;
            *reinterpret_cast<uint4*>(sm + OFF_WHI + off) = wh[i];
            *reinterpret_cast<uint4*>(sm + OFF_WLO + off) = wl[i];
        }
    }
    __syncthreads();

    const int warp = tid >> 5;
    const int lane = tid & 31;
    const int g = lane >> 2;
    const int j = lane & 3;
    const int wm0 = warp * 16;

    // ---- preload A fragments (8 k-steps, hi+lo) ----
    uint32_t ahi[8][4];
    uint32_t alo[8][4];
    {
        const char* bhg = sm + OFF_AHI + (wm0 + g) * STRIDE_B + j * 4;
        const char* bhg8 = bhg + 8 * STRIDE_B;
        const char* blg = sm + OFF_ALO + (wm0 + g) * STRIDE_B + j * 4;
        const char* blg8 = blg + 8 * STRIDE_B;
#pragma unroll
        for (int ks = 0; ks < 8; ks++) {
            int off = ks * 32;
            ahi[ks][0] = *reinterpret_cast<const uint32_t*>(bhg + off);
            ahi[ks][1] = *reinterpret_cast<const uint32_t*>(bhg8 + off);
            ahi[ks][2] = *reinterpret_cast<const uint32_t*>(bhg + off + 16);
            ahi[ks][3] = *reinterpret_cast<const uint32_t*>(bhg8 + off + 16);
            alo[ks][0] = *reinterpret_cast<const uint32_t*>(blg + off);
            alo[ks][1] = *reinterpret_cast<const uint32_t*>(blg8 + off);
            alo[ks][2] = *reinterpret_cast<const uint32_t*>(blg + off + 16);
            alo[ks][3] = *reinterpret_cast<const uint32_t*>(blg8 + off + 16);
        }
    }

    // ---- main MMA loops ----
    float acc[NT][4];
#pragma unroll
    for (int nt = 0; nt < NT; nt++)
#pragma unroll
        for (int q = 0; q < 4; q++) acc[nt][q] = 0.f;

    {
        const char* bwh = sm + OFF_WHI + g * STRIDE_B + j * 4;
        const char* bwl = sm + OFF_WLO + g * STRIDE_B + j * 4;
#pragma unroll
        for (int nt = 0; nt < NT; nt++) {
            int noff = nt * 8 * STRIDE_B;
#pragma unroll
            for (int ks = 0; ks < 8; ks++) {
                int koff = ks * 32;
                uint32_t bh0 = *reinterpret_cast<const uint32_t*>(bwh + noff + koff);
                uint32_t bh1 = *reinterpret_cast<const uint32_t*>(bwh + noff + koff + 16);
                uint32_t bl0 = *reinterpret_cast<const uint32_t*>(bwl + noff + koff);
                uint32_t bl1 = *reinterpret_cast<const uint32_t*>(bwl + noff + koff + 16);
                mma_bf16(acc[nt], ahi[ks], bh0, bh1);
                mma_bf16(acc[nt], ahi[ks], bl0, bl1);
                mma_bf16(acc[nt], alo[ks], bh0, bh1);
            }
        }
    }
    __syncthreads();  // A tiles dead; reuse as stage

    // ---- epilogue: alpha partials + stage ----
    const float* avs_s = reinterpret_cast<const float*>(sm + OFF_AVS);
    const float* avd_s = reinterpret_cast<const float*>(sm + OFF_AVD);
    float* stage = reinterpret_cast<float*>(sm + OFF_AHI);
    float asum[HEADS][2];
    float dsum[HEADS][2];
#pragma unroll
    for (int h = 0; h < HEADS; h++) {
        asum[h][0] = 0.f; asum[h][1] = 0.f;
        dsum[h][0] = 0.f; dsum[h][1] = 0.f;
    }
#pragma unroll
    for (int nt = 0; nt < NT; nt++) {
        int cn = nt * 8 + 2 * j;
        float av0 = avs_s[cn];
        float av1 = avs_s[cn + 1];
        float dv0 = avd_s[cn];
        float dv1 = avd_s[cn + 1];
        int h = (HEADS == 2 && nt >= NT / 2) ? 1 : 0;
        asum[h][0] += acc[nt][0] * av0 + acc[nt][1] * av1;
        asum[h][1] += acc[nt][2] * av0 + acc[nt][3] * av1;
        dsum[h][0] += acc[nt][0] * dv0 + acc[nt][1] * dv1;
        dsum[h][1] += acc[nt][2] * dv0 + acc[nt][3] * dv1;
        float* st0 = stage + (wm0 + g) * ST_W + cn;
        float* st1 = st0 + 8 * ST_W;
        *reinterpret_cast<float2*>(st0) = make_float2(acc[nt][0], acc[nt][1]);
        *reinterpret_cast<float2*>(st1) = make_float2(acc[nt][2], acc[nt][3]);
    }
#pragma unroll
    for (int off = 1; off <= 2; off <<= 1) {
#pragma unroll
        for (int h = 0; h < HEADS; h++) {
            asum[h][0] += __shfl_xor_sync(0xffffffffu, asum[h][0], off);
            asum[h][1] += __shfl_xor_sync(0xffffffffu, asum[h][1], off);
            dsum[h][0] += __shfl_xor_sync(0xffffffffu, dsum[h][0], off);
            dsum[h][1] += __shfl_xor_sync(0xffffffffu, dsum[h][1], off);
        }
    }
    if (j == 0) {
        int r0 = row0 + wm0 + g;
        int r1 = r0 + 8;
        if (r0 < n) {
#pragma unroll
            for (int h = 0; h < HEADS; h++) {
                as_out[(size_t)r0 * HEADS + h] = asum[h][0];
                ad_out[(size_t)r0 * HEADS + h] = dsum[h][0];
            }
        }
        if (r1 < n) {
#pragma unroll
            for (int h = 0; h < HEADS; h++) {
                as_out[(size_t)r1 * HEADS + h] = asum[h][1];
                ad_out[(size_t)r1 * HEADS + h] = dsum[h][1];
            }
        }
    }
    __syncthreads();

    // ---- coalesced C store ----
    {
        constexpr int C4 = NOUT / 4;
        float4* out4 = reinterpret_cast<float4*>(Hout);
        for (int i = tid; i < 128 * C4; i += 256) {
            int r = i / C4;
            int c4 = i % C4;
            if (row0 + r < n) {
                float4 v = *reinterpret_cast<const float4*>(stage + r * ST_W + c4 * 4);
                out4[(size_t)(row0 + r) * C4 + c4] = v;
            }
        }
    }
}

// ---------------- CSR build ----------------
__global__ void deg_init(int* __restrict__ deg, int n) {
    int i = blockIdx.x * blockDim.x + threadIdx.x;
    if (i < n) deg[i] = 1;
}
__global__ void deg_count(const int* __restrict__ ei, int* __restrict__ deg, int E) {
    int i = blockIdx.x * blockDim.x + threadIdx.x;
    if (i < E) atomicAdd(&deg[ei[E + i]], 1);
}
__global__ void scan_block(const int* __restrict__ deg, int* __restrict__ incl,
                           int* __restrict__ bsum, int n) {
    __shared__ int sh[1024];
    int tid = threadIdx.x;
    int gid = blockIdx.x * 1024 + tid;
    int v = (gid < n) ? deg[gid] : 0;
    sh[tid] = v;
    __syncthreads();
    for (int off = 1; off < 1024; off <<= 1) {
        int t = 0;
        if (tid >= off) t = sh[tid - off];
        __syncthreads();
        sh[tid] += t;
        __syncthreads();
    }
    if (gid < n) incl[gid] = sh[tid];
    if (tid == 1023) bsum[blockIdx.x] = sh[1023];
}
__global__ void scan_bsum(int* __restrict__ bsum, int nb) {
    __shared__ int sh[128];
    int tid = threadIdx.x;
    int v = (tid < nb) ? bsum[tid] : 0;
    sh[tid] = v;
    __syncthreads();
    for (int off = 1; off < 128; off <<= 1) {
        int t = 0;
        if (tid >= off) t = sh[tid - off];
        __syncthreads();
        sh[tid] += t;
        __syncthreads();
    }
    if (tid < nb) bsum[tid] = sh[tid] - v;
}
__global__ void scan_finish(const int* __restrict__ incl, const int* __restrict__ bsum,
                            const int* __restrict__ deg, int* __restrict__ rowptr,
                            int* __restrict__ cursor, int n) {
    int i = blockIdx.x * blockDim.x + threadIdx.x;
    if (i < n) {
        int end = incl[i] + bsum[i >> 10];
        rowptr[i + 1] = end;
        cursor[i] = end - deg[i];
    }
    if (i == 0) rowptr[0] = 0;
}
__global__ void scatter_edges(const int* __restrict__ ei, int* __restrict__ cursor,
                              int* __restrict__ adj, int E, int n) {
    int i = blockIdx.x * blockDim.x + threadIdx.x;
    if (i >= E + n) return;
    int s;
    int d;
    if (i < E) {
        s = ei[i];
        d = ei[E + i];
    } else {
        s = i - E;
        d = s;
    }
    int pos = atomicAdd(&cursor[d], 1);
    adj[pos] = s;
}

// ---------------- layer1 node aggregation (no max pass) ----------------
__global__ void gat_node1(const int* __restrict__ rowptr, const int* __restrict__ adj,
                          const float* __restrict__ as, const float* __restrict__ ad,
                          const float* __restrict__ h, const float* __restrict__ b,
                          float* __restrict__ out, int n) {
    int node = (blockIdx.x * blockDim.x + threadIdx.x) >> 5;
    int lane = threadIdx.x & 31;
    if (node >= n) return;
    int start = rowptr[node];
    int end = rowptr[node + 1];
    float ad0 = ad[node * 2];
    float ad1 = ad[node * 2 + 1];

    float a0 = 0.f;
    float a1 = 0.f;
    float a2 = 0.f;
    float a3 = 0.f;
    float den0 = 0.f;
    float den1 = 0.f;
    for (int base = start; base < end; base += 32) {
        int cnt = min(32, end - base);
        int s_l = 0;
        float ex0_l = 0.f;
        float ex1_l = 0.f;
        if (lane < cnt) {
            s_l = adj[base + lane];
            float e0 = as[s_l * 2] + ad0;
            e0 = e0 >= 0.f ? e0 : 0.2f * e0;
            float e1 = as[s_l * 2 + 1] + ad1;
            e1 = e1 >= 0.f ? e1 : 0.2f * e1;
            ex0_l = expf(e0);
            ex1_l = expf(e1);
        }
        den0 += ex0_l;
        den1 += ex1_l;
        for (int tt = 0; tt < cnt; tt++) {
            int s = __shfl_sync(0xffffffffu, s_l, tt);
            float ex0 = __shfl_sync(0xffffffffu, ex0_l, tt);
            float ex1 = __shfl_sync(0xffffffffu, ex1_l, tt);
            const float* hs = h + (size_t)s * 128;
            a0 = fmaf(ex0, hs[lane], a0);
            a1 = fmaf(ex0, hs[lane + 32], a1);
            a2 = fmaf(ex1, hs[lane + 64], a2);
            a3 = fmaf(ex1, hs[lane + 96], a3);
        }
    }
    for (int o = 16; o > 0; o >>= 1) {
        den0 += __shfl_xor_sync(0xffffffffu, den0, o);
        den1 += __shfl_xor_sync(0xffffffffu, den1, o);
    }
    den0 = fmaxf(den0, 1e-16f);
    den1 = fmaxf(den1, 1e-16f);
    float* op = out + (size_t)node * 128;
    op[lane] = fmaxf(a0 / den0 + b[lane], 0.f);
    op[lane + 32] = fmaxf(a1 / den0 + b[lane + 32], 0.f);
    op[lane + 64] = fmaxf(a2 / den1 + b[lane + 64], 0.f);
    op[lane + 96] = fmaxf(a3 / den1 + b[lane + 96], 0.f);
}

// ---------------- layer2 node aggregation ----------------
__global__ void gat_node2(const int* __restrict__ rowptr, const int* __restrict__ adj,
                          const float* __restrict__ as, const float* __restrict__ ad,
                          const float* __restrict__ h, const float* __restrict__ b,
                          float* __restrict__ out, int n) {
    int node = (blockIdx.x * blockDim.x + threadIdx.x) >> 5;
    int lane = threadIdx.x & 31;
    if (node >= n) return;
    int start = rowptr[node];
    int end = rowptr[node + 1];
    float add = ad[node];

    float a0 = 0.f;
    float a1 = 0.f;
    float den = 0.f;
    for (int base = start; base < end; base += 32) {
        int cnt = min(32, end - base);
        int s_l = 0;
        float ex_l = 0.f;
        if (lane < cnt) {
            s_l = adj[base + lane];
            float e = as[s_l] + add;
            e = e >= 0.f ? e : 0.2f * e;
            ex_l = expf(e);
        }
        den += ex_l;
        for (int tt = 0; tt < cnt; tt++) {
            int s = __shfl_sync(0xffffffffu, s_l, tt);
            float ex = __shfl_sync(0xffffffffu, ex_l, tt);
            const float* hs = h + (size_t)s * 64;
            a0 = fmaf(ex, hs[lane], a0);
            a1 = fmaf(ex, hs[lane + 32], a1);
        }
    }
    for (int o = 16; o > 0; o >>= 1) {
        den += __shfl_xor_sync(0xffffffffu, den, o);
    }
    den = fmaxf(den, 1e-16f);
    float* op = out + (size_t)node * 64;
    op[lane] = a0 / den + b[lane];
    op[lane + 32] = a1 / den + b[lane + 32];
}

// ---------------- per-graph pooling ----------------
__global__ void pool_kernel(const float* __restrict__ h, const int* __restrict__ batch,
                            float* __restrict__ psum, float* __restrict__ pmax,
                            float* __restrict__ cnt, int n) {
    int w = (blockIdx.x * blockDim.x + threadIdx.x) >> 5;
    int lane = threadIdx.x & 31;
    if (w >= n) return;
    int g = batch[w];
    float v0 = h[(size_t)w * 64 + lane];
    float v1 = h[(size_t)w * 64 + lane + 32];
    atomicAdd(&psum[g * 64 + lane], v0);
    atomicAdd(&psum[g * 64 + lane + 32], v1);
    atomicMaxF(&pmax[g * 64 + lane], v0);
    atomicMaxF(&pmax[g * 64 + lane + 32], v1);
    if (lane == 0) atomicAdd(&cnt[g], 1.f);
}

// ---------------- final MLP head ----------------
__global__ void final_mlp_kernel(const float* __restrict__ psum, const float* __restrict__ pmax,
                                 const float* __restrict__ cnt, const float* __restrict__ Wf1,
                                 const float* __restrict__ bf1, const float* __restrict__ Wf2,
                                 const float* __restrict__ bf2, float* __restrict__ out) {
    __shared__ float pooled[128];
    __shared__ float red[64];
    int g = blockIdx.x;
    int t = threadIdx.x;
    float c = cnt[g];
    pooled[t] = psum[g * 64 + t] / fmaxf(c, 1.f);
    pooled[64 + t] = (c > 0.f) ? pmax[g * 64 + t] : 0.f;
    __syncthreads();
    float hj = bf1[t];
    for (int k = 0; k < 128; k++) {
        hj = fmaf(pooled[k], Wf1[k * 64 + t], hj);
    }
    hj = fmaxf(hj, 0.f);
    red[t] = hj * Wf2[t];
    __syncthreads();
    for (int s = 32; s > 0; s >>= 1) {
        if (t < s) red[t] += red[t + s];
        __syncthreads();
    }
    if (t == 0) out[g] = red[0] + bf2[0];
}

// ---------------- host launch ----------------
static inline int cdiv(int a, int b) { return (a + b - 1) / b; }

extern "C" void kernel_launch(void* const* d_in, const int* in_sizes, int n_in,
                              void* d_out, int out_size) {
    const float* x = (const float*)d_in[0];
    const int* ei = (const int*)d_in[1];
    const int* bat = (const int*)d_in[2];
    const float* W1 = (const float*)d_in[3];
    const float* as1 = (const float*)d_in[4];
    const float* ad1 = (const float*)d_in[5];
    const float* b1 = (const float*)d_in[6];
    const float* W2 = (const float*)d_in[7];
    const float* as2 = (const float*)d_in[8];
    const float* ad2 = (const float*)d_in[9];
    const float* b2 = (const float*)d_in[10];
    const float* Wf1 = (const float*)d_in[11];
    const float* bf1 = (const float*)d_in[12];
    const float* Wf2 = (const float*)d_in[13];
    const float* bf2 = (const float*)d_in[14];
    float* out = (float*)d_out;

    const int n = in_sizes[0] / 128;
    const int E = in_sizes[1] / 2;
    const int G = out_size;

    float* p_h1;
    float* p_o1;
    float* p_h2;
    float* p_o2;
    float* p_as1;
    float* p_ad1;
    float* p_as2;
    float* p_ad2;
    float* p_psum;
    float* p_pmax;
    float* p_cnt;
    int* p_deg;
    int* p_incl;
    int* p_bsum;
    int* p_rowptr;
    int* p_cursor;
    int* p_adj;
    __nv_bfloat16* p_w1hi;
    __nv_bfloat16* p_w1lo;
    __nv_bfloat16* p_w2hi;
    __nv_bfloat16* p_w2lo;
    cudaGetSymbolAddress((void**)&p_h1, g_h1);
    cudaGetSymbolAddress((void**)&p_o1, g_o1);
    cudaGetSymbolAddress((void**)&p_h2, g_h2);
    cudaGetSymbolAddress((void**)&p_o2, g_o2);
    cudaGetSymbolAddress((void**)&p_as1, g_as1);
    cudaGetSymbolAddress((void**)&p_ad1, g_ad1);
    cudaGetSymbolAddress((void**)&p_as2, g_as2);
    cudaGetSymbolAddress((void**)&p_ad2, g_ad2);
    cudaGetSymbolAddress((void**)&p_psum, g_psum);
    cudaGetSymbolAddress((void**)&p_pmax, g_pmax);
    cudaGetSymbolAddress((void**)&p_cnt, g_cnt);
    cudaGetSymbolAddress((void**)&p_deg, g_deg);
    cudaGetSymbolAddress((void**)&p_incl, g_incl);
    cudaGetSymbolAddress((void**)&p_bsum, g_bsum);
    cudaGetSymbolAddress((void**)&p_rowptr, g_rowptr);
    cudaGetSymbolAddress((void**)&p_cursor, g_cursor);
    cudaGetSymbolAddress((void**)&p_adj, g_adj);
    cudaGetSymbolAddress((void**)&p_w1hi, g_w1hi);
    cudaGetSymbolAddress((void**)&p_w1lo, g_w1lo);
    cudaGetSymbolAddress((void**)&p_w2hi, g_w2hi);
    cudaGetSymbolAddress((void**)&p_w2lo, g_w2lo);

    const int TB = 256;
    const int nb = cdiv(n, 1024);

    // smem: 1024 (alpha vecs) + A hi/lo 2*34816 + W hi/lo 2*NOUT*272
    const int SMEM1 = 1024 + 2 * 34816 + 2 * 128 * 272;  // 140288
    const int SMEM2 = 1024 + 2 * 34816 + 2 * 64 * 272;   // 105472
    cudaFuncSetAttribute(gemm_mma<128, 2>, cudaFuncAttributeMaxDynamicSharedMemorySize, SMEM1);
    cudaFuncSetAttribute(gemm_mma<64, 1>, cudaFuncAttributeMaxDynamicSharedMemorySize, SMEM2);

    // ---- CSR build ----
    deg_init<<<cdiv(n, TB), TB>>>(p_deg, n);
    deg_count<<<cdiv(E, TB), TB>>>(ei, p_deg, E);
    scan_block<<<nb, 1024>>>(p_deg, p_incl, p_bsum, n);
    scan_bsum<<<1, 128>>>(p_bsum, nb);
    scan_finish<<<cdiv(n, TB), TB>>>(p_incl, p_bsum, p_deg, p_rowptr, p_cursor, n);
    scatter_edges<<<cdiv(E + n, TB), TB>>>(ei, p_cursor, p_adj, E, n);

    // ---- weight prep ----
    prep_w<<<cdiv(128 * 128, TB), TB>>>(W1, p_w1hi, p_w1lo, 128);
    prep_w<<<cdiv(64 * 128, TB), TB>>>(W2, p_w2hi, p_w2lo, 64);

    // ---- layer 1 ----
    gemm_mma<128, 2><<<cdiv(n, 128), 256, SMEM1>>>(x, p_w1hi, p_w1lo, as1, ad1, p_h1, p_as1,
                                                   p_ad1, n);
    gat_node1<<<cdiv(n * 32, TB), TB>>>(p_rowptr, p_adj, p_as1, p_ad1, p_h1, b1, p_o1, n);

    // ---- layer 2 ----
    gemm_mma<64, 1><<<cdiv(n, 128), 256, SMEM2>>>(p_o1, p_w2hi, p_w2lo, as2, ad2, p_h2, p_as2,
                                                  p_ad2, n);
    gat_node2<<<cdiv(n * 32, TB), TB>>>(p_rowptr, p_adj, p_as2, p_ad2, p_h2, b2, p_o2, n);

    // ---- pooling + head ----
    fillf<<<cdiv(G * 64, TB), TB>>>(p_psum, 0.f, G * 64);
    fillf<<<cdiv(G * 64, TB), TB>>>(p_pmax, -FLT_MAX, G * 64);
    fillf<<<cdiv(G, TB), TB>>>(p_cnt, 0.f, G);
    pool_kernel<<<cdiv(n * 32, TB), TB>>>(p_o2, bat, p_psum, p_pmax, p_cnt, n);
    final_mlp_kernel<<<G, 64>>>(p_psum, p_pmax, p_cnt, Wf1, bf1, Wf2, bf2, out);
}

// round 7
// speedup vs baseline: 2.2063x; 1.1258x over previous
#include <cuda_runtime.h>
#include <cuda_bf16.h>
#include <cstdint>
#include <stdint.h>
#include <float.h>
#include <math.h>

#define MAX_NODES 100000
#define MAX_EDGES 600000
#define MAX_GRAPHS 512

// ---------------- scratch (device globals) ----------------
__device__ float g_h1[(size_t)MAX_NODES * 128];
__device__ float g_o1[(size_t)MAX_NODES * 128];
__device__ float g_h2[(size_t)MAX_NODES * 64];
__device__ float g_o2[(size_t)MAX_NODES * 64];
__device__ float g_as1[MAX_NODES * 2];
__device__ float g_ad1[MAX_NODES * 2];
__device__ float g_as2[MAX_NODES];
__device__ float g_ad2[MAX_NODES];
__device__ __nv_bfloat16 g_w1hi[128 * 128];
__device__ __nv_bfloat16 g_w1lo[128 * 128];
__device__ __nv_bfloat16 g_w2hi[64 * 128];
__device__ __nv_bfloat16 g_w2lo[64 * 128];
__device__ int g_deg[MAX_NODES];
__device__ int g_incl[MAX_NODES];
__device__ int g_bsum[256];
__device__ int g_rowptr[MAX_NODES + 1];
__device__ int g_cursor[MAX_NODES];
__device__ int g_adj[MAX_EDGES + MAX_NODES];
__device__ float g_psum[MAX_GRAPHS * 64];
__device__ float g_pmax[MAX_GRAPHS * 64];
__device__ float g_cnt[MAX_GRAPHS];

// ---------------- misc ----------------
__device__ __forceinline__ void atomicMaxF(float* addr, float value) {
    if (value >= 0.f) {
        atomicMax((int*)addr, __float_as_int(value));
    } else {
        atomicMin((unsigned int*)addr, __float_as_uint(value));
    }
}

__device__ __forceinline__ void mma_bf16(float* d, const uint32_t* a, uint32_t b0, uint32_t b1) {
    asm volatile(
        "mma.sync.aligned.m16n8k16.row.col.f32.bf16.bf16.f32 "
        "{%0, %1, %2, %3}, {%4, %5, %6, %7}, {%8, %9}, {%0, %1, %2, %3};"
        : "+f"(d[0]), "+f"(d[1]), "+f"(d[2]), "+f"(d[3])
        : "r"(a[0]), "r"(a[1]), "r"(a[2]), "r"(a[3]), "r"(b0), "r"(b1));
}

// single fill for all pooling buffers
__global__ void fill_pool(float* __restrict__ psum, float* __restrict__ pmax,
                          float* __restrict__ cnt, int gtot) {
    int i = blockIdx.x * blockDim.x + threadIdx.x;
    if (i < gtot * 64) {
        psum[i] = 0.f;
        pmax[i] = -FLT_MAX;
    }
    if (i < gtot) cnt[i] = 0.f;
}

// ---------------- weight prep: W[128, nout] fp32 -> Wt[nout][128] bf16 hi/lo ----------------
__global__ void prep_w(const float* __restrict__ W, __nv_bfloat16* __restrict__ whi,
                       __nv_bfloat16* __restrict__ wlo, int nout) {
    int idx = blockIdx.x * blockDim.x + threadIdx.x;
    if (idx >= nout * 128) return;
    int nrow = idx >> 7;
    int k = idx & 127;
    float v = W[k * nout + nrow];
    __nv_bfloat16 h = __float2bfloat16(v);
    __nv_bfloat16 l = __float2bfloat16(v - __bfloat162float(h));
    whi[nrow * 128 + k] = h;
    wlo[nrow * 128 + k] = l;
}

// ---------------- HMMA GEMM + fused alpha epilogue ----------------
template <int NOUT, int HEADS>
__global__ __launch_bounds__(256) void gemm_mma(
    const float* __restrict__ A, const __nv_bfloat16* __restrict__ Whi,
    const __nv_bfloat16* __restrict__ Wlo, const float* __restrict__ avs,
    const float* __restrict__ avd, float* __restrict__ Hout, float* __restrict__ as_out,
    float* __restrict__ ad_out, int n) {
    extern __shared__ __align__(16) char sm[];
    constexpr int NT = NOUT / 8;
    constexpr int STRIDE_B = 272;
    constexpr int ST_W = NOUT + 4;
    const uint32_t OFF_AVS = 0;
    const uint32_t OFF_AVD = 512;
    const uint32_t OFF_AHI = 1024;
    const uint32_t OFF_ALO = OFF_AHI + 128 * STRIDE_B;
    const uint32_t OFF_WHI = OFF_ALO + 128 * STRIDE_B;
    const uint32_t OFF_WLO = OFF_WHI + NOUT * STRIDE_B;

    const int tid = threadIdx.x;
    const int row0 = blockIdx.x * 128;

    if (tid < NOUT) {
        reinterpret_cast<float*>(sm + OFF_AVS)[tid] = avs[tid];
        reinterpret_cast<float*>(sm + OFF_AVD)[tid] = avd[tid];
    }

    // A rows -> bf16 hi/lo (thread = half row)
    {
        int r = tid >> 1;
        int half = tid & 1;
        bool valid = (row0 + r) < n;
        const float4* arow =
            reinterpret_cast<const float4*>(A + (size_t)(row0 + r) * 128 + half * 64);
#pragma unroll
        for (int g = 0; g < 8; g++) {
            float vs[8];
            if (valid) {
                float4 v0 = arow[g * 2];
                float4 v1 = arow[g * 2 + 1];
                vs[0] = v0.x; vs[1] = v0.y; vs[2] = v0.z; vs[3] = v0.w;
                vs[4] = v1.x; vs[5] = v1.y; vs[6] = v1.z; vs[7] = v1.w;
            } else {
#pragma unroll
                for (int q = 0; q < 8; q++) vs[q] = 0.f;
            }
            uint32_t hw[4];
            uint32_t lw[4];
#pragma unroll
            for (int q = 0; q < 4; q++) {
                __nv_bfloat16 h0 = __float2bfloat16(vs[2 * q]);
                __nv_bfloat16 h1 = __float2bfloat16(vs[2 * q + 1]);
                __nv_bfloat16 l0 = __float2bfloat16(vs[2 * q] - __bfloat162float(h0));
                __nv_bfloat16 l1 = __float2bfloat16(vs[2 * q + 1] - __bfloat162float(h1));
                hw[q] = (uint32_t)__bfloat16_as_ushort(h0) |
                        ((uint32_t)__bfloat16_as_ushort(h1) << 16);
                lw[q] = (uint32_t)__bfloat16_as_ushort(l0) |
                        ((uint32_t)__bfloat16_as_ushort(l1) << 16);
            }
            uint32_t off = r * STRIDE_B + half * 128 + g * 16;
            *reinterpret_cast<uint4*>(sm + OFF_AHI + off) = make_uint4(hw[0], hw[1], hw[2], hw[3]);
            *reinterpret_cast<uint4*>(sm + OFF_ALO + off) = make_uint4(lw[0], lw[1], lw[2], lw[3]);
        }
    }
    // W copy to padded smem
    {
        const uint4* wh = reinterpret_cast<const uint4*>(Whi);
        const uint4* wl = reinterpret_cast<const uint4*>(Wlo);
        for (int i = tid; i < NOUT * 16; i += 256) {
            int nrow = i >> 4;
            int seg = i & 15;
            uint32_t off = nrow * STRIDE_B + seg * 16;
            *reinterpret_cast<uint4*>(sm + OFF_WHI + off) = wh[i];
            *reinterpret_cast<uint4*>(sm + OFF_WLO + off) = wl[i];
        }
    }
    __syncthreads();

    const int warp = tid >> 5;
    const int lane = tid & 31;
    const int g = lane >> 2;
    const int j = lane & 3;
    const int wm0 = warp * 16;

    uint32_t ahi[8][4];
    uint32_t alo[8][4];
    {
        const char* bhg = sm + OFF_AHI + (wm0 + g) * STRIDE_B + j * 4;
        const char* bhg8 = bhg + 8 * STRIDE_B;
        const char* blg = sm + OFF_ALO + (wm0 + g) * STRIDE_B + j * 4;
        const char* blg8 = blg + 8 * STRIDE_B;
#pragma unroll
        for (int ks = 0; ks < 8; ks++) {
            int off = ks * 32;
            ahi[ks][0] = *reinterpret_cast<const uint32_t*>(bhg + off);
            ahi[ks][1] = *reinterpret_cast<const uint32_t*>(bhg8 + off);
            ahi[ks][2] = *reinterpret_cast<const uint32_t*>(bhg + off + 16);
            ahi[ks][3] = *reinterpret_cast<const uint32_t*>(bhg8 + off + 16);
            alo[ks][0] = *reinterpret_cast<const uint32_t*>(blg + off);
            alo[ks][1] = *reinterpret_cast<const uint32_t*>(blg8 + off);
            alo[ks][2] = *reinterpret_cast<const uint32_t*>(blg + off + 16);
            alo[ks][3] = *reinterpret_cast<const uint32_t*>(blg8 + off + 16);
        }
    }

    float acc[NT][4];
#pragma unroll
    for (int nt = 0; nt < NT; nt++)
#pragma unroll
        for (int q = 0; q < 4; q++) acc[nt][q] = 0.f;

    {
        const char* bwh = sm + OFF_WHI + g * STRIDE_B + j * 4;
        const char* bwl = sm + OFF_WLO + g * STRIDE_B + j * 4;
#pragma unroll
        for (int nt = 0; nt < NT; nt++) {
            int noff = nt * 8 * STRIDE_B;
#pragma unroll
            for (int ks = 0; ks < 8; ks++) {
                int koff = ks * 32;
                uint32_t bh0 = *reinterpret_cast<const uint32_t*>(bwh + noff + koff);
                uint32_t bh1 = *reinterpret_cast<const uint32_t*>(bwh + noff + koff + 16);
                uint32_t bl0 = *reinterpret_cast<const uint32_t*>(bwl + noff + koff);
                uint32_t bl1 = *reinterpret_cast<const uint32_t*>(bwl + noff + koff + 16);
                mma_bf16(acc[nt], ahi[ks], bh0, bh1);
                mma_bf16(acc[nt], ahi[ks], bl0, bl1);
                mma_bf16(acc[nt], alo[ks], bh0, bh1);
            }
        }
    }
    __syncthreads();

    const float* avs_s = reinterpret_cast<const float*>(sm + OFF_AVS);
    const float* avd_s = reinterpret_cast<const float*>(sm + OFF_AVD);
    float* stage = reinterpret_cast<float*>(sm + OFF_AHI);
    float asum[HEADS][2];
    float dsum[HEADS][2];
#pragma unroll
    for (int h = 0; h < HEADS; h++) {
        asum[h][0] = 0.f; asum[h][1] = 0.f;
        dsum[h][0] = 0.f; dsum[h][1] = 0.f;
    }
#pragma unroll
    for (int nt = 0; nt < NT; nt++) {
        int cn = nt * 8 + 2 * j;
        float av0 = avs_s[cn];
        float av1 = avs_s[cn + 1];
        float dv0 = avd_s[cn];
        float dv1 = avd_s[cn + 1];
        int h = (HEADS == 2 && nt >= NT / 2) ? 1 : 0;
        asum[h][0] += acc[nt][0] * av0 + acc[nt][1] * av1;
        asum[h][1] += acc[nt][2] * av0 + acc[nt][3] * av1;
        dsum[h][0] += acc[nt][0] * dv0 + acc[nt][1] * dv1;
        dsum[h][1] += acc[nt][2] * dv0 + acc[nt][3] * dv1;
        float* st0 = stage + (wm0 + g) * ST_W + cn;
        float* st1 = st0 + 8 * ST_W;
        *reinterpret_cast<float2*>(st0) = make_float2(acc[nt][0], acc[nt][1]);
        *reinterpret_cast<float2*>(st1) = make_float2(acc[nt][2], acc[nt][3]);
    }
#pragma unroll
    for (int off = 1; off <= 2; off <<= 1) {
#pragma unroll
        for (int h = 0; h < HEADS; h++) {
            asum[h][0] += __shfl_xor_sync(0xffffffffu, asum[h][0], off);
            asum[h][1] += __shfl_xor_sync(0xffffffffu, asum[h][1], off);
            dsum[h][0] += __shfl_xor_sync(0xffffffffu, dsum[h][0], off);
            dsum[h][1] += __shfl_xor_sync(0xffffffffu, dsum[h][1], off);
        }
    }
    if (j == 0) {
        int r0 = row0 + wm0 + g;
        int r1 = r0 + 8;
        if (r0 < n) {
#pragma unroll
            for (int h = 0; h < HEADS; h++) {
                as_out[(size_t)r0 * HEADS + h] = asum[h][0];
                ad_out[(size_t)r0 * HEADS + h] = dsum[h][0];
            }
        }
        if (r1 < n) {
#pragma unroll
            for (int h = 0; h < HEADS; h++) {
                as_out[(size_t)r1 * HEADS + h] = asum[h][1];
                ad_out[(size_t)r1 * HEADS + h] = dsum[h][1];
            }
        }
    }
    __syncthreads();

    {
        constexpr int C4 = NOUT / 4;
        float4* out4 = reinterpret_cast<float4*>(Hout);
        for (int i = tid; i < 128 * C4; i += 256) {
            int r = i / C4;
            int c4 = i % C4;
            if (row0 + r < n) {
                float4 v = *reinterpret_cast<const float4*>(stage + r * ST_W + c4 * 4);
                out4[(size_t)(row0 + r) * C4 + c4] = v;
            }
        }
    }
}

// ---------------- CSR build ----------------
__global__ void deg_init(int* __restrict__ deg, int n) {
    int i = blockIdx.x * blockDim.x + threadIdx.x;
    if (i < n) deg[i] = 1;
}
__global__ void deg_count(const int* __restrict__ ei, int* __restrict__ deg, int E) {
    int i = blockIdx.x * blockDim.x + threadIdx.x;
    if (i < E) atomicAdd(&deg[ei[E + i]], 1);
}
__global__ void scan_block(const int* __restrict__ deg, int* __restrict__ incl,
                           int* __restrict__ bsum, int n) {
    __shared__ int sh[1024];
    int tid = threadIdx.x;
    int gid = blockIdx.x * 1024 + tid;
    int v = (gid < n) ? deg[gid] : 0;
    sh[tid] = v;
    __syncthreads();
    for (int off = 1; off < 1024; off <<= 1) {
        int t = 0;
        if (tid >= off) t = sh[tid - off];
        __syncthreads();
        sh[tid] += t;
        __syncthreads();
    }
    if (gid < n) incl[gid] = sh[tid];
    if (tid == 1023) bsum[blockIdx.x] = sh[1023];
}
__global__ void scan_bsum(int* __restrict__ bsum, int nb) {
    __shared__ int sh[128];
    int tid = threadIdx.x;
    int v = (tid < nb) ? bsum[tid] : 0;
    sh[tid] = v;
    __syncthreads();
    for (int off = 1; off < 128; off <<= 1) {
        int t = 0;
        if (tid >= off) t = sh[tid - off];
        __syncthreads();
        sh[tid] += t;
        __syncthreads();
    }
    if (tid < nb) bsum[tid] = sh[tid] - v;
}
__global__ void scan_finish(const int* __restrict__ incl, const int* __restrict__ bsum,
                            const int* __restrict__ deg, int* __restrict__ rowptr,
                            int* __restrict__ cursor, int n) {
    int i = blockIdx.x * blockDim.x + threadIdx.x;
    if (i < n) {
        int end = incl[i] + bsum[i >> 10];
        rowptr[i + 1] = end;
        cursor[i] = end - deg[i];
    }
    if (i == 0) rowptr[0] = 0;
}
__global__ void scatter_edges(const int* __restrict__ ei, int* __restrict__ cursor,
                              int* __restrict__ adj, int E, int n) {
    int i = blockIdx.x * blockDim.x + threadIdx.x;
    if (i >= E + n) return;
    int s;
    int d;
    if (i < E) {
        s = ei[i];
        d = ei[E + i];
    } else {
        s = i - E;
        d = s;
    }
    int pos = atomicAdd(&cursor[d], 1);
    adj[pos] = s;
}

// ---------------- layer1 node aggregation (float4 gather, no max pass) ----------------
__global__ void gat_node1(const int* __restrict__ rowptr, const int* __restrict__ adj,
                          const float* __restrict__ as, const float* __restrict__ ad,
                          const float* __restrict__ h, const float* __restrict__ b,
                          float* __restrict__ out, int n) {
    int node = (blockIdx.x * blockDim.x + threadIdx.x) >> 5;
    int lane = threadIdx.x & 31;
    if (node >= n) return;
    int start = rowptr[node];
    int end = rowptr[node + 1];
    float ad0 = ad[node * 2];
    float ad1 = ad[node * 2 + 1];
    bool hi = lane >= 16;

    float4 acc = make_float4(0.f, 0.f, 0.f, 0.f);
    float den0 = 0.f;
    float den1 = 0.f;
    for (int base = start; base < end; base += 32) {
        int cnt = min(32, end - base);
        int s_l = 0;
        float ex0_l = 0.f;
        float ex1_l = 0.f;
        if (lane < cnt) {
            s_l = adj[base + lane];
            float e0 = as[s_l * 2] + ad0;
            e0 = e0 >= 0.f ? e0 : 0.2f * e0;
            float e1 = as[s_l * 2 + 1] + ad1;
            e1 = e1 >= 0.f ? e1 : 0.2f * e1;
            ex0_l = expf(e0);
            ex1_l = expf(e1);
        }
        den0 += ex0_l;
        den1 += ex1_l;
        for (int tt = 0; tt < cnt; tt++) {
            int s = __shfl_sync(0xffffffffu, s_l, tt);
            float ex0 = __shfl_sync(0xffffffffu, ex0_l, tt);
            float ex1 = __shfl_sync(0xffffffffu, ex1_l, tt);
            float ex = hi ? ex1 : ex0;
            float4 v = reinterpret_cast<const float4*>(h + (size_t)s * 128)[lane];
            acc.x = fmaf(ex, v.x, acc.x);
            acc.y = fmaf(ex, v.y, acc.y);
            acc.z = fmaf(ex, v.z, acc.z);
            acc.w = fmaf(ex, v.w, acc.w);
        }
    }
    for (int o = 16; o > 0; o >>= 1) {
        den0 += __shfl_xor_sync(0xffffffffu, den0, o);
        den1 += __shfl_xor_sync(0xffffffffu, den1, o);
    }
    float den = fmaxf(hi ? den1 : den0, 1e-16f);
    float inv = 1.f / den;
    float4 bb = reinterpret_cast<const float4*>(b)[lane];
    float4 o;
    o.x = fmaxf(fmaf(acc.x, inv, bb.x), 0.f);
    o.y = fmaxf(fmaf(acc.y, inv, bb.y), 0.f);
    o.z = fmaxf(fmaf(acc.z, inv, bb.z), 0.f);
    o.w = fmaxf(fmaf(acc.w, inv, bb.w), 0.f);
    reinterpret_cast<float4*>(out + (size_t)node * 128)[lane] = o;
}

// ---------------- layer2 node aggregation (float2 gather) ----------------
__global__ void gat_node2(const int* __restrict__ rowptr, const int* __restrict__ adj,
                          const float* __restrict__ as, const float* __restrict__ ad,
                          const float* __restrict__ h, const float* __restrict__ b,
                          float* __restrict__ out, int n) {
    int node = (blockIdx.x * blockDim.x + threadIdx.x) >> 5;
    int lane = threadIdx.x & 31;
    if (node >= n) return;
    int start = rowptr[node];
    int end = rowptr[node + 1];
    float add = ad[node];

    float2 acc = make_float2(0.f, 0.f);
    float den = 0.f;
    for (int base = start; base < end; base += 32) {
        int cnt = min(32, end - base);
        int s_l = 0;
        float ex_l = 0.f;
        if (lane < cnt) {
            s_l = adj[base + lane];
            float e = as[s_l] + add;
            e = e >= 0.f ? e : 0.2f * e;
            ex_l = expf(e);
        }
        den += ex_l;
        for (int tt = 0; tt < cnt; tt++) {
            int s = __shfl_sync(0xffffffffu, s_l, tt);
            float ex = __shfl_sync(0xffffffffu, ex_l, tt);
            float2 v = reinterpret_cast<const float2*>(h + (size_t)s * 64)[lane];
            acc.x = fmaf(ex, v.x, acc.x);
            acc.y = fmaf(ex, v.y, acc.y);
        }
    }
    for (int o = 16; o > 0; o >>= 1) {
        den += __shfl_xor_sync(0xffffffffu, den, o);
    }
    float inv = 1.f / fmaxf(den, 1e-16f);
    float2 bb = reinterpret_cast<const float2*>(b)[lane];
    float2 o;
    o.x = fmaf(acc.x, inv, bb.x);
    o.y = fmaf(acc.y, inv, bb.y);
    reinterpret_cast<float2*>(out + (size_t)node * 64)[lane] = o;
}

// ---------------- per-graph pooling (batch sorted -> running accumulation) ----------------
__global__ void pool_seg(const float* __restrict__ h, const int* __restrict__ batch,
                         float* __restrict__ psum, float* __restrict__ pmax,
                         float* __restrict__ cnt, int n) {
    int n0 = blockIdx.x * 128;
    int t = threadIdx.x;  // 256
    int c = t & 63;
    int off = t >> 6;  // 0..3
    int gcur = -1;
    float sum = 0.f;
    float mx = -FLT_MAX;
    float count = 0.f;
    int lim = min(n0 + 128, n);
    for (int i = n0 + off; i < lim; i += 4) {
        int g = batch[i];
        if (g != gcur) {
            if (gcur >= 0) {
                atomicAdd(&psum[gcur * 64 + c], sum);
                atomicMaxF(&pmax[gcur * 64 + c], mx);
                if (c == 0) atomicAdd(&cnt[gcur], count);
            }
            gcur = g;
            sum = 0.f;
            mx = -FLT_MAX;
            count = 0.f;
        }
        float v = h[(size_t)i * 64 + c];
        sum += v;
        mx = fmaxf(mx, v);
        count += 1.f;
    }
    if (gcur >= 0) {
        atomicAdd(&psum[gcur * 64 + c], sum);
        atomicMaxF(&pmax[gcur * 64 + c], mx);
        if (c == 0) atomicAdd(&cnt[gcur], count);
    }
}

// ---------------- final MLP head ----------------
__global__ void final_mlp_kernel(const float* __restrict__ psum, const float* __restrict__ pmax,
                                 const float* __restrict__ cnt, const float* __restrict__ Wf1,
                                 const float* __restrict__ bf1, const float* __restrict__ Wf2,
                                 const float* __restrict__ bf2, float* __restrict__ out) {
    __shared__ float pooled[128];
    __shared__ float red[64];
    int g = blockIdx.x;
    int t = threadIdx.x;
    float c = cnt[g];
    pooled[t] = psum[g * 64 + t] / fmaxf(c, 1.f);
    pooled[64 + t] = (c > 0.f) ? pmax[g * 64 + t] : 0.f;
    __syncthreads();
    float hj = bf1[t];
    for (int k = 0; k < 128; k++) {
        hj = fmaf(pooled[k], Wf1[k * 64 + t], hj);
    }
    hj = fmaxf(hj, 0.f);
    red[t] = hj * Wf2[t];
    __syncthreads();
    for (int s = 32; s > 0; s >>= 1) {
        if (t < s) red[t] += red[t + s];
        __syncthreads();
    }
    if (t == 0) out[g] = red[0] + bf2[0];
}

// ---------------- host launch ----------------
static inline int cdiv(int a, int b) { return (a + b - 1) / b; }

extern "C" void kernel_launch(void* const* d_in, const int* in_sizes, int n_in,
                              void* d_out, int out_size) {
    const float* x = (const float*)d_in[0];
    const int* ei = (const int*)d_in[1];
    const int* bat = (const int*)d_in[2];
    const float* W1 = (const float*)d_in[3];
    const float* as1 = (const float*)d_in[4];
    const float* ad1 = (const float*)d_in[5];
    const float* b1 = (const float*)d_in[6];
    const float* W2 = (const float*)d_in[7];
    const float* as2 = (const float*)d_in[8];
    const float* ad2 = (const float*)d_in[9];
    const float* b2 = (const float*)d_in[10];
    const float* Wf1 = (const float*)d_in[11];
    const float* bf1 = (const float*)d_in[12];
    const float* Wf2 = (const float*)d_in[13];
    const float* bf2 = (const float*)d_in[14];
    float* out = (float*)d_out;

    const int n = in_sizes[0] / 128;
    const int E = in_sizes[1] / 2;
    const int G = out_size;

    float* p_h1;
    float* p_o1;
    float* p_h2;
    float* p_o2;
    float* p_as1;
    float* p_ad1;
    float* p_as2;
    float* p_ad2;
    float* p_psum;
    float* p_pmax;
    float* p_cnt;
    int* p_deg;
    int* p_incl;
    int* p_bsum;
    int* p_rowptr;
    int* p_cursor;
    int* p_adj;
    __nv_bfloat16* p_w1hi;
    __nv_bfloat16* p_w1lo;
    __nv_bfloat16* p_w2hi;
    __nv_bfloat16* p_w2lo;
    cudaGetSymbolAddress((void**)&p_h1, g_h1);
    cudaGetSymbolAddress((void**)&p_o1, g_o1);
    cudaGetSymbolAddress((void**)&p_h2, g_h2);
    cudaGetSymbolAddress((void**)&p_o2, g_o2);
    cudaGetSymbolAddress((void**)&p_as1, g_as1);
    cudaGetSymbolAddress((void**)&p_ad1, g_ad1);
    cudaGetSymbolAddress((void**)&p_as2, g_as2);
    cudaGetSymbolAddress((void**)&p_ad2, g_ad2);
    cudaGetSymbolAddress((void**)&p_psum, g_psum);
    cudaGetSymbolAddress((void**)&p_pmax, g_pmax);
    cudaGetSymbolAddress((void**)&p_cnt, g_cnt);
    cudaGetSymbolAddress((void**)&p_deg, g_deg);
    cudaGetSymbolAddress((void**)&p_incl, g_incl);
    cudaGetSymbolAddress((void**)&p_bsum, g_bsum);
    cudaGetSymbolAddress((void**)&p_rowptr, g_rowptr);
    cudaGetSymbolAddress((void**)&p_cursor, g_cursor);
    cudaGetSymbolAddress((void**)&p_adj, g_adj);
    cudaGetSymbolAddress((void**)&p_w1hi, g_w1hi);
    cudaGetSymbolAddress((void**)&p_w1lo, g_w1lo);
    cudaGetSymbolAddress((void**)&p_w2hi, g_w2hi);
    cudaGetSymbolAddress((void**)&p_w2lo, g_w2lo);

    const int TB = 256;
    const int nb = cdiv(n, 1024);

    const int SMEM1 = 1024 + 2 * 34816 + 2 * 128 * 272;  // 140288
    const int SMEM2 = 1024 + 2 * 34816 + 2 * 64 * 272;   // 105472
    cudaFuncSetAttribute(gemm_mma<128, 2>, cudaFuncAttributeMaxDynamicSharedMemorySize, SMEM1);
    cudaFuncSetAttribute(gemm_mma<64, 1>, cudaFuncAttributeMaxDynamicSharedMemorySize, SMEM2);

    // ---- CSR build ----
    deg_init<<<cdiv(n, TB), TB>>>(p_deg, n);
    deg_count<<<cdiv(E, TB), TB>>>(ei, p_deg, E);
    scan_block<<<nb, 1024>>>(p_deg, p_incl, p_bsum, n);
    scan_bsum<<<1, 128>>>(p_bsum, nb);
    scan_finish<<<cdiv(n, TB), TB>>>(p_incl, p_bsum, p_deg, p_rowptr, p_cursor, n);
    scatter_edges<<<cdiv(E + n, TB), TB>>>(ei, p_cursor, p_adj, E, n);

    // ---- weight prep ----
    prep_w<<<cdiv(128 * 128, TB), TB>>>(W1, p_w1hi, p_w1lo, 128);
    prep_w<<<cdiv(64 * 128, TB), TB>>>(W2, p_w2hi, p_w2lo, 64);

    // ---- layer 1 ----
    gemm_mma<128, 2><<<cdiv(n, 128), 256, SMEM1>>>(x, p_w1hi, p_w1lo, as1, ad1, p_h1, p_as1,
                                                   p_ad1, n);
    gat_node1<<<cdiv(n * 32, TB), TB>>>(p_rowptr, p_adj, p_as1, p_ad1, p_h1, b1, p_o1, n);

    // ---- layer 2 ----
    gemm_mma<64, 1><<<cdiv(n, 128), 256, SMEM2>>>(p_o1, p_w2hi, p_w2lo, as2, ad2, p_h2, p_as2,
                                                  p_ad2, n);
    gat_node2<<<cdiv(n * 32, TB), TB>>>(p_rowptr, p_adj, p_as2, p_ad2, p_h2, b2, p_o2, n);

    // ---- pooling + head ----
    fill_pool<<<cdiv(G * 64, TB), TB>>>(p_psum, p_pmax, p_cnt, G);
    pool_seg<<<cdiv(n, 128), 256>>>(p_o2, bat, p_psum, p_pmax, p_cnt, n);
    final_mlp_kernel<<<G, 64>>>(p_psum, p_pmax, p_cnt, Wf1, bf1, Wf2, bf2, out);
}

// round 8
// speedup vs baseline: 2.3518x; 1.0659x over previous
#include <cuda_runtime.h>
#include <cuda_bf16.h>
#include <cstdint>
#include <stdint.h>
#include <float.h>
#include <math.h>

#define MAX_NODES 100000
#define MAX_EDGES 600000
#define MAX_GRAPHS 512

// ---------------- scratch (device globals) ----------------
__device__ float g_h1[(size_t)MAX_NODES * 128];
__device__ float g_o1[(size_t)MAX_NODES * 128];
__device__ float g_h2[(size_t)MAX_NODES * 64];
__device__ float g_o2[(size_t)MAX_NODES * 64];
__device__ float g_as1[MAX_NODES * 2];
__device__ float g_ad1[MAX_NODES * 2];
__device__ float g_as2[MAX_NODES];
__device__ float g_ad2[MAX_NODES];
__device__ __nv_bfloat16 g_w1hi[128 * 128];
__device__ __nv_bfloat16 g_w1lo[128 * 128];
__device__ __nv_bfloat16 g_w2hi[64 * 128];
__device__ __nv_bfloat16 g_w2lo[64 * 128];
__device__ int g_deg[MAX_NODES];
__device__ int g_incl[MAX_NODES];
__device__ int g_bsum[256];
__device__ int g_rowptr[MAX_NODES + 1];
__device__ int g_cursor[MAX_NODES];
__device__ int g_adj[MAX_EDGES + MAX_NODES];
__device__ float g_psum[MAX_GRAPHS * 64];
__device__ float g_pmax[MAX_GRAPHS * 64];
__device__ float g_cnt[MAX_GRAPHS];

// ---------------- misc ----------------
__device__ __forceinline__ void atomicMaxF(float* addr, float value) {
    if (value >= 0.f) {
        atomicMax((int*)addr, __float_as_int(value));
    } else {
        atomicMin((unsigned int*)addr, __float_as_uint(value));
    }
}

__device__ __forceinline__ void mma_bf16(float* d, const uint32_t* a, uint32_t b0, uint32_t b1) {
    asm volatile(
        "mma.sync.aligned.m16n8k16.row.col.f32.bf16.bf16.f32 "
        "{%0, %1, %2, %3}, {%4, %5, %6, %7}, {%8, %9}, {%0, %1, %2, %3};"
        : "+f"(d[0]), "+f"(d[1]), "+f"(d[2]), "+f"(d[3])
        : "r"(a[0]), "r"(a[1]), "r"(a[2]), "r"(a[3]), "r"(b0), "r"(b1));
}

__global__ void fill_pool(float* __restrict__ psum, float* __restrict__ pmax,
                          float* __restrict__ cnt, int gtot) {
    int i = blockIdx.x * blockDim.x + threadIdx.x;
    if (i < gtot * 64) {
        psum[i] = 0.f;
        pmax[i] = -FLT_MAX;
    }
    if (i < gtot) cnt[i] = 0.f;
}

// ---------------- setup: deg=1 + both weight preps fused ----------------
__global__ void setup_kernel(const float* __restrict__ W1, const float* __restrict__ W2,
                             __nv_bfloat16* __restrict__ w1hi, __nv_bfloat16* __restrict__ w1lo,
                             __nv_bfloat16* __restrict__ w2hi, __nv_bfloat16* __restrict__ w2lo,
                             int* __restrict__ deg, int n) {
    int idx = blockIdx.x * blockDim.x + threadIdx.x;
    if (idx < n) deg[idx] = 1;
    if (idx < 128 * 128) {
        int nrow = idx >> 7;
        int k = idx & 127;
        float v = W1[k * 128 + nrow];
        __nv_bfloat16 h = __float2bfloat16(v);
        w1hi[idx] = h;
        w1lo[idx] = __float2bfloat16(v - __bfloat162float(h));
    }
    if (idx < 64 * 128) {
        int nrow = idx >> 7;
        int k = idx & 127;
        float v = W2[k * 64 + nrow];
        __nv_bfloat16 h = __float2bfloat16(v);
        w2hi[idx] = h;
        w2lo[idx] = __float2bfloat16(v - __bfloat162float(h));
    }
}

// ---------------- HMMA GEMM + fused alpha epilogue ----------------
template <int NOUT, int HEADS>
__global__ __launch_bounds__(256) void gemm_mma(
    const float* __restrict__ A, const __nv_bfloat16* __restrict__ Whi,
    const __nv_bfloat16* __restrict__ Wlo, const float* __restrict__ avs,
    const float* __restrict__ avd, float* __restrict__ Hout, float* __restrict__ as_out,
    float* __restrict__ ad_out, int n) {
    extern __shared__ __align__(16) char sm[];
    constexpr int NT = NOUT / 8;
    constexpr int STRIDE_B = 272;
    constexpr int ST_W = NOUT + 4;
    const uint32_t OFF_AVS = 0;
    const uint32_t OFF_AVD = 512;
    const uint32_t OFF_AHI = 1024;
    const uint32_t OFF_ALO = OFF_AHI + 128 * STRIDE_B;
    const uint32_t OFF_WHI = OFF_ALO + 128 * STRIDE_B;
    const uint32_t OFF_WLO = OFF_WHI + NOUT * STRIDE_B;

    const int tid = threadIdx.x;
    const int row0 = blockIdx.x * 128;

    if (tid < NOUT) {
        reinterpret_cast<float*>(sm + OFF_AVS)[tid] = avs[tid];
        reinterpret_cast<float*>(sm + OFF_AVD)[tid] = avd[tid];
    }

    {
        int r = tid >> 1;
        int half = tid & 1;
        bool valid = (row0 + r) < n;
        const float4* arow =
            reinterpret_cast<const float4*>(A + (size_t)(row0 + r) * 128 + half * 64);
#pragma unroll
        for (int g = 0; g < 8; g++) {
            float vs[8];
            if (valid) {
                float4 v0 = arow[g * 2];
                float4 v1 = arow[g * 2 + 1];
                vs[0] = v0.x; vs[1] = v0.y; vs[2] = v0.z; vs[3] = v0.w;
                vs[4] = v1.x; vs[5] = v1.y; vs[6] = v1.z; vs[7] = v1.w;
            } else {
#pragma unroll
                for (int q = 0; q < 8; q++) vs[q] = 0.f;
            }
            uint32_t hw[4];
            uint32_t lw[4];
#pragma unroll
            for (int q = 0; q < 4; q++) {
                __nv_bfloat16 h0 = __float2bfloat16(vs[2 * q]);
                __nv_bfloat16 h1 = __float2bfloat16(vs[2 * q + 1]);
                __nv_bfloat16 l0 = __float2bfloat16(vs[2 * q] - __bfloat162float(h0));
                __nv_bfloat16 l1 = __float2bfloat16(vs[2 * q + 1] - __bfloat162float(h1));
                hw[q] = (uint32_t)__bfloat16_as_ushort(h0) |
                        ((uint32_t)__bfloat16_as_ushort(h1) << 16);
                lw[q] = (uint32_t)__bfloat16_as_ushort(l0) |
                        ((uint32_t)__bfloat16_as_ushort(l1) << 16);
            }
            uint32_t off = r * STRIDE_B + half * 128 + g * 16;
            *reinterpret_cast<uint4*>(sm + OFF_AHI + off) = make_uint4(hw[0], hw[1], hw[2], hw[3]);
            *reinterpret_cast<uint4*>(sm + OFF_ALO + off) = make_uint4(lw[0], lw[1], lw[2], lw[3]);
        }
    }
    {
        const uint4* wh = reinterpret_cast<const uint4*>(Whi);
        const uint4* wl = reinterpret_cast<const uint4*>(Wlo);
        for (int i = tid; i < NOUT * 16; i += 256) {
            int nrow = i >> 4;
            int seg = i & 15;
            uint32_t off = nrow * STRIDE_B + seg * 16;
            *reinterpret_cast<uint4*>(sm + OFF_WHI + off) = wh[i];
            *reinterpret_cast<uint4*>(sm + OFF_WLO + off) = wl[i];
        }
    }
    __syncthreads();

    const int warp = tid >> 5;
    const int lane = tid & 31;
    const int g = lane >> 2;
    const int j = lane & 3;
    const int wm0 = warp * 16;

    uint32_t ahi[8][4];
    uint32_t alo[8][4];
    {
        const char* bhg = sm + OFF_AHI + (wm0 + g) * STRIDE_B + j * 4;
        const char* bhg8 = bhg + 8 * STRIDE_B;
        const char* blg = sm + OFF_ALO + (wm0 + g) * STRIDE_B + j * 4;
        const char* blg8 = blg + 8 * STRIDE_B;
#pragma unroll
        for (int ks = 0; ks < 8; ks++) {
            int off = ks * 32;
            ahi[ks][0] = *reinterpret_cast<const uint32_t*>(bhg + off);
            ahi[ks][1] = *reinterpret_cast<const uint32_t*>(bhg8 + off);
            ahi[ks][2] = *reinterpret_cast<const uint32_t*>(bhg + off + 16);
            ahi[ks][3] = *reinterpret_cast<const uint32_t*>(bhg8 + off + 16);
            alo[ks][0] = *reinterpret_cast<const uint32_t*>(blg + off);
            alo[ks][1] = *reinterpret_cast<const uint32_t*>(blg8 + off);
            alo[ks][2] = *reinterpret_cast<const uint32_t*>(blg + off + 16);
            alo[ks][3] = *reinterpret_cast<const uint32_t*>(blg8 + off + 16);
        }
    }

    float acc[NT][4];
#pragma unroll
    for (int nt = 0; nt < NT; nt++)
#pragma unroll
        for (int q = 0; q < 4; q++) acc[nt][q] = 0.f;

    {
        const char* bwh = sm + OFF_WHI + g * STRIDE_B + j * 4;
        const char* bwl = sm + OFF_WLO + g * STRIDE_B + j * 4;
#pragma unroll
        for (int nt = 0; nt < NT; nt++) {
            int noff = nt * 8 * STRIDE_B;
#pragma unroll
            for (int ks = 0; ks < 8; ks++) {
                int koff = ks * 32;
                uint32_t bh0 = *reinterpret_cast<const uint32_t*>(bwh + noff + koff);
                uint32_t bh1 = *reinterpret_cast<const uint32_t*>(bwh + noff + koff + 16);
                uint32_t bl0 = *reinterpret_cast<const uint32_t*>(bwl + noff + koff);
                uint32_t bl1 = *reinterpret_cast<const uint32_t*>(bwl + noff + koff + 16);
                mma_bf16(acc[nt], ahi[ks], bh0, bh1);
                mma_bf16(acc[nt], ahi[ks], bl0, bl1);
                mma_bf16(acc[nt], alo[ks], bh0, bh1);
            }
        }
    }
    __syncthreads();

    const float* avs_s = reinterpret_cast<const float*>(sm + OFF_AVS);
    const float* avd_s = reinterpret_cast<const float*>(sm + OFF_AVD);
    float* stage = reinterpret_cast<float*>(sm + OFF_AHI);
    float asum[HEADS][2];
    float dsum[HEADS][2];
#pragma unroll
    for (int h = 0; h < HEADS; h++) {
        asum[h][0] = 0.f; asum[h][1] = 0.f;
        dsum[h][0] = 0.f; dsum[h][1] = 0.f;
    }
#pragma unroll
    for (int nt = 0; nt < NT; nt++) {
        int cn = nt * 8 + 2 * j;
        float av0 = avs_s[cn];
        float av1 = avs_s[cn + 1];
        float dv0 = avd_s[cn];
        float dv1 = avd_s[cn + 1];
        int h = (HEADS == 2 && nt >= NT / 2) ? 1 : 0;
        asum[h][0] += acc[nt][0] * av0 + acc[nt][1] * av1;
        asum[h][1] += acc[nt][2] * av0 + acc[nt][3] * av1;
        dsum[h][0] += acc[nt][0] * dv0 + acc[nt][1] * dv1;
        dsum[h][1] += acc[nt][2] * dv0 + acc[nt][3] * dv1;
        float* st0 = stage + (wm0 + g) * ST_W + cn;
        float* st1 = st0 + 8 * ST_W;
        *reinterpret_cast<float2*>(st0) = make_float2(acc[nt][0], acc[nt][1]);
        *reinterpret_cast<float2*>(st1) = make_float2(acc[nt][2], acc[nt][3]);
    }
#pragma unroll
    for (int off = 1; off <= 2; off <<= 1) {
#pragma unroll
        for (int h = 0; h < HEADS; h++) {
            asum[h][0] += __shfl_xor_sync(0xffffffffu, asum[h][0], off);
            asum[h][1] += __shfl_xor_sync(0xffffffffu, asum[h][1], off);
            dsum[h][0] += __shfl_xor_sync(0xffffffffu, dsum[h][0], off);
            dsum[h][1] += __shfl_xor_sync(0xffffffffu, dsum[h][1], off);
        }
    }
    if (j == 0) {
        int r0 = row0 + wm0 + g;
        int r1 = r0 + 8;
        if (r0 < n) {
#pragma unroll
            for (int h = 0; h < HEADS; h++) {
                as_out[(size_t)r0 * HEADS + h] = asum[h][0];
                ad_out[(size_t)r0 * HEADS + h] = dsum[h][0];
            }
        }
        if (r1 < n) {
#pragma unroll
            for (int h = 0; h < HEADS; h++) {
                as_out[(size_t)r1 * HEADS + h] = asum[h][1];
                ad_out[(size_t)r1 * HEADS + h] = dsum[h][1];
            }
        }
    }
    __syncthreads();

    {
        constexpr int C4 = NOUT / 4;
        float4* out4 = reinterpret_cast<float4*>(Hout);
        for (int i = tid; i < 128 * C4; i += 256) {
            int r = i / C4;
            int c4 = i % C4;
            if (row0 + r < n) {
                float4 v = *reinterpret_cast<const float4*>(stage + r * ST_W + c4 * 4);
                out4[(size_t)(row0 + r) * C4 + c4] = v;
            }
        }
    }
}

// ---------------- CSR build ----------------
__global__ void deg_count(const int* __restrict__ ei, int* __restrict__ deg, int E) {
    int i = blockIdx.x * blockDim.x + threadIdx.x;
    if (i < E) atomicAdd(&deg[ei[E + i]], 1);
}

// shfl-based inclusive scan over 1024-blocks
__global__ void scan_block(const int* __restrict__ deg, int* __restrict__ incl,
                           int* __restrict__ bsum, int n) {
    __shared__ int wsum[32];
    int tid = threadIdx.x;
    int lane = tid & 31;
    int wid = tid >> 5;
    int gid = blockIdx.x * 1024 + tid;
    int v = (gid < n) ? deg[gid] : 0;
#pragma unroll
    for (int off = 1; off < 32; off <<= 1) {
        int t = __shfl_up_sync(0xffffffffu, v, off);
        if (lane >= off) v += t;
    }
    if (lane == 31) wsum[wid] = v;
    __syncthreads();
    if (wid == 0) {
        int w = wsum[lane];
#pragma unroll
        for (int off = 1; off < 32; off <<= 1) {
            int t = __shfl_up_sync(0xffffffffu, w, off);
            if (lane >= off) w += t;
        }
        wsum[lane] = w;
    }
    __syncthreads();
    if (wid > 0) v += wsum[wid - 1];
    if (gid < n) incl[gid] = v;
    if (tid == 1023) bsum[blockIdx.x] = v;
}

// single-warp exclusive scan of block sums (nb <= 128)
__global__ void scan_bsum(int* __restrict__ bsum, int nb) {
    int lane = threadIdx.x;
    int base = lane * 4;
    int v[4];
#pragma unroll
    for (int q = 0; q < 4; q++) v[q] = (base + q < nb) ? bsum[base + q] : 0;
    int tot = v[0] + v[1] + v[2] + v[3];
    int inc = tot;
#pragma unroll
    for (int off = 1; off < 32; off <<= 1) {
        int t = __shfl_up_sync(0xffffffffu, inc, off);
        if (lane >= off) inc += t;
    }
    int run = inc - tot;
#pragma unroll
    for (int q = 0; q < 4; q++) {
        int old = run;
        run += v[q];
        if (base + q < nb) bsum[base + q] = old;
    }
}

__global__ void scan_finish(const int* __restrict__ incl, const int* __restrict__ bsum,
                            const int* __restrict__ deg, int* __restrict__ rowptr,
                            int* __restrict__ cursor, int n) {
    int i = blockIdx.x * blockDim.x + threadIdx.x;
    if (i < n) {
        int end = incl[i] + bsum[i >> 10];
        rowptr[i + 1] = end;
        cursor[i] = end - deg[i];
    }
    if (i == 0) rowptr[0] = 0;
}
__global__ void scatter_edges(const int* __restrict__ ei, int* __restrict__ cursor,
                              int* __restrict__ adj, int E, int n) {
    int i = blockIdx.x * blockDim.x + threadIdx.x;
    if (i >= E + n) return;
    int s;
    int d;
    if (i < E) {
        s = ei[i];
        d = ei[E + i];
    } else {
        s = i - E;
        d = s;
    }
    int pos = atomicAdd(&cursor[d], 1);
    adj[pos] = s;
}

// ---------------- layer1 node aggregation ----------------
__global__ void gat_node1(const int* __restrict__ rowptr, const int* __restrict__ adj,
                          const float* __restrict__ as, const float* __restrict__ ad,
                          const float* __restrict__ h, const float* __restrict__ b,
                          float* __restrict__ out, int n) {
    int node = (blockIdx.x * blockDim.x + threadIdx.x) >> 5;
    int lane = threadIdx.x & 31;
    if (node >= n) return;
    int start = rowptr[node];
    int end = rowptr[node + 1];
    float ad0 = ad[node * 2];
    float ad1 = ad[node * 2 + 1];
    bool hi = lane >= 16;

    float4 acc = make_float4(0.f, 0.f, 0.f, 0.f);
    float den0 = 0.f;
    float den1 = 0.f;
    for (int base = start; base < end; base += 32) {
        int cnt = min(32, end - base);
        int s_l = 0;
        float ex0_l = 0.f;
        float ex1_l = 0.f;
        if (lane < cnt) {
            s_l = adj[base + lane];
            float e0 = as[s_l * 2] + ad0;
            e0 = e0 >= 0.f ? e0 : 0.2f * e0;
            float e1 = as[s_l * 2 + 1] + ad1;
            e1 = e1 >= 0.f ? e1 : 0.2f * e1;
            ex0_l = expf(e0);
            ex1_l = expf(e1);
        }
        den0 += ex0_l;
        den1 += ex1_l;
        for (int tt = 0; tt < cnt; tt++) {
            int s = __shfl_sync(0xffffffffu, s_l, tt);
            float ex0 = __shfl_sync(0xffffffffu, ex0_l, tt);
            float ex1 = __shfl_sync(0xffffffffu, ex1_l, tt);
            float ex = hi ? ex1 : ex0;
            float4 v = reinterpret_cast<const float4*>(h + (size_t)s * 128)[lane];
            acc.x = fmaf(ex, v.x, acc.x);
            acc.y = fmaf(ex, v.y, acc.y);
            acc.z = fmaf(ex, v.z, acc.z);
            acc.w = fmaf(ex, v.w, acc.w);
        }
    }
    for (int o = 16; o > 0; o >>= 1) {
        den0 += __shfl_xor_sync(0xffffffffu, den0, o);
        den1 += __shfl_xor_sync(0xffffffffu, den1, o);
    }
    float den = fmaxf(hi ? den1 : den0, 1e-16f);
    float inv = 1.f / den;
    float4 bb = reinterpret_cast<const float4*>(b)[lane];
    float4 o;
    o.x = fmaxf(fmaf(acc.x, inv, bb.x), 0.f);
    o.y = fmaxf(fmaf(acc.y, inv, bb.y), 0.f);
    o.z = fmaxf(fmaf(acc.z, inv, bb.z), 0.f);
    o.w = fmaxf(fmaf(acc.w, inv, bb.w), 0.f);
    reinterpret_cast<float4*>(out + (size_t)node * 128)[lane] = o;
}

// ---------------- layer2 node aggregation ----------------
__global__ void gat_node2(const int* __restrict__ rowptr, const int* __restrict__ adj,
                          const float* __restrict__ as, const float* __restrict__ ad,
                          const float* __restrict__ h, const float* __restrict__ b,
                          float* __restrict__ out, int n) {
    int node = (blockIdx.x * blockDim.x + threadIdx.x) >> 5;
    int lane = threadIdx.x & 31;
    if (node >= n) return;
    int start = rowptr[node];
    int end = rowptr[node + 1];
    float add = ad[node];

    float2 acc = make_float2(0.f, 0.f);
    float den = 0.f;
    for (int base = start; base < end; base += 32) {
        int cnt = min(32, end - base);
        int s_l = 0;
        float ex_l = 0.f;
        if (lane < cnt) {
            s_l = adj[base + lane];
            float e = as[s_l] + add;
            e = e >= 0.f ? e : 0.2f * e;
            ex_l = expf(e);
        }
        den += ex_l;
        for (int tt = 0; tt < cnt; tt++) {
            int s = __shfl_sync(0xffffffffu, s_l, tt);
            float ex = __shfl_sync(0xffffffffu, ex_l, tt);
            float2 v = reinterpret_cast<const float2*>(h + (size_t)s * 64)[lane];
            acc.x = fmaf(ex, v.x, acc.x);
            acc.y = fmaf(ex, v.y, acc.y);
        }
    }
    for (int o = 16; o > 0; o >>= 1) {
        den += __shfl_xor_sync(0xffffffffu, den, o);
    }
    float inv = 1.f / fmaxf(den, 1e-16f);
    float2 bb = reinterpret_cast<const float2*>(b)[lane];
    float2 o;
    o.x = fmaf(acc.x, inv, bb.x);
    o.y = fmaf(acc.y, inv, bb.y);
    reinterpret_cast<float2*>(out + (size_t)node * 64)[lane] = o;
}

// ---------------- per-graph pooling (batch sorted) ----------------
__global__ void pool_seg(const float* __restrict__ h, const int* __restrict__ batch,
                         float* __restrict__ psum, float* __restrict__ pmax,
                         float* __restrict__ cnt, int n) {
    int n0 = blockIdx.x * 128;
    int t = threadIdx.x;
    int c = t & 63;
    int off = t >> 6;
    int gcur = -1;
    float sum = 0.f;
    float mx = -FLT_MAX;
    float count = 0.f;
    int lim = min(n0 + 128, n);
    for (int i = n0 + off; i < lim; i += 4) {
        int g = batch[i];
        if (g != gcur) {
            if (gcur >= 0) {
                atomicAdd(&psum[gcur * 64 + c], sum);
                atomicMaxF(&pmax[gcur * 64 + c], mx);
                if (c == 0) atomicAdd(&cnt[gcur], count);
            }
            gcur = g;
            sum = 0.f;
            mx = -FLT_MAX;
            count = 0.f;
        }
        float v = h[(size_t)i * 64 + c];
        sum += v;
        mx = fmaxf(mx, v);
        count += 1.f;
    }
    if (gcur >= 0) {
        atomicAdd(&psum[gcur * 64 + c], sum);
        atomicMaxF(&pmax[gcur * 64 + c], mx);
        if (c == 0) atomicAdd(&cnt[gcur], count);
    }
}

// ---------------- final MLP head ----------------
__global__ void final_mlp_kernel(const float* __restrict__ psum, const float* __restrict__ pmax,
                                 const float* __restrict__ cnt, const float* __restrict__ Wf1,
                                 const float* __restrict__ bf1, const float* __restrict__ Wf2,
                                 const float* __restrict__ bf2, float* __restrict__ out) {
    __shared__ float pooled[128];
    __shared__ float red[64];
    int g = blockIdx.x;
    int t = threadIdx.x;
    float c = cnt[g];
    pooled[t] = psum[g * 64 + t] / fmaxf(c, 1.f);
    pooled[64 + t] = (c > 0.f) ? pmax[g * 64 + t] : 0.f;
    __syncthreads();
    float hj = bf1[t];
    for (int k = 0; k < 128; k++) {
        hj = fmaf(pooled[k], Wf1[k * 64 + t], hj);
    }
    hj = fmaxf(hj, 0.f);
    red[t] = hj * Wf2[t];
    __syncthreads();
    for (int s = 32; s > 0; s >>= 1) {
        if (t < s) red[t] += red[t + s];
        __syncthreads();
    }
    if (t == 0) out[g] = red[0] + bf2[0];
}

// ---------------- host launch ----------------
static inline int cdiv(int a, int b) { return (a + b - 1) / b; }

extern "C" void kernel_launch(void* const* d_in, const int* in_sizes, int n_in,
                              void* d_out, int out_size) {
    const float* x = (const float*)d_in[0];
    const int* ei = (const int*)d_in[1];
    const int* bat = (const int*)d_in[2];
    const float* W1 = (const float*)d_in[3];
    const float* as1 = (const float*)d_in[4];
    const float* ad1 = (const float*)d_in[5];
    const float* b1 = (const float*)d_in[6];
    const float* W2 = (const float*)d_in[7];
    const float* as2 = (const float*)d_in[8];
    const float* ad2 = (const float*)d_in[9];
    const float* b2 = (const float*)d_in[10];
    const float* Wf1 = (const float*)d_in[11];
    const float* bf1 = (const float*)d_in[12];
    const float* Wf2 = (const float*)d_in[13];
    const float* bf2 = (const float*)d_in[14];
    float* out = (float*)d_out;

    const int n = in_sizes[0] / 128;
    const int E = in_sizes[1] / 2;
    const int G = out_size;

    float* p_h1;
    float* p_o1;
    float* p_h2;
    float* p_o2;
    float* p_as1;
    float* p_ad1;
    float* p_as2;
    float* p_ad2;
    float* p_psum;
    float* p_pmax;
    float* p_cnt;
    int* p_deg;
    int* p_incl;
    int* p_bsum;
    int* p_rowptr;
    int* p_cursor;
    int* p_adj;
    __nv_bfloat16* p_w1hi;
    __nv_bfloat16* p_w1lo;
    __nv_bfloat16* p_w2hi;
    __nv_bfloat16* p_w2lo;
    cudaGetSymbolAddress((void**)&p_h1, g_h1);
    cudaGetSymbolAddress((void**)&p_o1, g_o1);
    cudaGetSymbolAddress((void**)&p_h2, g_h2);
    cudaGetSymbolAddress((void**)&p_o2, g_o2);
    cudaGetSymbolAddress((void**)&p_as1, g_as1);
    cudaGetSymbolAddress((void**)&p_ad1, g_ad1);
    cudaGetSymbolAddress((void**)&p_as2, g_as2);
    cudaGetSymbolAddress((void**)&p_ad2, g_ad2);
    cudaGetSymbolAddress((void**)&p_psum, g_psum);
    cudaGetSymbolAddress((void**)&p_pmax, g_pmax);
    cudaGetSymbolAddress((void**)&p_cnt, g_cnt);
    cudaGetSymbolAddress((void**)&p_deg, g_deg);
    cudaGetSymbolAddress((void**)&p_incl, g_incl);
    cudaGetSymbolAddress((void**)&p_bsum, g_bsum);
    cudaGetSymbolAddress((void**)&p_rowptr, g_rowptr);
    cudaGetSymbolAddress((void**)&p_cursor, g_cursor);
    cudaGetSymbolAddress((void**)&p_adj, g_adj);
    cudaGetSymbolAddress((void**)&p_w1hi, g_w1hi);
    cudaGetSymbolAddress((void**)&p_w1lo, g_w1lo);
    cudaGetSymbolAddress((void**)&p_w2hi, g_w2hi);
    cudaGetSymbolAddress((void**)&p_w2lo, g_w2lo);

    const int TB = 256;
    const int nb = cdiv(n, 1024);

    const int SMEM1 = 1024 + 2 * 34816 + 2 * 128 * 272;  // 140288
    const int SMEM2 = 1024 + 2 * 34816 + 2 * 64 * 272;   // 105472
    cudaFuncSetAttribute(gemm_mma<128, 2>, cudaFuncAttributeMaxDynamicSharedMemorySize, SMEM1);
    cudaFuncSetAttribute(gemm_mma<64, 1>, cudaFuncAttributeMaxDynamicSharedMemorySize, SMEM2);

    // persistent side stream + events for capture fork/join
    static cudaStream_t s2 = nullptr;
    static cudaEvent_t evA = nullptr;
    static cudaEvent_t evB = nullptr;
    if (s2 == nullptr) {
        cudaStreamCreateWithFlags(&s2, cudaStreamNonBlocking);
        cudaEventCreateWithFlags(&evA, cudaEventDisableTiming);
        cudaEventCreateWithFlags(&evB, cudaEventDisableTiming);
    }

    // ---- setup (weights bf16 split + deg init) on main stream ----
    setup_kernel<<<cdiv(n, TB), TB>>>(W1, W2, p_w1hi, p_w1lo, p_w2hi, p_w2lo, p_deg, n);

    // fork: CSR build + pool fills on side stream
    cudaEventRecord(evA, 0);
    cudaStreamWaitEvent(s2, evA, 0);
    deg_count<<<cdiv(E, TB), TB, 0, s2>>>(ei, p_deg, E);
    scan_block<<<nb, 1024, 0, s2>>>(p_deg, p_incl, p_bsum, n);
    scan_bsum<<<1, 32, 0, s2>>>(p_bsum, nb);
    scan_finish<<<cdiv(n, TB), TB, 0, s2>>>(p_incl, p_bsum, p_deg, p_rowptr, p_cursor, n);
    scatter_edges<<<cdiv(E + n, TB), TB, 0, s2>>>(ei, p_cursor, p_adj, E, n);
    fill_pool<<<cdiv(G * 64, TB), TB, 0, s2>>>(p_psum, p_pmax, p_cnt, G);
    cudaEventRecord(evB, s2);

    // main stream: layer-1 GEMM in parallel with CSR
    gemm_mma<128, 2><<<cdiv(n, 128), 256, SMEM1>>>(x, p_w1hi, p_w1lo, as1, ad1, p_h1, p_as1,
                                                   p_ad1, n);

    // join: gat_node1 needs both gemm1 and CSR
    cudaStreamWaitEvent(0, evB, 0);
    gat_node1<<<cdiv(n * 32, TB), TB>>>(p_rowptr, p_adj, p_as1, p_ad1, p_h1, b1, p_o1, n);

    // ---- layer 2 ----
    gemm_mma<64, 1><<<cdiv(n, 128), 256, SMEM2>>>(p_o1, p_w2hi, p_w2lo, as2, ad2, p_h2, p_as2,
                                                  p_ad2, n);
    gat_node2<<<cdiv(n * 32, TB), TB>>>(p_rowptr, p_adj, p_as2, p_ad2, p_h2, b2, p_o2, n);

    // ---- pooling + head ----
    pool_seg<<<cdiv(n, 128), 256>>>(p_o2, bat, p_psum, p_pmax, p_cnt, n);
    final_mlp_kernel<<<G, 64>>>(p_psum, p_pmax, p_cnt, Wf1, bf1, Wf2, bf2, out);
}

// round 9
// speedup vs baseline: 2.4452x; 1.0397x over previous
#include <cuda_runtime.h>
#include <cuda_bf16.h>
#include <cstdint>
#include <stdint.h>
#include <float.h>
#include <math.h>

#define MAX_NODES 100000
#define MAX_EDGES 600000
#define MAX_GRAPHS 512

// ---------------- scratch (device globals) ----------------
__device__ float g_h1[(size_t)MAX_NODES * 128];
__device__ float g_o1[(size_t)MAX_NODES * 128];
__device__ float g_h2[(size_t)MAX_NODES * 64];
__device__ float g_o2[(size_t)MAX_NODES * 64];
__device__ float g_as1[MAX_NODES * 2];
__device__ float g_ad1[MAX_NODES * 2];
__device__ float g_as2[MAX_NODES];
__device__ float g_ad2[MAX_NODES];
__device__ __nv_bfloat16 g_w1hi[128 * 128];
__device__ __nv_bfloat16 g_w1lo[128 * 128];
__device__ __nv_bfloat16 g_w2hi[64 * 128];
__device__ __nv_bfloat16 g_w2lo[64 * 128];
__device__ int g_deg[MAX_NODES];
__device__ int g_incl[MAX_NODES];
__device__ int g_bsum[256];
__device__ int g_rowptr[MAX_NODES + 1];
__device__ int g_cursor[MAX_NODES];
__device__ int g_adj[MAX_EDGES + MAX_NODES];
__device__ float g_psum[MAX_GRAPHS * 64];
__device__ float g_pmax[MAX_GRAPHS * 64];
__device__ float g_cnt[MAX_GRAPHS];

// ---------------- misc ----------------
__device__ __forceinline__ void atomicMaxF(float* addr, float value) {
    if (value >= 0.f) {
        atomicMax((int*)addr, __float_as_int(value));
    } else {
        atomicMin((unsigned int*)addr, __float_as_uint(value));
    }
}

__device__ __forceinline__ void mma_bf16(float* d, const uint32_t* a, uint32_t b0, uint32_t b1) {
    asm volatile(
        "mma.sync.aligned.m16n8k16.row.col.f32.bf16.bf16.f32 "
        "{%0, %1, %2, %3}, {%4, %5, %6, %7}, {%8, %9}, {%0, %1, %2, %3};"
        : "+f"(d[0]), "+f"(d[1]), "+f"(d[2]), "+f"(d[3])
        : "r"(a[0]), "r"(a[1]), "r"(a[2]), "r"(a[3]), "r"(b0), "r"(b1));
}

// ---------------- setup: deg=1 + weight preps + pool fills fused ----------------
__global__ void setup_kernel(const float* __restrict__ W1, const float* __restrict__ W2,
                             __nv_bfloat16* __restrict__ w1hi, __nv_bfloat16* __restrict__ w1lo,
                             __nv_bfloat16* __restrict__ w2hi, __nv_bfloat16* __restrict__ w2lo,
                             int* __restrict__ deg, float* __restrict__ psum,
                             float* __restrict__ pmax, float* __restrict__ cnt, int n, int gtot) {
    int idx = blockIdx.x * blockDim.x + threadIdx.x;
    if (idx < n) deg[idx] = 1;
    if (idx < 128 * 128) {
        int nrow = idx >> 7;
        int k = idx & 127;
        float v = W1[k * 128 + nrow];
        __nv_bfloat16 h = __float2bfloat16(v);
        w1hi[idx] = h;
        w1lo[idx] = __float2bfloat16(v - __bfloat162float(h));
    }
    if (idx < 64 * 128) {
        int nrow = idx >> 7;
        int k = idx & 127;
        float v = W2[k * 64 + nrow];
        __nv_bfloat16 h = __float2bfloat16(v);
        w2hi[idx] = h;
        w2lo[idx] = __float2bfloat16(v - __bfloat162float(h));
    }
    if (idx < gtot * 64) {
        psum[idx] = 0.f;
        pmax[idx] = -FLT_MAX;
    }
    if (idx < gtot) cnt[idx] = 0.f;
}

// ---------------- HMMA GEMM + fused alpha epilogue ----------------
template <int NOUT, int HEADS>
__global__ __launch_bounds__(256) void gemm_mma(
    const float* __restrict__ A, const __nv_bfloat16* __restrict__ Whi,
    const __nv_bfloat16* __restrict__ Wlo, const float* __restrict__ avs,
    const float* __restrict__ avd, float* __restrict__ Hout, float* __restrict__ as_out,
    float* __restrict__ ad_out, int n) {
    extern __shared__ __align__(16) char sm[];
    constexpr int NT = NOUT / 8;
    constexpr int STRIDE_B = 272;
    constexpr int ST_W = NOUT + 4;
    const uint32_t OFF_AVS = 0;
    const uint32_t OFF_AVD = 512;
    const uint32_t OFF_AHI = 1024;
    const uint32_t OFF_ALO = OFF_AHI + 128 * STRIDE_B;
    const uint32_t OFF_WHI = OFF_ALO + 128 * STRIDE_B;
    const uint32_t OFF_WLO = OFF_WHI + NOUT * STRIDE_B;

    const int tid = threadIdx.x;
    const int row0 = blockIdx.x * 128;

    if (tid < NOUT) {
        reinterpret_cast<float*>(sm + OFF_AVS)[tid] = avs[tid];
        reinterpret_cast<float*>(sm + OFF_AVD)[tid] = avd[tid];
    }

    {
        int r = tid >> 1;
        int half = tid & 1;
        bool valid = (row0 + r) < n;
        const float4* arow =
            reinterpret_cast<const float4*>(A + (size_t)(row0 + r) * 128 + half * 64);
#pragma unroll
        for (int g = 0; g < 8; g++) {
            float vs[8];
            if (valid) {
                float4 v0 = arow[g * 2];
                float4 v1 = arow[g * 2 + 1];
                vs[0] = v0.x; vs[1] = v0.y; vs[2] = v0.z; vs[3] = v0.w;
                vs[4] = v1.x; vs[5] = v1.y; vs[6] = v1.z; vs[7] = v1.w;
            } else {
#pragma unroll
                for (int q = 0; q < 8; q++) vs[q] = 0.f;
            }
            uint32_t hw[4];
            uint32_t lw[4];
#pragma unroll
            for (int q = 0; q < 4; q++) {
                __nv_bfloat16 h0 = __float2bfloat16(vs[2 * q]);
                __nv_bfloat16 h1 = __float2bfloat16(vs[2 * q + 1]);
                __nv_bfloat16 l0 = __float2bfloat16(vs[2 * q] - __bfloat162float(h0));
                __nv_bfloat16 l1 = __float2bfloat16(vs[2 * q + 1] - __bfloat162float(h1));
                hw[q] = (uint32_t)__bfloat16_as_ushort(h0) |
                        ((uint32_t)__bfloat16_as_ushort(h1) << 16);
                lw[q] = (uint32_t)__bfloat16_as_ushort(l0) |
                        ((uint32_t)__bfloat16_as_ushort(l1) << 16);
            }
            uint32_t off = r * STRIDE_B + half * 128 + g * 16;
            *reinterpret_cast<uint4*>(sm + OFF_AHI + off) = make_uint4(hw[0], hw[1], hw[2], hw[3]);
            *reinterpret_cast<uint4*>(sm + OFF_ALO + off) = make_uint4(lw[0], lw[1], lw[2], lw[3]);
        }
    }
    {
        const uint4* wh = reinterpret_cast<const uint4*>(Whi);
        const uint4* wl = reinterpret_cast<const uint4*>(Wlo);
        for (int i = tid; i < NOUT * 16; i += 256) {
            int nrow = i >> 4;
            int seg = i & 15;
            uint32_t off = nrow * STRIDE_B + seg * 16;
            *reinterpret_cast<uint4*>(sm + OFF_WHI + off) = wh[i];
            *reinterpret_cast<uint4*>(sm + OFF_WLO + off) = wl[i];
        }
    }
    __syncthreads();

    const int warp = tid >> 5;
    const int lane = tid & 31;
    const int g = lane >> 2;
    const int j = lane & 3;
    const int wm0 = warp * 16;

    uint32_t ahi[8][4];
    uint32_t alo[8][4];
    {
        const char* bhg = sm + OFF_AHI + (wm0 + g) * STRIDE_B + j * 4;
        const char* bhg8 = bhg + 8 * STRIDE_B;
        const char* blg = sm + OFF_ALO + (wm0 + g) * STRIDE_B + j * 4;
        const char* blg8 = blg + 8 * STRIDE_B;
#pragma unroll
        for (int ks = 0; ks < 8; ks++) {
            int off = ks * 32;
            ahi[ks][0] = *reinterpret_cast<const uint32_t*>(bhg + off);
            ahi[ks][1] = *reinterpret_cast<const uint32_t*>(bhg8 + off);
            ahi[ks][2] = *reinterpret_cast<const uint32_t*>(bhg + off + 16);
            ahi[ks][3] = *reinterpret_cast<const uint32_t*>(bhg8 + off + 16);
            alo[ks][0] = *reinterpret_cast<const uint32_t*>(blg + off);
            alo[ks][1] = *reinterpret_cast<const uint32_t*>(blg8 + off);
            alo[ks][2] = *reinterpret_cast<const uint32_t*>(blg + off + 16);
            alo[ks][3] = *reinterpret_cast<const uint32_t*>(blg8 + off + 16);
        }
    }

    float acc[NT][4];
#pragma unroll
    for (int nt = 0; nt < NT; nt++)
#pragma unroll
        for (int q = 0; q < 4; q++) acc[nt][q] = 0.f;

    {
        const char* bwh = sm + OFF_WHI + g * STRIDE_B + j * 4;
        const char* bwl = sm + OFF_WLO + g * STRIDE_B + j * 4;
#pragma unroll
        for (int nt = 0; nt < NT; nt++) {
            int noff = nt * 8 * STRIDE_B;
#pragma unroll
            for (int ks = 0; ks < 8; ks++) {
                int koff = ks * 32;
                uint32_t bh0 = *reinterpret_cast<const uint32_t*>(bwh + noff + koff);
                uint32_t bh1 = *reinterpret_cast<const uint32_t*>(bwh + noff + koff + 16);
                uint32_t bl0 = *reinterpret_cast<const uint32_t*>(bwl + noff + koff);
                uint32_t bl1 = *reinterpret_cast<const uint32_t*>(bwl + noff + koff + 16);
                mma_bf16(acc[nt], ahi[ks], bh0, bh1);
                mma_bf16(acc[nt], ahi[ks], bl0, bl1);
                mma_bf16(acc[nt], alo[ks], bh0, bh1);
            }
        }
    }
    __syncthreads();

    const float* avs_s = reinterpret_cast<const float*>(sm + OFF_AVS);
    const float* avd_s = reinterpret_cast<const float*>(sm + OFF_AVD);
    float* stage = reinterpret_cast<float*>(sm + OFF_AHI);
    float asum[HEADS][2];
    float dsum[HEADS][2];
#pragma unroll
    for (int h = 0; h < HEADS; h++) {
        asum[h][0] = 0.f; asum[h][1] = 0.f;
        dsum[h][0] = 0.f; dsum[h][1] = 0.f;
    }
#pragma unroll
    for (int nt = 0; nt < NT; nt++) {
        int cn = nt * 8 + 2 * j;
        float av0 = avs_s[cn];
        float av1 = avs_s[cn + 1];
        float dv0 = avd_s[cn];
        float dv1 = avd_s[cn + 1];
        int h = (HEADS == 2 && nt >= NT / 2) ? 1 : 0;
        asum[h][0] += acc[nt][0] * av0 + acc[nt][1] * av1;
        asum[h][1] += acc[nt][2] * av0 + acc[nt][3] * av1;
        dsum[h][0] += acc[nt][0] * dv0 + acc[nt][1] * dv1;
        dsum[h][1] += acc[nt][2] * dv0 + acc[nt][3] * dv1;
        float* st0 = stage + (wm0 + g) * ST_W + cn;
        float* st1 = st0 + 8 * ST_W;
        *reinterpret_cast<float2*>(st0) = make_float2(acc[nt][0], acc[nt][1]);
        *reinterpret_cast<float2*>(st1) = make_float2(acc[nt][2], acc[nt][3]);
    }
#pragma unroll
    for (int off = 1; off <= 2; off <<= 1) {
#pragma unroll
        for (int h = 0; h < HEADS; h++) {
            asum[h][0] += __shfl_xor_sync(0xffffffffu, asum[h][0], off);
            asum[h][1] += __shfl_xor_sync(0xffffffffu, asum[h][1], off);
            dsum[h][0] += __shfl_xor_sync(0xffffffffu, dsum[h][0], off);
            dsum[h][1] += __shfl_xor_sync(0xffffffffu, dsum[h][1], off);
        }
    }
    if (j == 0) {
        int r0 = row0 + wm0 + g;
        int r1 = r0 + 8;
        if (r0 < n) {
#pragma unroll
            for (int h = 0; h < HEADS; h++) {
                as_out[(size_t)r0 * HEADS + h] = asum[h][0];
                ad_out[(size_t)r0 * HEADS + h] = dsum[h][0];
            }
        }
        if (r1 < n) {
#pragma unroll
            for (int h = 0; h < HEADS; h++) {
                as_out[(size_t)r1 * HEADS + h] = asum[h][1];
                ad_out[(size_t)r1 * HEADS + h] = dsum[h][1];
            }
        }
    }
    __syncthreads();

    {
        constexpr int C4 = NOUT / 4;
        float4* out4 = reinterpret_cast<float4*>(Hout);
        for (int i = tid; i < 128 * C4; i += 256) {
            int r = i / C4;
            int c4 = i % C4;
            if (row0 + r < n) {
                float4 v = *reinterpret_cast<const float4*>(stage + r * ST_W + c4 * 4);
                out4[(size_t)(row0 + r) * C4 + c4] = v;
            }
        }
    }
}

// ---------------- CSR build ----------------
__global__ void deg_count(const int* __restrict__ ei, int* __restrict__ deg, int E) {
    int i = blockIdx.x * blockDim.x + threadIdx.x;
    if (i < E) atomicAdd(&deg[ei[E + i]], 1);
}

// shfl-based inclusive scan over 1024-blocks
__global__ void scan_block(const int* __restrict__ deg, int* __restrict__ incl,
                           int* __restrict__ bsum, int n) {
    __shared__ int wsum[32];
    int tid = threadIdx.x;
    int lane = tid & 31;
    int wid = tid >> 5;
    int gid = blockIdx.x * 1024 + tid;
    int v = (gid < n) ? deg[gid] : 0;
#pragma unroll
    for (int off = 1; off < 32; off <<= 1) {
        int t = __shfl_up_sync(0xffffffffu, v, off);
        if (lane >= off) v += t;
    }
    if (lane == 31) wsum[wid] = v;
    __syncthreads();
    if (wid == 0) {
        int w = wsum[lane];
#pragma unroll
        for (int off = 1; off < 32; off <<= 1) {
            int t = __shfl_up_sync(0xffffffffu, w, off);
            if (lane >= off) w += t;
        }
        wsum[lane] = w;
    }
    __syncthreads();
    if (wid > 0) v += wsum[wid - 1];
    if (gid < n) incl[gid] = v;
    if (tid == 1023) bsum[blockIdx.x] = v;
}

// scan_finish with in-block redundant scan of block sums (removes scan_bsum launch)
__global__ void scan_finish(const int* __restrict__ incl, const int* __restrict__ bsum,
                            const int* __restrict__ deg, int* __restrict__ rowptr,
                            int* __restrict__ cursor, int n, int nb) {
    __shared__ int pre[128];
    int tid = threadIdx.x;
    if (tid < 32) {
        int base = tid * 4;
        int v[4];
#pragma unroll
        for (int q = 0; q < 4; q++) v[q] = (base + q < nb) ? bsum[base + q] : 0;
        int tot = v[0] + v[1] + v[2] + v[3];
        int inc = tot;
#pragma unroll
        for (int off = 1; off < 32; off <<= 1) {
            int t = __shfl_up_sync(0xffffffffu, inc, off);
            if (tid >= off) inc += t;
        }
        int run = inc - tot;
#pragma unroll
        for (int q = 0; q < 4; q++) {
            pre[base + q] = run;
            run += v[q];
        }
    }
    __syncthreads();
    int i = blockIdx.x * blockDim.x + tid;
    if (i < n) {
        int end = incl[i] + pre[i >> 10];
        rowptr[i + 1] = end;
        cursor[i] = end - deg[i];
    }
    if (i == 0) rowptr[0] = 0;
}

__global__ void scatter_edges(const int* __restrict__ ei, int* __restrict__ cursor,
                              int* __restrict__ adj, int E, int n) {
    int i = blockIdx.x * blockDim.x + threadIdx.x;
    if (i >= E + n) return;
    int s;
    int d;
    if (i < E) {
        s = ei[i];
        d = ei[E + i];
    } else {
        s = i - E;
        d = s;
    }
    int pos = atomicAdd(&cursor[d], 1);
    adj[pos] = s;
}

// ---------------- layer1 node aggregation ----------------
__global__ void gat_node1(const int* __restrict__ rowptr, const int* __restrict__ adj,
                          const float* __restrict__ as, const float* __restrict__ ad,
                          const float* __restrict__ h, const float* __restrict__ b,
                          float* __restrict__ out, int n) {
    int node = (blockIdx.x * blockDim.x + threadIdx.x) >> 5;
    int lane = threadIdx.x & 31;
    if (node >= n) return;
    int start = rowptr[node];
    int end = rowptr[node + 1];
    float ad0 = ad[node * 2];
    float ad1 = ad[node * 2 + 1];
    bool hi = lane >= 16;

    float4 acc = make_float4(0.f, 0.f, 0.f, 0.f);
    float den0 = 0.f;
    float den1 = 0.f;
    for (int base = start; base < end; base += 32) {
        int cnt = min(32, end - base);
        int s_l = 0;
        float ex0_l = 0.f;
        float ex1_l = 0.f;
        if (lane < cnt) {
            s_l = adj[base + lane];
            float e0 = as[s_l * 2] + ad0;
            e0 = e0 >= 0.f ? e0 : 0.2f * e0;
            float e1 = as[s_l * 2 + 1] + ad1;
            e1 = e1 >= 0.f ? e1 : 0.2f * e1;
            ex0_l = expf(e0);
            ex1_l = expf(e1);
        }
        den0 += ex0_l;
        den1 += ex1_l;
#pragma unroll 4
        for (int tt = 0; tt < cnt; tt++) {
            int s = __shfl_sync(0xffffffffu, s_l, tt);
            float ex0 = __shfl_sync(0xffffffffu, ex0_l, tt);
            float ex1 = __shfl_sync(0xffffffffu, ex1_l, tt);
            float ex = hi ? ex1 : ex0;
            float4 v = reinterpret_cast<const float4*>(h + (size_t)s * 128)[lane];
            acc.x = fmaf(ex, v.x, acc.x);
            acc.y = fmaf(ex, v.y, acc.y);
            acc.z = fmaf(ex, v.z, acc.z);
            acc.w = fmaf(ex, v.w, acc.w);
        }
    }
    for (int o = 16; o > 0; o >>= 1) {
        den0 += __shfl_xor_sync(0xffffffffu, den0, o);
        den1 += __shfl_xor_sync(0xffffffffu, den1, o);
    }
    float den = fmaxf(hi ? den1 : den0, 1e-16f);
    float inv = 1.f / den;
    float4 bb = reinterpret_cast<const float4*>(b)[lane];
    float4 o;
    o.x = fmaxf(fmaf(acc.x, inv, bb.x), 0.f);
    o.y = fmaxf(fmaf(acc.y, inv, bb.y), 0.f);
    o.z = fmaxf(fmaf(acc.z, inv, bb.z), 0.f);
    o.w = fmaxf(fmaf(acc.w, inv, bb.w), 0.f);
    reinterpret_cast<float4*>(out + (size_t)node * 128)[lane] = o;
}

// ---------------- layer2 node aggregation ----------------
__global__ void gat_node2(const int* __restrict__ rowptr, const int* __restrict__ adj,
                          const float* __restrict__ as, const float* __restrict__ ad,
                          const float* __restrict__ h, const float* __restrict__ b,
                          float* __restrict__ out, int n) {
    int node = (blockIdx.x * blockDim.x + threadIdx.x) >> 5;
    int lane = threadIdx.x & 31;
    if (node >= n) return;
    int start = rowptr[node];
    int end = rowptr[node + 1];
    float add = ad[node];

    float2 acc = make_float2(0.f, 0.f);
    float den = 0.f;
    for (int base = start; base < end; base += 32) {
        int cnt = min(32, end - base);
        int s_l = 0;
        float ex_l = 0.f;
        if (lane < cnt) {
            s_l = adj[base + lane];
            float e = as[s_l] + add;
            e = e >= 0.f ? e : 0.2f * e;
            ex_l = expf(e);
        }
        den += ex_l;
#pragma unroll 4
        for (int tt = 0; tt < cnt; tt++) {
            int s = __shfl_sync(0xffffffffu, s_l, tt);
            float ex = __shfl_sync(0xffffffffu, ex_l, tt);
            float2 v = reinterpret_cast<const float2*>(h + (size_t)s * 64)[lane];
            acc.x = fmaf(ex, v.x, acc.x);
            acc.y = fmaf(ex, v.y, acc.y);
        }
    }
    for (int o = 16; o > 0; o >>= 1) {
        den += __shfl_xor_sync(0xffffffffu, den, o);
    }
    float inv = 1.f / fmaxf(den, 1e-16f);
    float2 bb = reinterpret_cast<const float2*>(b)[lane];
    float2 o;
    o.x = fmaf(acc.x, inv, bb.x);
    o.y = fmaf(acc.y, inv, bb.y);
    reinterpret_cast<float2*>(out + (size_t)node * 64)[lane] = o;
}

// ---------------- per-graph pooling (batch sorted) ----------------
__global__ void pool_seg(const float* __restrict__ h, const int* __restrict__ batch,
                         float* __restrict__ psum, float* __restrict__ pmax,
                         float* __restrict__ cnt, int n) {
    int n0 = blockIdx.x * 128;
    int t = threadIdx.x;
    int c = t & 63;
    int off = t >> 6;
    int gcur = -1;
    float sum = 0.f;
    float mx = -FLT_MAX;
    float count = 0.f;
    int lim = min(n0 + 128, n);
    for (int i = n0 + off; i < lim; i += 4) {
        int g = batch[i];
        if (g != gcur) {
            if (gcur >= 0) {
                atomicAdd(&psum[gcur * 64 + c], sum);
                atomicMaxF(&pmax[gcur * 64 + c], mx);
                if (c == 0) atomicAdd(&cnt[gcur], count);
            }
            gcur = g;
            sum = 0.f;
            mx = -FLT_MAX;
            count = 0.f;
        }
        float v = h[(size_t)i * 64 + c];
        sum += v;
        mx = fmaxf(mx, v);
        count += 1.f;
    }
    if (gcur >= 0) {
        atomicAdd(&psum[gcur * 64 + c], sum);
        atomicMaxF(&pmax[gcur * 64 + c], mx);
        if (c == 0) atomicAdd(&cnt[gcur], count);
    }
}

// ---------------- final MLP head ----------------
__global__ void final_mlp_kernel(const float* __restrict__ psum, const float* __restrict__ pmax,
                                 const float* __restrict__ cnt, const float* __restrict__ Wf1,
                                 const float* __restrict__ bf1, const float* __restrict__ Wf2,
                                 const float* __restrict__ bf2, float* __restrict__ out) {
    __shared__ float pooled[128];
    __shared__ float red[64];
    int g = blockIdx.x;
    int t = threadIdx.x;
    float c = cnt[g];
    pooled[t] = psum[g * 64 + t] / fmaxf(c, 1.f);
    pooled[64 + t] = (c > 0.f) ? pmax[g * 64 + t] : 0.f;
    __syncthreads();
    float hj = bf1[t];
    for (int k = 0; k < 128; k++) {
        hj = fmaf(pooled[k], Wf1[k * 64 + t], hj);
    }
    hj = fmaxf(hj, 0.f);
    red[t] = hj * Wf2[t];
    __syncthreads();
    for (int s = 32; s > 0; s >>= 1) {
        if (t < s) red[t] += red[t + s];
        __syncthreads();
    }
    if (t == 0) out[g] = red[0] + bf2[0];
}

// ---------------- host launch ----------------
static inline int cdiv(int a, int b) { return (a + b - 1) / b; }

extern "C" void kernel_launch(void* const* d_in, const int* in_sizes, int n_in,
                              void* d_out, int out_size) {
    const float* x = (const float*)d_in[0];
    const int* ei = (const int*)d_in[1];
    const int* bat = (const int*)d_in[2];
    const float* W1 = (const float*)d_in[3];
    const float* as1 = (const float*)d_in[4];
    const float* ad1 = (const float*)d_in[5];
    const float* b1 = (const float*)d_in[6];
    const float* W2 = (const float*)d_in[7];
    const float* as2 = (const float*)d_in[8];
    const float* ad2 = (const float*)d_in[9];
    const float* b2 = (const float*)d_in[10];
    const float* Wf1 = (const float*)d_in[11];
    const float* bf1 = (const float*)d_in[12];
    const float* Wf2 = (const float*)d_in[13];
    const float* bf2 = (const float*)d_in[14];
    float* out = (float*)d_out;

    const int n = in_sizes[0] / 128;
    const int E = in_sizes[1] / 2;
    const int G = out_size;

    float* p_h1;
    float* p_o1;
    float* p_h2;
    float* p_o2;
    float* p_as1;
    float* p_ad1;
    float* p_as2;
    float* p_ad2;
    float* p_psum;
    float* p_pmax;
    float* p_cnt;
    int* p_deg;
    int* p_incl;
    int* p_bsum;
    int* p_rowptr;
    int* p_cursor;
    int* p_adj;
    __nv_bfloat16* p_w1hi;
    __nv_bfloat16* p_w1lo;
    __nv_bfloat16* p_w2hi;
    __nv_bfloat16* p_w2lo;
    cudaGetSymbolAddress((void**)&p_h1, g_h1);
    cudaGetSymbolAddress((void**)&p_o1, g_o1);
    cudaGetSymbolAddress((void**)&p_h2, g_h2);
    cudaGetSymbolAddress((void**)&p_o2, g_o2);
    cudaGetSymbolAddress((void**)&p_as1, g_as1);
    cudaGetSymbolAddress((void**)&p_ad1, g_ad1);
    cudaGetSymbolAddress((void**)&p_as2, g_as2);
    cudaGetSymbolAddress((void**)&p_ad2, g_ad2);
    cudaGetSymbolAddress((void**)&p_psum, g_psum);
    cudaGetSymbolAddress((void**)&p_pmax, g_pmax);
    cudaGetSymbolAddress((void**)&p_cnt, g_cnt);
    cudaGetSymbolAddress((void**)&p_deg, g_deg);
    cudaGetSymbolAddress((void**)&p_incl, g_incl);
    cudaGetSymbolAddress((void**)&p_bsum, g_bsum);
    cudaGetSymbolAddress((void**)&p_rowptr, g_rowptr);
    cudaGetSymbolAddress((void**)&p_cursor, g_cursor);
    cudaGetSymbolAddress((void**)&p_adj, g_adj);
    cudaGetSymbolAddress((void**)&p_w1hi, g_w1hi);
    cudaGetSymbolAddress((void**)&p_w1lo, g_w1lo);
    cudaGetSymbolAddress((void**)&p_w2hi, g_w2hi);
    cudaGetSymbolAddress((void**)&p_w2lo, g_w2lo);

    const int TB = 256;
    const int nb = cdiv(n, 1024);

    const int SMEM1 = 1024 + 2 * 34816 + 2 * 128 * 272;  // 140288
    const int SMEM2 = 1024 + 2 * 34816 + 2 * 64 * 272;   // 105472
    cudaFuncSetAttribute(gemm_mma<128, 2>, cudaFuncAttributeMaxDynamicSharedMemorySize, SMEM1);
    cudaFuncSetAttribute(gemm_mma<64, 1>, cudaFuncAttributeMaxDynamicSharedMemorySize, SMEM2);

    static cudaStream_t s2 = nullptr;
    static cudaEvent_t evA = nullptr;
    static cudaEvent_t evB = nullptr;
    if (s2 == nullptr) {
        cudaStreamCreateWithFlags(&s2, cudaStreamNonBlocking);
        cudaEventCreateWithFlags(&evA, cudaEventDisableTiming);
        cudaEventCreateWithFlags(&evB, cudaEventDisableTiming);
    }

    // launch 0: setup (weights + deg init + pool fills)
    setup_kernel<<<cdiv(n, TB), TB>>>(W1, W2, p_w1hi, p_w1lo, p_w2hi, p_w2lo, p_deg,
                                      p_psum, p_pmax, p_cnt, n, G);

    // fork CSR chain to side stream
    cudaEventRecord(evA, 0);
    cudaStreamWaitEvent(s2, evA, 0);
    deg_count<<<cdiv(E, TB), TB, 0, s2>>>(ei, p_deg, E);        // launch 1
    scan_block<<<nb, 1024, 0, s2>>>(p_deg, p_incl, p_bsum, n);  // launch 2

    // launch 3 (profiled slot): layer-1 GEMM on main stream
    gemm_mma<128, 2><<<cdiv(n, 128), 256, SMEM1>>>(x, p_w1hi, p_w1lo, as1, ad1, p_h1, p_as1,
                                                   p_ad1, n);

    scan_finish<<<cdiv(n, TB), TB, 0, s2>>>(p_incl, p_bsum, p_deg, p_rowptr, p_cursor, n, nb);
    scatter_edges<<<cdiv(E + n, TB), TB, 0, s2>>>(ei, p_cursor, p_adj, E, n);
    cudaEventRecord(evB, s2);

    // join: gat_node1 needs gemm1 + CSR
    cudaStreamWaitEvent(0, evB, 0);
    gat_node1<<<cdiv(n * 32, TB), TB>>>(p_rowptr, p_adj, p_as1, p_ad1, p_h1, b1, p_o1, n);

    // layer 2
    gemm_mma<64, 1><<<cdiv(n, 128), 256, SMEM2>>>(p_o1, p_w2hi, p_w2lo, as2, ad2, p_h2, p_as2,
                                                  p_ad2, n);
    gat_node2<<<cdiv(n * 32, TB), TB>>>(p_rowptr, p_adj, p_as2, p_ad2, p_h2, b2, p_o2, n);

    // pooling + head
    pool_seg<<<cdiv(n, 128), 256>>>(p_o2, bat, p_psum, p_pmax, p_cnt, n);
    final_mlp_kernel<<<G, 64>>>(p_psum, p_pmax, p_cnt, Wf1, bf1, Wf2, bf2, out);
}

// round 10
// speedup vs baseline: 3.1117x; 1.2726x over previous
#include <cuda_runtime.h>
#include <cuda_bf16.h>
#include <cstdint>
#include <stdint.h>
#include <float.h>
#include <math.h>

#define MAX_NODES 100000
#define MAX_EDGES 600000
#define MAX_GRAPHS 512

// ---------------- scratch (device globals) ----------------
__device__ float g_h1[(size_t)MAX_NODES * 128];
__device__ float g_o1[(size_t)MAX_NODES * 128];
__device__ float g_h2[(size_t)MAX_NODES * 64];
__device__ float g_o2[(size_t)MAX_NODES * 64];
__device__ float g_as1[MAX_NODES * 2];
__device__ float g_ad1[MAX_NODES * 2];
__device__ float g_as2[MAX_NODES];
__device__ float g_ad2[MAX_NODES];
// fragment-packed weights: word idx = ((n*8+ks)*4+j)*4 + {hi_k, hi_k8, lo_k, lo_k8}
__device__ uint32_t g_w1pk[128 * 128];  // 64KB
__device__ uint32_t g_w2pk[64 * 128];   // 32KB
__device__ int g_deg[MAX_NODES];
__device__ int g_incl[MAX_NODES];
__device__ int g_bsum[256];
__device__ int g_rowptr[MAX_NODES + 1];
__device__ int g_cursor[MAX_NODES];
__device__ int g_adj[MAX_EDGES + MAX_NODES];
__device__ float g_psum[MAX_GRAPHS * 64];
__device__ float g_pmax[MAX_GRAPHS * 64];
__device__ float g_cnt[MAX_GRAPHS];

// ---------------- misc ----------------
__device__ __forceinline__ void atomicMaxF(float* addr, float value) {
    if (value >= 0.f) {
        atomicMax((int*)addr, __float_as_int(value));
    } else {
        atomicMin((unsigned int*)addr, __float_as_uint(value));
    }
}

__device__ __forceinline__ void mma_bf16(float* d, const uint32_t* a, uint32_t b0, uint32_t b1) {
    asm volatile(
        "mma.sync.aligned.m16n8k16.row.col.f32.bf16.bf16.f32 "
        "{%0, %1, %2, %3}, {%4, %5, %6, %7}, {%8, %9}, {%0, %1, %2, %3};"
        : "+f"(d[0]), "+f"(d[1]), "+f"(d[2]), "+f"(d[3])
        : "r"(a[0]), "r"(a[1]), "r"(a[2]), "r"(a[3]), "r"(b0), "r"(b1));
}

__device__ __forceinline__ void cvt_hilo(float2 x, uint32_t& hi, uint32_t& lo) {
    __nv_bfloat16 h0 = __float2bfloat16(x.x);
    __nv_bfloat16 h1 = __float2bfloat16(x.y);
    __nv_bfloat16 l0 = __float2bfloat16(x.x - __bfloat162float(h0));
    __nv_bfloat16 l1 = __float2bfloat16(x.y - __bfloat162float(h1));
    hi = (uint32_t)__bfloat16_as_ushort(h0) | ((uint32_t)__bfloat16_as_ushort(h1) << 16);
    lo = (uint32_t)__bfloat16_as_ushort(l0) | ((uint32_t)__bfloat16_as_ushort(l1) << 16);
}

// ---------------- setup: deg=1 + fragment-packed weight preps + pool fills ----------------
__global__ void setup_kernel(const float* __restrict__ W1, const float* __restrict__ W2,
                             uint32_t* __restrict__ w1pk, uint32_t* __restrict__ w2pk,
                             int* __restrict__ deg, float* __restrict__ psum,
                             float* __restrict__ pmax, float* __restrict__ cnt, int n, int gtot) {
    int idx = blockIdx.x * blockDim.x + threadIdx.x;
    if (idx < n) deg[idx] = 1;
    if (idx < 128 * 64) {  // W1 pairs: nout=128, 64 k-pairs per n-row
        int nr = idx >> 6;
        int p = idx & 63;
        int k0 = p * 2;
        int ks = k0 >> 4;
        int r = k0 & 15;
        int halfk = r >> 3;
        int j = (r & 7) >> 1;
        float2 v = make_float2(W1[k0 * 128 + nr], W1[(k0 + 1) * 128 + nr]);
        uint32_t hw;
        uint32_t lw;
        cvt_hilo(v, hw, lw);
        int base = ((nr * 8 + ks) * 4 + j) * 4;
        w1pk[base + halfk] = hw;
        w1pk[base + 2 + halfk] = lw;
    }
    if (idx < 64 * 64) {  // W2 pairs: nout=64
        int nr = idx >> 6;
        int p = idx & 63;
        int k0 = p * 2;
        int ks = k0 >> 4;
        int r = k0 & 15;
        int halfk = r >> 3;
        int j = (r & 7) >> 1;
        float2 v = make_float2(W2[k0 * 64 + nr], W2[(k0 + 1) * 64 + nr]);
        uint32_t hw;
        uint32_t lw;
        cvt_hilo(v, hw, lw);
        int base = ((nr * 8 + ks) * 4 + j) * 4;
        w2pk[base + halfk] = hw;
        w2pk[base + 2 + halfk] = lw;
    }
    if (idx < gtot * 64) {
        psum[idx] = 0.f;
        pmax[idx] = -FLT_MAX;
    }
    if (idx < gtot) cnt[idx] = 0.f;
}

// ---------------- HMMA GEMM: A frags from global, W frags one LDS.128, direct C stores ----------------
// C[n,NOUT] = A[n,128] @ W; 128 rows/CTA (8 warps x 16 rows); D = Ahi*Whi + Ahi*Wlo + Alo*Whi
template <int NOUT, int HEADS>
__global__ __launch_bounds__(256, 2) void gemm_mma(
    const float* __restrict__ A, const uint32_t* __restrict__ Wpk,
    const float* __restrict__ avs, const float* __restrict__ avd, float* __restrict__ Hout,
    float* __restrict__ as_out, float* __restrict__ ad_out, int n) {
    extern __shared__ __align__(16) char sm[];
    constexpr int NT = NOUT / 8;
    constexpr int WST = 576;  // smem bytes per W n-row (512 data + 64 pad, conflict-free LDS.128)
    const uint32_t OFF_AVS = 0;
    const uint32_t OFF_AVD = 512;
    const uint32_t OFF_W = 1024;

    const int tid = threadIdx.x;
    const int row0 = blockIdx.x * 128;

    if (tid < NOUT) {
        reinterpret_cast<float*>(sm + OFF_AVS)[tid] = avs[tid];
        reinterpret_cast<float*>(sm + OFF_AVD)[tid] = avd[tid];
    }
    // copy packed W -> smem with 576B row stride
    {
        const uint4* wsrc = reinterpret_cast<const uint4*>(Wpk);
#pragma unroll
        for (int i = tid; i < NOUT * 32; i += 256) {
            int nr = i >> 5;
            int w = i & 31;
            *reinterpret_cast<uint4*>(sm + OFF_W + nr * WST + w * 16) = wsrc[i];
        }
    }
    __syncthreads();

    const int warp = tid >> 5;
    const int lane = tid & 31;
    const int g = lane >> 2;
    const int j = lane & 3;
    const int wm0 = warp * 16;

    const int rowA0 = row0 + wm0 + g;
    const int rowA1 = rowA0 + 8;
    const bool v0r = rowA0 < n;
    const bool v1r = rowA1 < n;
    const float* a0p = A + (size_t)rowA0 * 128 + j * 2;
    const float* a1p = A + (size_t)rowA1 * 128 + j * 2;

    float acc[NT][4];
#pragma unroll
    for (int nt = 0; nt < NT; nt++)
#pragma unroll
        for (int q = 0; q < 4; q++) acc[nt][q] = 0.f;

    const char* bw = sm + OFF_W + g * WST + j * 16;
    const float2 z2 = make_float2(0.f, 0.f);
#pragma unroll
    for (int ks = 0; ks < 8; ks++) {
        float2 x00 = v0r ? *reinterpret_cast<const float2*>(a0p + ks * 16) : z2;
        float2 x01 = v0r ? *reinterpret_cast<const float2*>(a0p + ks * 16 + 8) : z2;
        float2 x10 = v1r ? *reinterpret_cast<const float2*>(a1p + ks * 16) : z2;
        float2 x11 = v1r ? *reinterpret_cast<const float2*>(a1p + ks * 16 + 8) : z2;
        uint32_t ahi[4];
        uint32_t alo[4];
        cvt_hilo(x00, ahi[0], alo[0]);
        cvt_hilo(x10, ahi[1], alo[1]);
        cvt_hilo(x01, ahi[2], alo[2]);
        cvt_hilo(x11, ahi[3], alo[3]);
        const char* bks = bw + ks * 64;
#pragma unroll
        for (int nt = 0; nt < NT; nt++) {
            uint4 b = *reinterpret_cast<const uint4*>(bks + nt * 8 * WST);
            mma_bf16(acc[nt], ahi, b.x, b.y);
            mma_bf16(acc[nt], ahi, b.z, b.w);
            mma_bf16(acc[nt], alo, b.x, b.y);
        }
    }

    // epilogue: alpha partials + direct C stores
    const float* avs_s = reinterpret_cast<const float*>(sm + OFF_AVS);
    const float* avd_s = reinterpret_cast<const float*>(sm + OFF_AVD);
    float asum[HEADS][2];
    float dsum[HEADS][2];
#pragma unroll
    for (int h = 0; h < HEADS; h++) {
        asum[h][0] = 0.f;
        asum[h][1] = 0.f;
        dsum[h][0] = 0.f;
        dsum[h][1] = 0.f;
    }
#pragma unroll
    for (int nt = 0; nt < NT; nt++) {
        int cn = nt * 8 + 2 * j;
        float av0 = avs_s[cn];
        float av1 = avs_s[cn + 1];
        float dv0 = avd_s[cn];
        float dv1 = avd_s[cn + 1];
        int h = (HEADS == 2 && nt >= NT / 2) ? 1 : 0;
        asum[h][0] += acc[nt][0] * av0 + acc[nt][1] * av1;
        asum[h][1] += acc[nt][2] * av0 + acc[nt][3] * av1;
        dsum[h][0] += acc[nt][0] * dv0 + acc[nt][1] * dv1;
        dsum[h][1] += acc[nt][2] * dv0 + acc[nt][3] * dv1;
        if (v0r)
            *reinterpret_cast<float2*>(Hout + (size_t)rowA0 * NOUT + cn) =
                make_float2(acc[nt][0], acc[nt][1]);
        if (v1r)
            *reinterpret_cast<float2*>(Hout + (size_t)rowA1 * NOUT + cn) =
                make_float2(acc[nt][2], acc[nt][3]);
    }
#pragma unroll
    for (int off = 1; off <= 2; off <<= 1) {
#pragma unroll
        for (int h = 0; h < HEADS; h++) {
            asum[h][0] += __shfl_xor_sync(0xffffffffu, asum[h][0], off);
            asum[h][1] += __shfl_xor_sync(0xffffffffu, asum[h][1], off);
            dsum[h][0] += __shfl_xor_sync(0xffffffffu, dsum[h][0], off);
            dsum[h][1] += __shfl_xor_sync(0xffffffffu, dsum[h][1], off);
        }
    }
    if (j == 0) {
        if (v0r) {
#pragma unroll
            for (int h = 0; h < HEADS; h++) {
                as_out[(size_t)rowA0 * HEADS + h] = asum[h][0];
                ad_out[(size_t)rowA0 * HEADS + h] = dsum[h][0];
            }
        }
        if (v1r) {
#pragma unroll
            for (int h = 0; h < HEADS; h++) {
                as_out[(size_t)rowA1 * HEADS + h] = asum[h][1];
                ad_out[(size_t)rowA1 * HEADS + h] = dsum[h][1];
            }
        }
    }
}

// ---------------- CSR build ----------------
__global__ void deg_count(const int* __restrict__ ei, int* __restrict__ deg, int E) {
    int i = blockIdx.x * blockDim.x + threadIdx.x;
    if (i < E) atomicAdd(&deg[ei[E + i]], 1);
}

__global__ void scan_block(const int* __restrict__ deg, int* __restrict__ incl,
                           int* __restrict__ bsum, int n) {
    __shared__ int wsum[32];
    int tid = threadIdx.x;
    int lane = tid & 31;
    int wid = tid >> 5;
    int gid = blockIdx.x * 1024 + tid;
    int v = (gid < n) ? deg[gid] : 0;
#pragma unroll
    for (int off = 1; off < 32; off <<= 1) {
        int t = __shfl_up_sync(0xffffffffu, v, off);
        if (lane >= off) v += t;
    }
    if (lane == 31) wsum[wid] = v;
    __syncthreads();
    if (wid == 0) {
        int w = wsum[lane];
#pragma unroll
        for (int off = 1; off < 32; off <<= 1) {
            int t = __shfl_up_sync(0xffffffffu, w, off);
            if (lane >= off) w += t;
        }
        wsum[lane] = w;
    }
    __syncthreads();
    if (wid > 0) v += wsum[wid - 1];
    if (gid < n) incl[gid] = v;
    if (tid == 1023) bsum[blockIdx.x] = v;
}

__global__ void scan_finish(const int* __restrict__ incl, const int* __restrict__ bsum,
                            const int* __restrict__ deg, int* __restrict__ rowptr,
                            int* __restrict__ cursor, int n, int nb) {
    __shared__ int pre[128];
    int tid = threadIdx.x;
    if (tid < 32) {
        int base = tid * 4;
        int v[4];
#pragma unroll
        for (int q = 0; q < 4; q++) v[q] = (base + q < nb) ? bsum[base + q] : 0;
        int tot = v[0] + v[1] + v[2] + v[3];
        int inc = tot;
#pragma unroll
        for (int off = 1; off < 32; off <<= 1) {
            int t = __shfl_up_sync(0xffffffffu, inc, off);
            if (tid >= off) inc += t;
        }
        int run = inc - tot;
#pragma unroll
        for (int q = 0; q < 4; q++) {
            pre[base + q] = run;
            run += v[q];
        }
    }
    __syncthreads();
    int i = blockIdx.x * blockDim.x + tid;
    if (i < n) {
        int end = incl[i] + pre[i >> 10];
        rowptr[i + 1] = end;
        cursor[i] = end - deg[i];
    }
    if (i == 0) rowptr[0] = 0;
}

__global__ void scatter_edges(const int* __restrict__ ei, int* __restrict__ cursor,
                              int* __restrict__ adj, int E, int n) {
    int i = blockIdx.x * blockDim.x + threadIdx.x;
    if (i >= E + n) return;
    int s;
    int d;
    if (i < E) {
        s = ei[i];
        d = ei[E + i];
    } else {
        s = i - E;
        d = s;
    }
    int pos = atomicAdd(&cursor[d], 1);
    adj[pos] = s;
}

// ---------------- layer1 node aggregation ----------------
__global__ void gat_node1(const int* __restrict__ rowptr, const int* __restrict__ adj,
                          const float* __restrict__ as, const float* __restrict__ ad,
                          const float* __restrict__ h, const float* __restrict__ b,
                          float* __restrict__ out, int n) {
    int node = (blockIdx.x * blockDim.x + threadIdx.x) >> 5;
    int lane = threadIdx.x & 31;
    if (node >= n) return;
    int start = rowptr[node];
    int end = rowptr[node + 1];
    float ad0 = ad[node * 2];
    float ad1 = ad[node * 2 + 1];
    bool hi = lane >= 16;

    float4 acc = make_float4(0.f, 0.f, 0.f, 0.f);
    float den0 = 0.f;
    float den1 = 0.f;
    for (int base = start; base < end; base += 32) {
        int cnt = min(32, end - base);
        int s_l = 0;
        float ex0_l = 0.f;
        float ex1_l = 0.f;
        if (lane < cnt) {
            s_l = adj[base + lane];
            float e0 = as[s_l * 2] + ad0;
            e0 = e0 >= 0.f ? e0 : 0.2f * e0;
            float e1 = as[s_l * 2 + 1] + ad1;
            e1 = e1 >= 0.f ? e1 : 0.2f * e1;
            ex0_l = expf(e0);
            ex1_l = expf(e1);
        }
        den0 += ex0_l;
        den1 += ex1_l;
#pragma unroll 4
        for (int tt = 0; tt < cnt; tt++) {
            int s = __shfl_sync(0xffffffffu, s_l, tt);
            float ex0 = __shfl_sync(0xffffffffu, ex0_l, tt);
            float ex1 = __shfl_sync(0xffffffffu, ex1_l, tt);
            float ex = hi ? ex1 : ex0;
            float4 v = reinterpret_cast<const float4*>(h + (size_t)s * 128)[lane];
            acc.x = fmaf(ex, v.x, acc.x);
            acc.y = fmaf(ex, v.y, acc.y);
            acc.z = fmaf(ex, v.z, acc.z);
            acc.w = fmaf(ex, v.w, acc.w);
        }
    }
    for (int o = 16; o > 0; o >>= 1) {
        den0 += __shfl_xor_sync(0xffffffffu, den0, o);
        den1 += __shfl_xor_sync(0xffffffffu, den1, o);
    }
    float den = fmaxf(hi ? den1 : den0, 1e-16f);
    float inv = 1.f / den;
    float4 bb = reinterpret_cast<const float4*>(b)[lane];
    float4 o;
    o.x = fmaxf(fmaf(acc.x, inv, bb.x), 0.f);
    o.y = fmaxf(fmaf(acc.y, inv, bb.y), 0.f);
    o.z = fmaxf(fmaf(acc.z, inv, bb.z), 0.f);
    o.w = fmaxf(fmaf(acc.w, inv, bb.w), 0.f);
    reinterpret_cast<float4*>(out + (size_t)node * 128)[lane] = o;
}

// ---------------- layer2 node aggregation ----------------
__global__ void gat_node2(const int* __restrict__ rowptr, const int* __restrict__ adj,
                          const float* __restrict__ as, const float* __restrict__ ad,
                          const float* __restrict__ h, const float* __restrict__ b,
                          float* __restrict__ out, int n) {
    int node = (blockIdx.x * blockDim.x + threadIdx.x) >> 5;
    int lane = threadIdx.x & 31;
    if (node >= n) return;
    int start = rowptr[node];
    int end = rowptr[node + 1];
    float add = ad[node];

    float2 acc = make_float2(0.f, 0.f);
    float den = 0.f;
    for (int base = start; base < end; base += 32) {
        int cnt = min(32, end - base);
        int s_l = 0;
        float ex_l = 0.f;
        if (lane < cnt) {
            s_l = adj[base + lane];
            float e = as[s_l] + add;
            e = e >= 0.f ? e : 0.2f * e;
            ex_l = expf(e);
        }
        den += ex_l;
#pragma unroll 4
        for (int tt = 0; tt < cnt; tt++) {
            int s = __shfl_sync(0xffffffffu, s_l, tt);
            float ex = __shfl_sync(0xffffffffu, ex_l, tt);
            float2 v = reinterpret_cast<const float2*>(h + (size_t)s * 64)[lane];
            acc.x = fmaf(ex, v.x, acc.x);
            acc.y = fmaf(ex, v.y, acc.y);
        }
    }
    for (int o = 16; o > 0; o >>= 1) {
        den += __shfl_xor_sync(0xffffffffu, den, o);
    }
    float inv = 1.f / fmaxf(den, 1e-16f);
    float2 bb = reinterpret_cast<const float2*>(b)[lane];
    float2 o;
    o.x = fmaf(acc.x, inv, bb.x);
    o.y = fmaf(acc.y, inv, bb.y);
    reinterpret_cast<float2*>(out + (size_t)node * 64)[lane] = o;
}

// ---------------- per-graph pooling (batch sorted) ----------------
__global__ void pool_seg(const float* __restrict__ h, const int* __restrict__ batch,
                         float* __restrict__ psum, float* __restrict__ pmax,
                         float* __restrict__ cnt, int n) {
    int n0 = blockIdx.x * 128;
    int t = threadIdx.x;
    int c = t & 63;
    int off = t >> 6;
    int gcur = -1;
    float sum = 0.f;
    float mx = -FLT_MAX;
    float count = 0.f;
    int lim = min(n0 + 128, n);
    for (int i = n0 + off; i < lim; i += 4) {
        int g = batch[i];
        if (g != gcur) {
            if (gcur >= 0) {
                atomicAdd(&psum[gcur * 64 + c], sum);
                atomicMaxF(&pmax[gcur * 64 + c], mx);
                if (c == 0) atomicAdd(&cnt[gcur], count);
            }
            gcur = g;
            sum = 0.f;
            mx = -FLT_MAX;
            count = 0.f;
        }
        float v = h[(size_t)i * 64 + c];
        sum += v;
        mx = fmaxf(mx, v);
        count += 1.f;
    }
    if (gcur >= 0) {
        atomicAdd(&psum[gcur * 64 + c], sum);
        atomicMaxF(&pmax[gcur * 64 + c], mx);
        if (c == 0) atomicAdd(&cnt[gcur], count);
    }
}

// ---------------- final MLP head ----------------
__global__ void final_mlp_kernel(const float* __restrict__ psum, const float* __restrict__ pmax,
                                 const float* __restrict__ cnt, const float* __restrict__ Wf1,
                                 const float* __restrict__ bf1, const float* __restrict__ Wf2,
                                 const float* __restrict__ bf2, float* __restrict__ out) {
    __shared__ float pooled[128];
    __shared__ float red[64];
    int g = blockIdx.x;
    int t = threadIdx.x;
    float c = cnt[g];
    pooled[t] = psum[g * 64 + t] / fmaxf(c, 1.f);
    pooled[64 + t] = (c > 0.f) ? pmax[g * 64 + t] : 0.f;
    __syncthreads();
    float hj = bf1[t];
    for (int k = 0; k < 128; k++) {
        hj = fmaf(pooled[k], Wf1[k * 64 + t], hj);
    }
    hj = fmaxf(hj, 0.f);
    red[t] = hj * Wf2[t];
    __syncthreads();
    for (int s = 32; s > 0; s >>= 1) {
        if (t < s) red[t] += red[t + s];
        __syncthreads();
    }
    if (t == 0) out[g] = red[0] + bf2[0];
}

// ---------------- host launch ----------------
static inline int cdiv(int a, int b) { return (a + b - 1) / b; }

extern "C" void kernel_launch(void* const* d_in, const int* in_sizes, int n_in,
                              void* d_out, int out_size) {
    const float* x = (const float*)d_in[0];
    const int* ei = (const int*)d_in[1];
    const int* bat = (const int*)d_in[2];
    const float* W1 = (const float*)d_in[3];
    const float* as1 = (const float*)d_in[4];
    const float* ad1 = (const float*)d_in[5];
    const float* b1 = (const float*)d_in[6];
    const float* W2 = (const float*)d_in[7];
    const float* as2 = (const float*)d_in[8];
    const float* ad2 = (const float*)d_in[9];
    const float* b2 = (const float*)d_in[10];
    const float* Wf1 = (const float*)d_in[11];
    const float* bf1 = (const float*)d_in[12];
    const float* Wf2 = (const float*)d_in[13];
    const float* bf2 = (const float*)d_in[14];
    float* out = (float*)d_out;

    const int n = in_sizes[0] / 128;
    const int E = in_sizes[1] / 2;
    const int G = out_size;

    float* p_h1;
    float* p_o1;
    float* p_h2;
    float* p_o2;
    float* p_as1;
    float* p_ad1;
    float* p_as2;
    float* p_ad2;
    float* p_psum;
    float* p_pmax;
    float* p_cnt;
    int* p_deg;
    int* p_incl;
    int* p_bsum;
    int* p_rowptr;
    int* p_cursor;
    int* p_adj;
    uint32_t* p_w1pk;
    uint32_t* p_w2pk;
    cudaGetSymbolAddress((void**)&p_h1, g_h1);
    cudaGetSymbolAddress((void**)&p_o1, g_o1);
    cudaGetSymbolAddress((void**)&p_h2, g_h2);
    cudaGetSymbolAddress((void**)&p_o2, g_o2);
    cudaGetSymbolAddress((void**)&p_as1, g_as1);
    cudaGetSymbolAddress((void**)&p_ad1, g_ad1);
    cudaGetSymbolAddress((void**)&p_as2, g_as2);
    cudaGetSymbolAddress((void**)&p_ad2, g_ad2);
    cudaGetSymbolAddress((void**)&p_psum, g_psum);
    cudaGetSymbolAddress((void**)&p_pmax, g_pmax);
    cudaGetSymbolAddress((void**)&p_cnt, g_cnt);
    cudaGetSymbolAddress((void**)&p_deg, g_deg);
    cudaGetSymbolAddress((void**)&p_incl, g_incl);
    cudaGetSymbolAddress((void**)&p_bsum, g_bsum);
    cudaGetSymbolAddress((void**)&p_rowptr, g_rowptr);
    cudaGetSymbolAddress((void**)&p_cursor, g_cursor);
    cudaGetSymbolAddress((void**)&p_adj, g_adj);
    cudaGetSymbolAddress((void**)&p_w1pk, g_w1pk);
    cudaGetSymbolAddress((void**)&p_w2pk, g_w2pk);

    const int TB = 256;
    const int nb = cdiv(n, 1024);

    const int SMEM1 = 1024 + 128 * 576;  // 74752
    const int SMEM2 = 1024 + 64 * 576;   // 37888
    cudaFuncSetAttribute(gemm_mma<128, 2>, cudaFuncAttributeMaxDynamicSharedMemorySize, SMEM1);
    cudaFuncSetAttribute(gemm_mma<64, 1>, cudaFuncAttributeMaxDynamicSharedMemorySize, SMEM2);

    static cudaStream_t s2 = nullptr;
    static cudaEvent_t evA = nullptr;
    static cudaEvent_t evB = nullptr;
    if (s2 == nullptr) {
        cudaStreamCreateWithFlags(&s2, cudaStreamNonBlocking);
        cudaEventCreateWithFlags(&evA, cudaEventDisableTiming);
        cudaEventCreateWithFlags(&evB, cudaEventDisableTiming);
    }

    // launch 0: setup (packed weights + deg init + pool fills)
    setup_kernel<<<cdiv(n, TB), TB>>>(W1, W2, p_w1pk, p_w2pk, p_deg, p_psum, p_pmax, p_cnt, n, G);

    // fork CSR chain to side stream
    cudaEventRecord(evA, 0);
    cudaStreamWaitEvent(s2, evA, 0);
    deg_count<<<cdiv(E, TB), TB, 0, s2>>>(ei, p_deg, E);        // launch 1
    scan_block<<<nb, 1024, 0, s2>>>(p_deg, p_incl, p_bsum, n);  // launch 2

    // launch 3 (profiled slot): layer-1 GEMM on main stream
    gemm_mma<128, 2><<<cdiv(n, 128), 256, SMEM1>>>(x, p_w1pk, as1, ad1, p_h1, p_as1, p_ad1, n);

    scan_finish<<<cdiv(n, TB), TB, 0, s2>>>(p_incl, p_bsum, p_deg, p_rowptr, p_cursor, n, nb);
    scatter_edges<<<cdiv(E + n, TB), TB, 0, s2>>>(ei, p_cursor, p_adj, E, n);
    cudaEventRecord(evB, s2);

    // join: gat_node1 needs gemm1 + CSR
    cudaStreamWaitEvent(0, evB, 0);
    gat_node1<<<cdiv(n * 32, TB), TB>>>(p_rowptr, p_adj, p_as1, p_ad1, p_h1, b1, p_o1, n);

    // layer 2
    gemm_mma<64, 1><<<cdiv(n, 128), 256, SMEM2>>>(p_o1, p_w2pk, as2, ad2, p_h2, p_as2, p_ad2, n);
    gat_node2<<<cdiv(n * 32, TB), TB>>>(p_rowptr, p_adj, p_as2, p_ad2, p_h2, b2, p_o2, n);

    // pooling + head
    pool_seg<<<cdiv(n, 128), 256>>>(p_o2, bat, p_psum, p_pmax, p_cnt, n);
    final_mlp_kernel<<<G, 64>>>(p_psum, p_pmax, p_cnt, Wf1, bf1, Wf2, bf2, out);
}

// round 11
// speedup vs baseline: 3.1232x; 1.0037x over previous
#include <cuda_runtime.h>
#include <cuda_bf16.h>
#include <cstdint>
#include <stdint.h>
#include <float.h>
#include <math.h>

#define MAX_NODES 100000
#define MAX_EDGES 600000
#define MAX_GRAPHS 512

// ---------------- scratch (device globals) ----------------
__device__ float g_h1[(size_t)MAX_NODES * 128];
__device__ float g_o1[(size_t)MAX_NODES * 128];
__device__ float g_h2[(size_t)MAX_NODES * 64];
__device__ float g_o2[(size_t)MAX_NODES * 64];
__device__ float g_as1[MAX_NODES * 2];
__device__ float g_ad1[MAX_NODES * 2];
__device__ float g_as2[MAX_NODES];
__device__ float g_ad2[MAX_NODES];
// fragment-packed weights: word idx = ((n*8+ks)*4+j)*4 + {hi_k, hi_k8, lo_k, lo_k8}
__device__ uint32_t g_w1pk[128 * 128];
__device__ uint32_t g_w2pk[64 * 128];
__device__ int g_deg[MAX_NODES];
__device__ int g_incl[MAX_NODES];
__device__ int g_bsum[256];
__device__ int g_rowptr[MAX_NODES + 1];
__device__ int g_cursor[MAX_NODES];
__device__ int g_adj[MAX_EDGES + MAX_NODES];
__device__ float g_psum[MAX_GRAPHS * 64];
__device__ float g_pmax[MAX_GRAPHS * 64];
__device__ float g_cnt[MAX_GRAPHS];

// ---------------- misc ----------------
__device__ __forceinline__ void atomicMaxF(float* addr, float value) {
    if (value >= 0.f) {
        atomicMax((int*)addr, __float_as_int(value));
    } else {
        atomicMin((unsigned int*)addr, __float_as_uint(value));
    }
}

__device__ __forceinline__ void mma_bf16(float* d, const uint32_t* a, uint32_t b0, uint32_t b1) {
    asm volatile(
        "mma.sync.aligned.m16n8k16.row.col.f32.bf16.bf16.f32 "
        "{%0, %1, %2, %3}, {%4, %5, %6, %7}, {%8, %9}, {%0, %1, %2, %3};"
        : "+f"(d[0]), "+f"(d[1]), "+f"(d[2]), "+f"(d[3])
        : "r"(a[0]), "r"(a[1]), "r"(a[2]), "r"(a[3]), "r"(b0), "r"(b1));
}

__device__ __forceinline__ void cvt_hilo(float2 x, uint32_t& hi, uint32_t& lo) {
    __nv_bfloat16 h0 = __float2bfloat16(x.x);
    __nv_bfloat16 h1 = __float2bfloat16(x.y);
    __nv_bfloat16 l0 = __float2bfloat16(x.x - __bfloat162float(h0));
    __nv_bfloat16 l1 = __float2bfloat16(x.y - __bfloat162float(h1));
    hi = (uint32_t)__bfloat16_as_ushort(h0) | ((uint32_t)__bfloat16_as_ushort(h1) << 16);
    lo = (uint32_t)__bfloat16_as_ushort(l0) | ((uint32_t)__bfloat16_as_ushort(l1) << 16);
}

// ---------------- setup: deg=1 + fragment-packed weight preps + pool fills ----------------
__global__ void setup_kernel(const float* __restrict__ W1, const float* __restrict__ W2,
                             uint32_t* __restrict__ w1pk, uint32_t* __restrict__ w2pk,
                             int* __restrict__ deg, float* __restrict__ psum,
                             float* __restrict__ pmax, float* __restrict__ cnt, int n, int gtot) {
    int idx = blockIdx.x * blockDim.x + threadIdx.x;
    if (idx < n) deg[idx] = 1;
    if (idx < 128 * 64) {
        int nr = idx >> 6;
        int p = idx & 63;
        int k0 = p * 2;
        int ks = k0 >> 4;
        int r = k0 & 15;
        int halfk = r >> 3;
        int j = (r & 7) >> 1;
        float2 v = make_float2(W1[k0 * 128 + nr], W1[(k0 + 1) * 128 + nr]);
        uint32_t hw;
        uint32_t lw;
        cvt_hilo(v, hw, lw);
        int base = ((nr * 8 + ks) * 4 + j) * 4;
        w1pk[base + halfk] = hw;
        w1pk[base + 2 + halfk] = lw;
    }
    if (idx < 64 * 64) {
        int nr = idx >> 6;
        int p = idx & 63;
        int k0 = p * 2;
        int ks = k0 >> 4;
        int r = k0 & 15;
        int halfk = r >> 3;
        int j = (r & 7) >> 1;
        float2 v = make_float2(W2[k0 * 64 + nr], W2[(k0 + 1) * 64 + nr]);
        uint32_t hw;
        uint32_t lw;
        cvt_hilo(v, hw, lw);
        int base = ((nr * 8 + ks) * 4 + j) * 4;
        w2pk[base + halfk] = hw;
        w2pk[base + 2 + halfk] = lw;
    }
    if (idx < gtot * 64) {
        psum[idx] = 0.f;
        pmax[idx] = -FLT_MAX;
    }
    if (idx < gtot) cnt[idx] = 0.f;
}

// ---------------- layer-1 HMMA GEMM: warp = 32 rows x 8 n-tiles (one head) ----------------
// C[n,128] = A[n,128] @ W; 128 rows/CTA; 8 warps = 4 rowgrps x 2 colgrps.
// Each W LDS.128 feeds 6 MMAs (two m-tiles).
__global__ __launch_bounds__(256, 2) void gemm_mma1(
    const float* __restrict__ A, const uint32_t* __restrict__ Wpk,
    const float* __restrict__ avs, const float* __restrict__ avd, float* __restrict__ Hout,
    float* __restrict__ as_out, float* __restrict__ ad_out, int n) {
    extern __shared__ __align__(16) char sm[];
    constexpr int WST = 576;
    const uint32_t OFF_AVS = 0;
    const uint32_t OFF_AVD = 512;
    const uint32_t OFF_W = 1024;

    const int tid = threadIdx.x;
    const int row0 = blockIdx.x * 128;

    if (tid < 128) {
        reinterpret_cast<float*>(sm + OFF_AVS)[tid] = avs[tid];
        reinterpret_cast<float*>(sm + OFF_AVD)[tid] = avd[tid];
    }
    {
        const uint4* wsrc = reinterpret_cast<const uint4*>(Wpk);
#pragma unroll
        for (int i = tid; i < 128 * 32; i += 256) {
            int nr = i >> 5;
            int w = i & 31;
            *reinterpret_cast<uint4*>(sm + OFF_W + nr * WST + w * 16) = wsrc[i];
        }
    }
    __syncthreads();

    const int warp = tid >> 5;
    const int lane = tid & 31;
    const int g = lane >> 2;
    const int j = lane & 3;
    const int rowgrp = warp >> 1;
    const int colgrp = warp & 1;

    const int r0 = row0 + rowgrp * 32 + g;  // rows r0, r0+8, r0+16, r0+24
    const bool v0 = (r0 < n);
    const bool v1 = (r0 + 8 < n);
    const bool v2 = (r0 + 16 < n);
    const bool v3 = (r0 + 24 < n);
    const float* ap0 = A + (size_t)r0 * 128 + j * 2;
    const float* ap1 = ap0 + 8 * 128;
    const float* ap2 = ap0 + 16 * 128;
    const float* ap3 = ap0 + 24 * 128;

    float acc0[8][4];
    float acc1[8][4];
#pragma unroll
    for (int nt = 0; nt < 8; nt++)
#pragma unroll
        for (int q = 0; q < 4; q++) {
            acc0[nt][q] = 0.f;
            acc1[nt][q] = 0.f;
        }

    const char* bw = sm + OFF_W + (colgrp * 64 + g) * WST + j * 16;
    const float2 z2 = make_float2(0.f, 0.f);
#pragma unroll
    for (int ks = 0; ks < 8; ks++) {
        float2 x00 = v0 ? *reinterpret_cast<const float2*>(ap0 + ks * 16) : z2;
        float2 x01 = v0 ? *reinterpret_cast<const float2*>(ap0 + ks * 16 + 8) : z2;
        float2 x10 = v1 ? *reinterpret_cast<const float2*>(ap1 + ks * 16) : z2;
        float2 x11 = v1 ? *reinterpret_cast<const float2*>(ap1 + ks * 16 + 8) : z2;
        float2 x20 = v2 ? *reinterpret_cast<const float2*>(ap2 + ks * 16) : z2;
        float2 x21 = v2 ? *reinterpret_cast<const float2*>(ap2 + ks * 16 + 8) : z2;
        float2 x30 = v3 ? *reinterpret_cast<const float2*>(ap3 + ks * 16) : z2;
        float2 x31 = v3 ? *reinterpret_cast<const float2*>(ap3 + ks * 16 + 8) : z2;
        uint32_t ahi0[4];
        uint32_t alo0[4];
        uint32_t ahi1[4];
        uint32_t alo1[4];
        cvt_hilo(x00, ahi0[0], alo0[0]);
        cvt_hilo(x10, ahi0[1], alo0[1]);
        cvt_hilo(x01, ahi0[2], alo0[2]);
        cvt_hilo(x11, ahi0[3], alo0[3]);
        cvt_hilo(x20, ahi1[0], alo1[0]);
        cvt_hilo(x30, ahi1[1], alo1[1]);
        cvt_hilo(x21, ahi1[2], alo1[2]);
        cvt_hilo(x31, ahi1[3], alo1[3]);
        const char* bks = bw + ks * 64;
#pragma unroll
        for (int nt = 0; nt < 8; nt++) {
            uint4 b = *reinterpret_cast<const uint4*>(bks + nt * 8 * WST);
            mma_bf16(acc0[nt], ahi0, b.x, b.y);
            mma_bf16(acc0[nt], ahi0, b.z, b.w);
            mma_bf16(acc0[nt], alo0, b.x, b.y);
            mma_bf16(acc1[nt], ahi1, b.x, b.y);
            mma_bf16(acc1[nt], ahi1, b.z, b.w);
            mma_bf16(acc1[nt], alo1, b.x, b.y);
        }
    }

    // epilogue: alpha partials (this warp covers one full head = colgrp) + direct C stores
    const float* avs_s = reinterpret_cast<const float*>(sm + OFF_AVS);
    const float* avd_s = reinterpret_cast<const float*>(sm + OFF_AVD);
    float as[4] = {0.f, 0.f, 0.f, 0.f};  // rows r0, r0+8, r0+16, r0+24
    float ds[4] = {0.f, 0.f, 0.f, 0.f};
#pragma unroll
    for (int nt = 0; nt < 8; nt++) {
        int cn = colgrp * 64 + nt * 8 + 2 * j;
        float av0 = avs_s[cn];
        float av1 = avs_s[cn + 1];
        float dv0 = avd_s[cn];
        float dv1 = avd_s[cn + 1];
        as[0] += acc0[nt][0] * av0 + acc0[nt][1] * av1;
        as[1] += acc0[nt][2] * av0 + acc0[nt][3] * av1;
        as[2] += acc1[nt][0] * av0 + acc1[nt][1] * av1;
        as[3] += acc1[nt][2] * av0 + acc1[nt][3] * av1;
        ds[0] += acc0[nt][0] * dv0 + acc0[nt][1] * dv1;
        ds[1] += acc0[nt][2] * dv0 + acc0[nt][3] * dv1;
        ds[2] += acc1[nt][0] * dv0 + acc1[nt][1] * dv1;
        ds[3] += acc1[nt][2] * dv0 + acc1[nt][3] * dv1;
        if (v0)
            *reinterpret_cast<float2*>(Hout + (size_t)r0 * 128 + cn) =
                make_float2(acc0[nt][0], acc0[nt][1]);
        if (v1)
            *reinterpret_cast<float2*>(Hout + (size_t)(r0 + 8) * 128 + cn) =
                make_float2(acc0[nt][2], acc0[nt][3]);
        if (v2)
            *reinterpret_cast<float2*>(Hout + (size_t)(r0 + 16) * 128 + cn) =
                make_float2(acc1[nt][0], acc1[nt][1]);
        if (v3)
            *reinterpret_cast<float2*>(Hout + (size_t)(r0 + 24) * 128 + cn) =
                make_float2(acc1[nt][2], acc1[nt][3]);
    }
#pragma unroll
    for (int off = 1; off <= 2; off <<= 1) {
#pragma unroll
        for (int q = 0; q < 4; q++) {
            as[q] += __shfl_xor_sync(0xffffffffu, as[q], off);
            ds[q] += __shfl_xor_sync(0xffffffffu, ds[q], off);
        }
    }
    if (j == 0) {
        const bool vr[4] = {v0, v1, v2, v3};
#pragma unroll
        for (int q = 0; q < 4; q++) {
            if (vr[q]) {
                int r = r0 + q * 8;
                as_out[(size_t)r * 2 + colgrp] = as[q];
                ad_out[(size_t)r * 2 + colgrp] = ds[q];
            }
        }
    }
}

// ---------------- layer-2 HMMA GEMM (NOUT=64, HEADS=1; original scheme) ----------------
__global__ __launch_bounds__(256, 2) void gemm_mma2(
    const float* __restrict__ A, const uint32_t* __restrict__ Wpk,
    const float* __restrict__ avs, const float* __restrict__ avd, float* __restrict__ Hout,
    float* __restrict__ as_out, float* __restrict__ ad_out, int n) {
    extern __shared__ __align__(16) char sm[];
    constexpr int NOUT = 64;
    constexpr int NT = 8;
    constexpr int WST = 576;
    const uint32_t OFF_AVS = 0;
    const uint32_t OFF_AVD = 512;
    const uint32_t OFF_W = 1024;

    const int tid = threadIdx.x;
    const int row0 = blockIdx.x * 128;

    if (tid < NOUT) {
        reinterpret_cast<float*>(sm + OFF_AVS)[tid] = avs[tid];
        reinterpret_cast<float*>(sm + OFF_AVD)[tid] = avd[tid];
    }
    {
        const uint4* wsrc = reinterpret_cast<const uint4*>(Wpk);
#pragma unroll
        for (int i = tid; i < NOUT * 32; i += 256) {
            int nr = i >> 5;
            int w = i & 31;
            *reinterpret_cast<uint4*>(sm + OFF_W + nr * WST + w * 16) = wsrc[i];
        }
    }
    __syncthreads();

    const int warp = tid >> 5;
    const int lane = tid & 31;
    const int g = lane >> 2;
    const int j = lane & 3;
    const int wm0 = warp * 16;

    const int rowA0 = row0 + wm0 + g;
    const int rowA1 = rowA0 + 8;
    const bool v0r = rowA0 < n;
    const bool v1r = rowA1 < n;
    const float* a0p = A + (size_t)rowA0 * 128 + j * 2;
    const float* a1p = A + (size_t)rowA1 * 128 + j * 2;

    float acc[NT][4];
#pragma unroll
    for (int nt = 0; nt < NT; nt++)
#pragma unroll
        for (int q = 0; q < 4; q++) acc[nt][q] = 0.f;

    const char* bw = sm + OFF_W + g * WST + j * 16;
    const float2 z2 = make_float2(0.f, 0.f);
#pragma unroll
    for (int ks = 0; ks < 8; ks++) {
        float2 x00 = v0r ? *reinterpret_cast<const float2*>(a0p + ks * 16) : z2;
        float2 x01 = v0r ? *reinterpret_cast<const float2*>(a0p + ks * 16 + 8) : z2;
        float2 x10 = v1r ? *reinterpret_cast<const float2*>(a1p + ks * 16) : z2;
        float2 x11 = v1r ? *reinterpret_cast<const float2*>(a1p + ks * 16 + 8) : z2;
        uint32_t ahi[4];
        uint32_t alo[4];
        cvt_hilo(x00, ahi[0], alo[0]);
        cvt_hilo(x10, ahi[1], alo[1]);
        cvt_hilo(x01, ahi[2], alo[2]);
        cvt_hilo(x11, ahi[3], alo[3]);
        const char* bks = bw + ks * 64;
#pragma unroll
        for (int nt = 0; nt < NT; nt++) {
            uint4 b = *reinterpret_cast<const uint4*>(bks + nt * 8 * WST);
            mma_bf16(acc[nt], ahi, b.x, b.y);
            mma_bf16(acc[nt], ahi, b.z, b.w);
            mma_bf16(acc[nt], alo, b.x, b.y);
        }
    }

    const float* avs_s = reinterpret_cast<const float*>(sm + OFF_AVS);
    const float* avd_s = reinterpret_cast<const float*>(sm + OFF_AVD);
    float asum[2] = {0.f, 0.f};
    float dsum[2] = {0.f, 0.f};
#pragma unroll
    for (int nt = 0; nt < NT; nt++) {
        int cn = nt * 8 + 2 * j;
        float av0 = avs_s[cn];
        float av1 = avs_s[cn + 1];
        float dv0 = avd_s[cn];
        float dv1 = avd_s[cn + 1];
        asum[0] += acc[nt][0] * av0 + acc[nt][1] * av1;
        asum[1] += acc[nt][2] * av0 + acc[nt][3] * av1;
        dsum[0] += acc[nt][0] * dv0 + acc[nt][1] * dv1;
        dsum[1] += acc[nt][2] * dv0 + acc[nt][3] * dv1;
        if (v0r)
            *reinterpret_cast<float2*>(Hout + (size_t)rowA0 * NOUT + cn) =
                make_float2(acc[nt][0], acc[nt][1]);
        if (v1r)
            *reinterpret_cast<float2*>(Hout + (size_t)rowA1 * NOUT + cn) =
                make_float2(acc[nt][2], acc[nt][3]);
    }
#pragma unroll
    for (int off = 1; off <= 2; off <<= 1) {
        asum[0] += __shfl_xor_sync(0xffffffffu, asum[0], off);
        asum[1] += __shfl_xor_sync(0xffffffffu, asum[1], off);
        dsum[0] += __shfl_xor_sync(0xffffffffu, dsum[0], off);
        dsum[1] += __shfl_xor_sync(0xffffffffu, dsum[1], off);
    }
    if (j == 0) {
        if (v0r) {
            as_out[rowA0] = asum[0];
            ad_out[rowA0] = dsum[0];
        }
        if (v1r) {
            as_out[rowA1] = asum[1];
            ad_out[rowA1] = dsum[1];
        }
    }
}

// ---------------- CSR build ----------------
__global__ void deg_count(const int* __restrict__ ei, int* __restrict__ deg, int E) {
    int i = blockIdx.x * blockDim.x + threadIdx.x;
    if (i < E) atomicAdd(&deg[ei[E + i]], 1);
}

__global__ void scan_block(const int* __restrict__ deg, int* __restrict__ incl,
                           int* __restrict__ bsum, int n) {
    __shared__ int wsum[32];
    int tid = threadIdx.x;
    int lane = tid & 31;
    int wid = tid >> 5;
    int gid = blockIdx.x * 1024 + tid;
    int v = (gid < n) ? deg[gid] : 0;
#pragma unroll
    for (int off = 1; off < 32; off <<= 1) {
        int t = __shfl_up_sync(0xffffffffu, v, off);
        if (lane >= off) v += t;
    }
    if (lane == 31) wsum[wid] = v;
    __syncthreads();
    if (wid == 0) {
        int w = wsum[lane];
#pragma unroll
        for (int off = 1; off < 32; off <<= 1) {
            int t = __shfl_up_sync(0xffffffffu, w, off);
            if (lane >= off) w += t;
        }
        wsum[lane] = w;
    }
    __syncthreads();
    if (wid > 0) v += wsum[wid - 1];
    if (gid < n) incl[gid] = v;
    if (tid == 1023) bsum[blockIdx.x] = v;
}

__global__ void scan_finish(const int* __restrict__ incl, const int* __restrict__ bsum,
                            const int* __restrict__ deg, int* __restrict__ rowptr,
                            int* __restrict__ cursor, int n, int nb) {
    __shared__ int pre[128];
    int tid = threadIdx.x;
    if (tid < 32) {
        int base = tid * 4;
        int v[4];
#pragma unroll
        for (int q = 0; q < 4; q++) v[q] = (base + q < nb) ? bsum[base + q] : 0;
        int tot = v[0] + v[1] + v[2] + v[3];
        int inc = tot;
#pragma unroll
        for (int off = 1; off < 32; off <<= 1) {
            int t = __shfl_up_sync(0xffffffffu, inc, off);
            if (tid >= off) inc += t;
        }
        int run = inc - tot;
#pragma unroll
        for (int q = 0; q < 4; q++) {
            pre[base + q] = run;
            run += v[q];
        }
    }
    __syncthreads();
    int i = blockIdx.x * blockDim.x + tid;
    if (i < n) {
        int end = incl[i] + pre[i >> 10];
        rowptr[i + 1] = end;
        cursor[i] = end - deg[i];
    }
    if (i == 0) rowptr[0] = 0;
}

__global__ void scatter_edges(const int* __restrict__ ei, int* __restrict__ cursor,
                              int* __restrict__ adj, int E, int n) {
    int i = blockIdx.x * blockDim.x + threadIdx.x;
    if (i >= E + n) return;
    int s;
    int d;
    if (i < E) {
        s = ei[i];
        d = ei[E + i];
    } else {
        s = i - E;
        d = s;
    }
    int pos = atomicAdd(&cursor[d], 1);
    adj[pos] = s;
}

// ---------------- layer1 node aggregation ----------------
__global__ void gat_node1(const int* __restrict__ rowptr, const int* __restrict__ adj,
                          const float* __restrict__ as, const float* __restrict__ ad,
                          const float* __restrict__ h, const float* __restrict__ b,
                          float* __restrict__ out, int n) {
    int node = (blockIdx.x * blockDim.x + threadIdx.x) >> 5;
    int lane = threadIdx.x & 31;
    if (node >= n) return;
    int start = rowptr[node];
    int end = rowptr[node + 1];
    float ad0 = ad[node * 2];
    float ad1 = ad[node * 2 + 1];
    bool hi = lane >= 16;

    float4 acc = make_float4(0.f, 0.f, 0.f, 0.f);
    float den0 = 0.f;
    float den1 = 0.f;
    for (int base = start; base < end; base += 32) {
        int cnt = min(32, end - base);
        int s_l = 0;
        float ex0_l = 0.f;
        float ex1_l = 0.f;
        if (lane < cnt) {
            s_l = adj[base + lane];
            float e0 = as[s_l * 2] + ad0;
            e0 = e0 >= 0.f ? e0 : 0.2f * e0;
            float e1 = as[s_l * 2 + 1] + ad1;
            e1 = e1 >= 0.f ? e1 : 0.2f * e1;
            ex0_l = expf(e0);
            ex1_l = expf(e1);
        }
        den0 += ex0_l;
        den1 += ex1_l;
#pragma unroll 4
        for (int tt = 0; tt < cnt; tt++) {
            int s = __shfl_sync(0xffffffffu, s_l, tt);
            float ex0 = __shfl_sync(0xffffffffu, ex0_l, tt);
            float ex1 = __shfl_sync(0xffffffffu, ex1_l, tt);
            float ex = hi ? ex1 : ex0;
            float4 v = reinterpret_cast<const float4*>(h + (size_t)s * 128)[lane];
            acc.x = fmaf(ex, v.x, acc.x);
            acc.y = fmaf(ex, v.y, acc.y);
            acc.z = fmaf(ex, v.z, acc.z);
            acc.w = fmaf(ex, v.w, acc.w);
        }
    }
    for (int o = 16; o > 0; o >>= 1) {
        den0 += __shfl_xor_sync(0xffffffffu, den0, o);
        den1 += __shfl_xor_sync(0xffffffffu, den1, o);
    }
    float den = fmaxf(hi ? den1 : den0, 1e-16f);
    float inv = 1.f / den;
    float4 bb = reinterpret_cast<const float4*>(b)[lane];
    float4 o;
    o.x = fmaxf(fmaf(acc.x, inv, bb.x), 0.f);
    o.y = fmaxf(fmaf(acc.y, inv, bb.y), 0.f);
    o.z = fmaxf(fmaf(acc.z, inv, bb.z), 0.f);
    o.w = fmaxf(fmaf(acc.w, inv, bb.w), 0.f);
    reinterpret_cast<float4*>(out + (size_t)node * 128)[lane] = o;
}

// ---------------- layer2 node aggregation ----------------
__global__ void gat_node2(const int* __restrict__ rowptr, const int* __restrict__ adj,
                          const float* __restrict__ as, const float* __restrict__ ad,
                          const float* __restrict__ h, const float* __restrict__ b,
                          float* __restrict__ out, int n) {
    int node = (blockIdx.x * blockDim.x + threadIdx.x) >> 5;
    int lane = threadIdx.x & 31;
    if (node >= n) return;
    int start = rowptr[node];
    int end = rowptr[node + 1];
    float add = ad[node];

    float2 acc = make_float2(0.f, 0.f);
    float den = 0.f;
    for (int base = start; base < end; base += 32) {
        int cnt = min(32, end - base);
        int s_l = 0;
        float ex_l = 0.f;
        if (lane < cnt) {
            s_l = adj[base + lane];
            float e = as[s_l] + add;
            e = e >= 0.f ? e : 0.2f * e;
            ex_l = expf(e);
        }
        den += ex_l;
#pragma unroll 4
        for (int tt = 0; tt < cnt; tt++) {
            int s = __shfl_sync(0xffffffffu, s_l, tt);
            float ex = __shfl_sync(0xffffffffu, ex_l, tt);
            float2 v = reinterpret_cast<const float2*>(h + (size_t)s * 64)[lane];
            acc.x = fmaf(ex, v.x, acc.x);
            acc.y = fmaf(ex, v.y, acc.y);
        }
    }
    for (int o = 16; o > 0; o >>= 1) {
        den += __shfl_xor_sync(0xffffffffu, den, o);
    }
    float inv = 1.f / fmaxf(den, 1e-16f);
    float2 bb = reinterpret_cast<const float2*>(b)[lane];
    float2 o;
    o.x = fmaf(acc.x, inv, bb.x);
    o.y = fmaf(acc.y, inv, bb.y);
    reinterpret_cast<float2*>(out + (size_t)node * 64)[lane] = o;
}

// ---------------- per-graph pooling (batch sorted) ----------------
__global__ void pool_seg(const float* __restrict__ h, const int* __restrict__ batch,
                         float* __restrict__ psum, float* __restrict__ pmax,
                         float* __restrict__ cnt, int n) {
    int n0 = blockIdx.x * 128;
    int t = threadIdx.x;
    int c = t & 63;
    int off = t >> 6;
    int gcur = -1;
    float sum = 0.f;
    float mx = -FLT_MAX;
    float count = 0.f;
    int lim = min(n0 + 128, n);
    for (int i = n0 + off; i < lim; i += 4) {
        int g = batch[i];
        if (g != gcur) {
            if (gcur >= 0) {
                atomicAdd(&psum[gcur * 64 + c], sum);
                atomicMaxF(&pmax[gcur * 64 + c], mx);
                if (c == 0) atomicAdd(&cnt[gcur], count);
            }
            gcur = g;
            sum = 0.f;
            mx = -FLT_MAX;
            count = 0.f;
        }
        float v = h[(size_t)i * 64 + c];
        sum += v;
        mx = fmaxf(mx, v);
        count += 1.f;
    }
    if (gcur >= 0) {
        atomicAdd(&psum[gcur * 64 + c], sum);
        atomicMaxF(&pmax[gcur * 64 + c], mx);
        if (c == 0) atomicAdd(&cnt[gcur], count);
    }
}

// ---------------- final MLP head ----------------
__global__ void final_mlp_kernel(const float* __restrict__ psum, const float* __restrict__ pmax,
                                 const float* __restrict__ cnt, const float* __restrict__ Wf1,
                                 const float* __restrict__ bf1, const float* __restrict__ Wf2,
                                 const float* __restrict__ bf2, float* __restrict__ out) {
    __shared__ float pooled[128];
    __shared__ float red[64];
    int g = blockIdx.x;
    int t = threadIdx.x;
    float c = cnt[g];
    pooled[t] = psum[g * 64 + t] / fmaxf(c, 1.f);
    pooled[64 + t] = (c > 0.f) ? pmax[g * 64 + t] : 0.f;
    __syncthreads();
    float hj = bf1[t];
    for (int k = 0; k < 128; k++) {
        hj = fmaf(pooled[k], Wf1[k * 64 + t], hj);
    }
    hj = fmaxf(hj, 0.f);
    red[t] = hj * Wf2[t];
    __syncthreads();
    for (int s = 32; s > 0; s >>= 1) {
        if (t < s) red[t] += red[t + s];
        __syncthreads();
    }
    if (t == 0) out[g] = red[0] + bf2[0];
}

// ---------------- host launch ----------------
static inline int cdiv(int a, int b) { return (a + b - 1) / b; }

extern "C" void kernel_launch(void* const* d_in, const int* in_sizes, int n_in,
                              void* d_out, int out_size) {
    const float* x = (const float*)d_in[0];
    const int* ei = (const int*)d_in[1];
    const int* bat = (const int*)d_in[2];
    const float* W1 = (const float*)d_in[3];
    const float* as1 = (const float*)d_in[4];
    const float* ad1 = (const float*)d_in[5];
    const float* b1 = (const float*)d_in[6];
    const float* W2 = (const float*)d_in[7];
    const float* as2 = (const float*)d_in[8];
    const float* ad2 = (const float*)d_in[9];
    const float* b2 = (const float*)d_in[10];
    const float* Wf1 = (const float*)d_in[11];
    const float* bf1 = (const float*)d_in[12];
    const float* Wf2 = (const float*)d_in[13];
    const float* bf2 = (const float*)d_in[14];
    float* out = (float*)d_out;

    const int n = in_sizes[0] / 128;
    const int E = in_sizes[1] / 2;
    const int G = out_size;

    float* p_h1;
    float* p_o1;
    float* p_h2;
    float* p_o2;
    float* p_as1;
    float* p_ad1;
    float* p_as2;
    float* p_ad2;
    float* p_psum;
    float* p_pmax;
    float* p_cnt;
    int* p_deg;
    int* p_incl;
    int* p_bsum;
    int* p_rowptr;
    int* p_cursor;
    int* p_adj;
    uint32_t* p_w1pk;
    uint32_t* p_w2pk;
    cudaGetSymbolAddress((void**)&p_h1, g_h1);
    cudaGetSymbolAddress((void**)&p_o1, g_o1);
    cudaGetSymbolAddress((void**)&p_h2, g_h2);
    cudaGetSymbolAddress((void**)&p_o2, g_o2);
    cudaGetSymbolAddress((void**)&p_as1, g_as1);
    cudaGetSymbolAddress((void**)&p_ad1, g_ad1);
    cudaGetSymbolAddress((void**)&p_as2, g_as2);
    cudaGetSymbolAddress((void**)&p_ad2, g_ad2);
    cudaGetSymbolAddress((void**)&p_psum, g_psum);
    cudaGetSymbolAddress((void**)&p_pmax, g_pmax);
    cudaGetSymbolAddress((void**)&p_cnt, g_cnt);
    cudaGetSymbolAddress((void**)&p_deg, g_deg);
    cudaGetSymbolAddress((void**)&p_incl, g_incl);
    cudaGetSymbolAddress((void**)&p_bsum, g_bsum);
    cudaGetSymbolAddress((void**)&p_rowptr, g_rowptr);
    cudaGetSymbolAddress((void**)&p_cursor, g_cursor);
    cudaGetSymbolAddress((void**)&p_adj, g_adj);
    cudaGetSymbolAddress((void**)&p_w1pk, g_w1pk);
    cudaGetSymbolAddress((void**)&p_w2pk, g_w2pk);

    const int TB = 256;
    const int nb = cdiv(n, 1024);

    const int SMEM1 = 1024 + 128 * 576;  // 74752
    const int SMEM2 = 1024 + 64 * 576;   // 37888
    cudaFuncSetAttribute(gemm_mma1, cudaFuncAttributeMaxDynamicSharedMemorySize, SMEM1);
    cudaFuncSetAttribute(gemm_mma2, cudaFuncAttributeMaxDynamicSharedMemorySize, SMEM2);

    static cudaStream_t s2 = nullptr;
    static cudaEvent_t evA = nullptr;
    static cudaEvent_t evB = nullptr;
    if (s2 == nullptr) {
        cudaStreamCreateWithFlags(&s2, cudaStreamNonBlocking);
        cudaEventCreateWithFlags(&evA, cudaEventDisableTiming);
        cudaEventCreateWithFlags(&evB, cudaEventDisableTiming);
    }

    // launch 0: setup (packed weights + deg init + pool fills)
    setup_kernel<<<cdiv(n, TB), TB>>>(W1, W2, p_w1pk, p_w2pk, p_deg, p_psum, p_pmax, p_cnt, n, G);

    // fork CSR chain to side stream
    cudaEventRecord(evA, 0);
    cudaStreamWaitEvent(s2, evA, 0);
    deg_count<<<cdiv(E, TB), TB, 0, s2>>>(ei, p_deg, E);        // launch 1
    scan_block<<<nb, 1024, 0, s2>>>(p_deg, p_incl, p_bsum, n);  // launch 2

    // launch 3 (profiled slot): layer-1 GEMM on main stream
    gemm_mma1<<<cdiv(n, 128), 256, SMEM1>>>(x, p_w1pk, as1, ad1, p_h1, p_as1, p_ad1, n);

    scan_finish<<<cdiv(n, TB), TB, 0, s2>>>(p_incl, p_bsum, p_deg, p_rowptr, p_cursor, n, nb);
    scatter_edges<<<cdiv(E + n, TB), TB, 0, s2>>>(ei, p_cursor, p_adj, E, n);
    cudaEventRecord(evB, s2);

    // join: gat_node1 needs gemm1 + CSR
    cudaStreamWaitEvent(0, evB, 0);
    gat_node1<<<cdiv(n * 32, TB), TB>>>(p_rowptr, p_adj, p_as1, p_ad1, p_h1, b1, p_o1, n);

    // layer 2
    gemm_mma2<<<cdiv(n, 128), 256, SMEM2>>>(p_o1, p_w2pk, as2, ad2, p_h2, p_as2, p_ad2, n);
    gat_node2<<<cdiv(n * 32, TB), TB>>>(p_rowptr, p_adj, p_as2, p_ad2, p_h2, b2, p_o2, n);

    // pooling + head
    pool_seg<<<cdiv(n, 128), 256>>>(p_o2, bat, p_psum, p_pmax, p_cnt, n);
    final_mlp_kernel<<<G, 64>>>(p_psum, p_pmax, p_cnt, Wf1, bf1, Wf2, bf2, out);
}